// round 8
// baseline (speedup 1.0000x reference)
#include <cuda_runtime.h>
#include <cuda_fp16.h>
#include <cstdint>
#include <cstddef>

#define BB 4
#define NN 4096
#define MM 1024
#define CC 128
#define DD 256
#define PHD 64
#define AHD 512
#define KNB 16
#define RR (BB*NN*KNB)   // 262144 rows (b,n,k)

// ---------------- static scratch --------------------------------------------
__device__ float  g_valueT[BB*MM*DD];     // (B*M, D)
__device__ float  g_keyfT [BB*MM*DD];
__device__ float  g_valftT[BB*MM*DD];
__device__ float  g_queryT[BB*NN*DD];     // (B*N, D)
__device__ float  g_W1qt  [BB*NN*AHD];    // (B*N, AH) fp32
__device__ float  g_W1kt  [BB*MM*AHD];    // (B*M, AH) fp32
__device__ int    g_idx   [RR];
__device__ __half g_hrelu [16777216];     // (R, 64) fp16
__device__ __half g_hid   [134217728];    // (R, 512) fp16
__device__ float  g_agg   [BB*NN*DD];     // (B*N, 256) aggv
__device__ float  g_pre1  [AHD*PHD];
__device__ __half g_pre1h [AHD*PHD];
__device__ __half g_w1h   [AHD*DD];       // attn_w1 fp16
__device__ __half g_w2h   [DD*AHD];       // attn_w2 fp16
__device__ __half g_pw2h  [DD*PHD];       // pos_w2 fp16
__device__ float  g_aA[AHD], g_cA[AHD], g_aP[PHD], g_cP[PHD];

// ---------------- helpers ----------------------------------------------------
__device__ __forceinline__ void mma16816(float* d, const uint32_t* a,
                                         uint32_t b0, uint32_t b1) {
    asm volatile(
        "mma.sync.aligned.m16n8k16.row.col.f32.f16.f16.f32 "
        "{%0,%1,%2,%3},{%4,%5,%6,%7},{%8,%9},{%0,%1,%2,%3};"
        : "+f"(d[0]), "+f"(d[1]), "+f"(d[2]), "+f"(d[3])
        : "r"(a[0]), "r"(a[1]), "r"(a[2]), "r"(a[3]), "r"(b0), "r"(b1));
}
__device__ __forceinline__ uint32_t packh2(float x, float y) {
    __half2 h = __floats2half2_rn(x, y);
    return *(uint32_t*)&h;
}

// ---------------- fp16 mma GEMM (double-buffered): C = A(rows,K)@W(O,K)^T ----
// BM=128, BN=128, BK=32. 256 threads = 8 warps (4M x 2N), warp tile 32x64.
// Smem: half2 words, [2][128][20] (16 data + 4 pad) conflict-free scalar LDS.
// EPI 0: C = acc (+bias fp32).   EPI 1: C = relu((acc+W1q-W1k)*aA+cA)
template<int O, int K, int EPI, bool AF16, bool OUTH>
__global__ __launch_bounds__(256)
void hgemm(const __half* __restrict__ Wh, const float* __restrict__ bias,
           const void* __restrict__ Ag, void* __restrict__ Cg,
           const float* __restrict__ W1q, const float* __restrict__ W1k,
           const int* __restrict__ idxg,
           const float* __restrict__ aA, const float* __restrict__ cA)
{
    constexpr int CCH = K / 32;
    __shared__ __align__(16) __half2 As2[2][128][20];
    __shared__ __align__(16) __half2 Bs2[2][128][20];
    const int row0 = blockIdx.y * 128;
    const int o0   = blockIdx.x * 128;
    const int tid  = threadIdx.x;
    const int lane = tid & 31;
    const int wid  = tid >> 5;
    const int wm = wid & 3;
    const int wn = wid >> 2;
    const int lq = lane >> 2;
    const int lr = lane & 3;

    float acc[2][8][4];
#pragma unroll
    for (int mt = 0; mt < 2; mt++)
#pragma unroll
        for (int nt = 0; nt < 8; nt++)
#pragma unroll
            for (int q = 0; q < 4; q++) acc[mt][nt][q] = 0.f;

    uint4  ra[2], rbv[2];
    float4 fa[2][2];

    auto fetch = [&](int c) {
        if (AF16) {
            const __half* s = (const __half*)Ag +
                (size_t)(row0 + (tid >> 1)) * K + c * 32 + (tid & 1) * 16;
            ra[0] = *(const uint4*)s;
            ra[1] = *(const uint4*)(s + 8);
        } else {
#pragma unroll
            for (int i = 0; i < 2; i++) {
                int lin = tid + i * 256;
                int r = lin >> 2, cq = (lin & 3) * 4;
                const float* s = (const float*)Ag +
                    (size_t)(row0 + r) * K + c * 32 + cq * 2;
                fa[i][0] = *(const float4*)s;
                fa[i][1] = *(const float4*)(s + 4);
            }
        }
        const __half* w = Wh + (size_t)(o0 + (tid >> 1)) * K + c * 32 + (tid & 1) * 16;
        rbv[0] = *(const uint4*)w;
        rbv[1] = *(const uint4*)(w + 8);
    };
    auto store = [&](int bufi) {
        int r = tid >> 1, c0 = (tid & 1) * 8;
        if (AF16) {
            *(uint4*)&As2[bufi][r][c0]     = ra[0];
            *(uint4*)&As2[bufi][r][c0 + 4] = ra[1];
        } else {
#pragma unroll
            for (int i = 0; i < 2; i++) {
                int lin = tid + i * 256;
                int rr = lin >> 2, cq = (lin & 3) * 4;
                uint4 u;
                u.x = packh2(fa[i][0].x, fa[i][0].y);
                u.y = packh2(fa[i][0].z, fa[i][0].w);
                u.z = packh2(fa[i][1].x, fa[i][1].y);
                u.w = packh2(fa[i][1].z, fa[i][1].w);
                *(uint4*)&As2[bufi][rr][cq] = u;
            }
        }
        *(uint4*)&Bs2[bufi][r][c0]     = rbv[0];
        *(uint4*)&Bs2[bufi][r][c0 + 4] = rbv[1];
    };

    fetch(0);
    store(0);
    __syncthreads();
#pragma unroll 1
    for (int c = 0; c < CCH; c++) {
        if (c + 1 < CCH) fetch(c + 1);
        const int p = c & 1;
#pragma unroll
        for (int ks = 0; ks < 2; ks++) {
            const int kb = ks * 8 + lr;
            uint32_t bf[8][2];
#pragma unroll
            for (int nt = 0; nt < 8; nt++) {
                int cb = wn * 64 + nt * 8 + lq;
                bf[nt][0] = *(const uint32_t*)&Bs2[p][cb][kb];
                bf[nt][1] = *(const uint32_t*)&Bs2[p][cb][kb + 4];
            }
#pragma unroll
            for (int mt = 0; mt < 2; mt++) {
                int rb = wm * 32 + mt * 16 + lq;
                uint32_t a[4];
                a[0] = *(const uint32_t*)&As2[p][rb][kb];
                a[1] = *(const uint32_t*)&As2[p][rb + 8][kb];
                a[2] = *(const uint32_t*)&As2[p][rb][kb + 4];
                a[3] = *(const uint32_t*)&As2[p][rb + 8][kb + 4];
#pragma unroll
                for (int nt = 0; nt < 8; nt++)
                    mma16816(acc[mt][nt], a, bf[nt][0], bf[nt][1]);
            }
        }
        if (c + 1 < CCH) store((c + 1) & 1);
        __syncthreads();
    }

    // ---- epilogue ----
#pragma unroll
    for (int mt = 0; mt < 2; mt++) {
#pragma unroll
        for (int h = 0; h < 2; h++) {
            int r = row0 + wm * 32 + mt * 16 + h * 8 + lq;
            const float* qp = nullptr;
            const float* kp = nullptr;
            if (EPI == 1) {
                int bbx = r >> 16;
                int jj = idxg[r];
                qp = W1q + (size_t)(r >> 4) * AHD;
                kp = W1k + ((size_t)bbx * MM + jj) * AHD;
            }
#pragma unroll
            for (int nt = 0; nt < 8; nt++) {
                int o = o0 + wn * 64 + nt * 8 + lr * 2;
                float v0 = acc[mt][nt][h * 2 + 0];
                float v1 = acc[mt][nt][h * 2 + 1];
                if (EPI == 0) {
                    if (bias) { v0 += bias[o]; v1 += bias[o + 1]; }
                } else {
                    float2 qv = *(const float2*)(qp + o);
                    float2 kv = *(const float2*)(kp + o);
                    float2 av = *(const float2*)(aA + o);
                    float2 cv = *(const float2*)(cA + o);
                    v0 = fmaxf((v0 + qv.x - kv.x) * av.x + cv.x, 0.f);
                    v1 = fmaxf((v1 + qv.y - kv.y) * av.y + cv.y, 0.f);
                }
                if (OUTH) {
                    __half2 hv = __floats2half2_rn(v0, v1);
                    *(__half2*)((__half*)Cg + (size_t)r * O + o) = hv;
                } else {
                    *(float2*)((float*)Cg + (size_t)r * O + o) = make_float2(v0, v1);
                }
            }
        }
    }
}

// ---------------- fused: logits GEMM + pe GEMM + softmax + gather + agg ------
// grid (2, RR/128). Writes aggv (B*N, 256) directly. No logits/pe in DRAM.
__global__ __launch_bounds__(256)
void fused_attn(const __half* __restrict__ w2h,    // (256,512)
                const __half* __restrict__ hid,    // (R,512)
                const __half* __restrict__ pw2h,   // (256,64)
                const __half* __restrict__ hrelu,  // (R,64)
                const float* __restrict__ pb2,     // (256)
                const float* __restrict__ valft,   // (B*M,256)
                const int*   __restrict__ idxg,
                float* __restrict__ aggv)          // (B*N,256)
{
    __shared__ __align__(16) __half2 As2[2][128][20];
    __shared__ __align__(16) __half2 Bs2[2][128][20];
    __shared__ int sidx[128];
    const int row0 = blockIdx.y * 128;
    const int o0   = blockIdx.x * 128;
    const int tid  = threadIdx.x;
    const int lane = tid & 31;
    const int wid  = tid >> 5;
    const int wm = wid & 3;
    const int wn = wid >> 2;
    const int lq = lane >> 2;
    const int lr = lane & 3;

    if (tid < 128) sidx[tid] = idxg[row0 + tid];

    float acc1[2][8][4];   // logits
    float acc2[2][8][4];   // pe
#pragma unroll
    for (int mt = 0; mt < 2; mt++)
#pragma unroll
        for (int nt = 0; nt < 8; nt++)
#pragma unroll
            for (int q = 0; q < 4; q++) { acc1[mt][nt][q] = 0.f; acc2[mt][nt][q] = 0.f; }

    auto run_phase = [&](const __half* Ap, const __half* Wp, int Kd, int CCHn,
                         float (&acc)[2][8][4]) {
        uint4 ra[2], rb[2];
        auto fetch = [&](int c) {
            const __half* s = Ap + (size_t)(row0 + (tid >> 1)) * Kd + c * 32 + (tid & 1) * 16;
            ra[0] = *(const uint4*)s;
            ra[1] = *(const uint4*)(s + 8);
            const __half* w = Wp + (size_t)(o0 + (tid >> 1)) * Kd + c * 32 + (tid & 1) * 16;
            rb[0] = *(const uint4*)w;
            rb[1] = *(const uint4*)(w + 8);
        };
        auto store = [&](int bufi) {
            int r = tid >> 1, c0 = (tid & 1) * 8;
            *(uint4*)&As2[bufi][r][c0]     = ra[0];
            *(uint4*)&As2[bufi][r][c0 + 4] = ra[1];
            *(uint4*)&Bs2[bufi][r][c0]     = rb[0];
            *(uint4*)&Bs2[bufi][r][c0 + 4] = rb[1];
        };
        fetch(0);
        store(0);
        __syncthreads();
#pragma unroll 1
        for (int c = 0; c < CCHn; c++) {
            if (c + 1 < CCHn) fetch(c + 1);
            const int p = c & 1;
#pragma unroll
            for (int ks = 0; ks < 2; ks++) {
                const int kb = ks * 8 + lr;
                uint32_t bf[8][2];
#pragma unroll
                for (int nt = 0; nt < 8; nt++) {
                    int cb = wn * 64 + nt * 8 + lq;
                    bf[nt][0] = *(const uint32_t*)&Bs2[p][cb][kb];
                    bf[nt][1] = *(const uint32_t*)&Bs2[p][cb][kb + 4];
                }
#pragma unroll
                for (int mt = 0; mt < 2; mt++) {
                    int rb2 = wm * 32 + mt * 16 + lq;
                    uint32_t a[4];
                    a[0] = *(const uint32_t*)&As2[p][rb2][kb];
                    a[1] = *(const uint32_t*)&As2[p][rb2 + 8][kb];
                    a[2] = *(const uint32_t*)&As2[p][rb2][kb + 4];
                    a[3] = *(const uint32_t*)&As2[p][rb2 + 8][kb + 4];
#pragma unroll
                    for (int nt = 0; nt < 8; nt++)
                        mma16816(acc[mt][nt], a, bf[nt][0], bf[nt][1]);
                }
            }
            if (c + 1 < CCHn) store((c + 1) & 1);
            __syncthreads();
        }
    };

    run_phase(hid,   w2h,  AHD, AHD / 32, acc1);   // logits
    run_phase(hrelu, pw2h, PHD, PHD / 32, acc2);   // pe

    // ---- softmax over k (16 rows per point, within warp) + gather + agg ----
    const int bb = row0 >> 16;                       // batch
#pragma unroll
    for (int mt = 0; mt < 2; mt++) {
        const int pt = (row0 + wm * 32 + mt * 16) >> 4;     // global point
        const int j0 = sidx[wm * 32 + mt * 16 + lq];
        const int j1 = sidx[wm * 32 + mt * 16 + 8 + lq];
        const float* v0b = valft + ((size_t)bb * MM + j0) * DD;
        const float* v1b = valft + ((size_t)bb * MM + j1) * DD;
#pragma unroll
        for (int nt = 0; nt < 8; nt++) {
            const int c = o0 + wn * 64 + nt * 8 + lr * 2;
            float2 vv0 = *(const float2*)(v0b + c);
            float2 vv1 = *(const float2*)(v1b + c);
            float2 pbv = *(const float2*)(pb2 + c);
            float outc[2];
#pragma unroll
            for (int j = 0; j < 2; j++) {
                float l0 = acc1[mt][nt][j];
                float l1 = acc1[mt][nt][2 + j];
                float m = fmaxf(l0, l1);
                m = fmaxf(m, __shfl_xor_sync(0xffffffffu, m, 4));
                m = fmaxf(m, __shfl_xor_sync(0xffffffffu, m, 8));
                m = fmaxf(m, __shfl_xor_sync(0xffffffffu, m, 16));
                float e0 = __expf(l0 - m), e1 = __expf(l1 - m);
                float S = e0 + e1;
                S += __shfl_xor_sync(0xffffffffu, S, 4);
                S += __shfl_xor_sync(0xffffffffu, S, 8);
                S += __shfl_xor_sync(0xffffffffu, S, 16);
                float pb = j ? pbv.y : pbv.x;
                float pe0 = acc2[mt][nt][j] + pb;
                float pe1 = acc2[mt][nt][2 + j] + pb;
                float va0 = j ? vv0.y : vv0.x;
                float va1 = j ? vv1.y : vv1.x;
                float T = e0 * (va0 + pe0) + e1 * (va1 + pe1);
                T += __shfl_xor_sync(0xffffffffu, T, 4);
                T += __shfl_xor_sync(0xffffffffu, T, 8);
                T += __shfl_xor_sync(0xffffffffu, T, 16);
                outc[j] = T / S;
            }
            if (lq == 0)
                *(float2*)(aggv + (size_t)pt * DD + c) = make_float2(outc[0], outc[1]);
        }
    }
}

// ---------------- precompute + weight conversions ----------------------------
__global__ void precomp_kernel(const float* __restrict__ w1,
                               const float* __restrict__ pw2,
                               const float* __restrict__ pb2,
                               const float* __restrict__ ag, const float* __restrict__ abeta,
                               const float* __restrict__ amu, const float* __restrict__ avar,
                               const float* __restrict__ ab1,
                               const float* __restrict__ pg, const float* __restrict__ pbeta,
                               const float* __restrict__ pmu, const float* __restrict__ pvar,
                               const float* __restrict__ pb1,
                               float* __restrict__ pre1, __half* __restrict__ pre1h,
                               float* __restrict__ aA,
                               float* __restrict__ cA, float* __restrict__ aP,
                               float* __restrict__ cP)
{
    int o = blockIdx.x;
    if (o < AHD) {
        int p = threadIdx.x;
        float s = 0.f;
        for (int c = 0; c < DD; c++) s += w1[o*DD + c] * pw2[c*PHD + p];
        pre1[o*PHD + p] = s;
        pre1h[o*PHD + p] = __float2half_rn(s);
        if (p == 0) {
            float vb = 0.f;
            for (int c = 0; c < DD; c++) vb += w1[o*DD + c] * pb2[c];
            float inv = ag[o] / sqrtf(avar[o] + 1e-5f);
            aA[o] = inv;
            cA[o] = (ab1[o] - amu[o]) * inv + abeta[o] + vb * inv;
        }
    } else {
        int p = threadIdx.x;
        float inv = pg[p] / sqrtf(pvar[p] + 1e-5f);
        aP[p] = inv;
        cP[p] = (pb1[p] - pmu[p]) * inv + pbeta[p];
    }
}

__global__ void cvt_h_kernel(const float* __restrict__ s, __half* __restrict__ d, int n)
{
    int i = blockIdx.x * 256 + threadIdx.x;
    if (i < n) d[i] = __float2half_rn(s[i]);
}

// ---------------- SIMT fp32 GEMM (small front/end GEMMs) ---------------------
constexpr int TBO = 128, TBX = 128, TBK = 16;

template<bool A_RM, bool OUT_XO>
__global__ __launch_bounds__(256)
void gemm_k(const float* __restrict__ W, const float* __restrict__ bias,
            const float* __restrict__ A, const float* __restrict__ resid,
            float* __restrict__ C, int O, int K, int X, size_t sA, size_t sC)
{
    __shared__ float As[TBK][TBX];
    __shared__ float Ws[TBK][TBO];
    const int bx = blockIdx.x * TBX;
    const int bo = blockIdx.y * TBO;
    const int b  = blockIdx.z;
    const float* Ab = A + (size_t)b * sA;
    float* Cb = C + (size_t)b * sC;
    const int tid = threadIdx.x;
    const int tco = (tid & 15) * 4;
    const int tcx = (tid >> 4) * 4;

    float acc[8][8];
#pragma unroll
    for (int i = 0; i < 8; i++)
#pragma unroll
        for (int j = 0; j < 8; j++) acc[i][j] = 0.f;

    for (int k0 = 0; k0 < K; k0 += TBK) {
        if (A_RM) {
            int row = tid >> 1, c0 = (tid & 1) * 8;
            const float* p = Ab + (size_t)(bx + row) * K + k0 + c0;
            float4 v0 = *(const float4*)p;
            float4 v1 = *(const float4*)(p + 4);
            As[c0+0][row] = v0.x; As[c0+1][row] = v0.y;
            As[c0+2][row] = v0.z; As[c0+3][row] = v0.w;
            As[c0+4][row] = v1.x; As[c0+5][row] = v1.y;
            As[c0+6][row] = v1.z; As[c0+7][row] = v1.w;
        } else {
            int kk = tid >> 4, x8 = (tid & 15) * 8;
            const float* p = Ab + (size_t)(k0 + kk) * X + bx + x8;
            float4 v0 = *(const float4*)p;
            float4 v1 = *(const float4*)(p + 4);
            *(float4*)&As[kk][x8]     = v0;
            *(float4*)&As[kk][x8 + 4] = v1;
        }
        {
            int row = tid >> 1, c0 = (tid & 1) * 8;
            const float* p = W + (size_t)(bo + row) * K + k0 + c0;
            float4 v0 = *(const float4*)p;
            float4 v1 = *(const float4*)(p + 4);
            Ws[c0+0][row] = v0.x; Ws[c0+1][row] = v0.y;
            Ws[c0+2][row] = v0.z; Ws[c0+3][row] = v0.w;
            Ws[c0+4][row] = v1.x; Ws[c0+5][row] = v1.y;
            Ws[c0+6][row] = v1.z; Ws[c0+7][row] = v1.w;
        }
        __syncthreads();
#pragma unroll
        for (int kk = 0; kk < TBK; kk++) {
            float4 a0 = *(const float4*)&As[kk][tcx];
            float4 a1 = *(const float4*)&As[kk][tcx + 64];
            float4 w0 = *(const float4*)&Ws[kk][tco];
            float4 w1 = *(const float4*)&Ws[kk][tco + 64];
            float a[8] = {a0.x, a0.y, a0.z, a0.w, a1.x, a1.y, a1.z, a1.w};
            float w[8] = {w0.x, w0.y, w0.z, w0.w, w1.x, w1.y, w1.z, w1.w};
#pragma unroll
            for (int i = 0; i < 8; i++)
#pragma unroll
                for (int j = 0; j < 8; j++)
                    acc[i][j] = fmaf(a[i], w[j], acc[i][j]);
        }
        __syncthreads();
    }
#pragma unroll
    for (int i = 0; i < 8; i++) {
        int xx = bx + (i < 4 ? tcx + i : 64 + tcx + (i - 4));
#pragma unroll
        for (int jh = 0; jh < 2; jh++) {
            int oo = bo + tco + jh * 64;
            float vr[4];
#pragma unroll
            for (int j = 0; j < 4; j++) vr[j] = acc[i][jh * 4 + j];
            if (bias) {
#pragma unroll
                for (int j = 0; j < 4; j++) vr[j] += bias[oo + j];
            }
            if (OUT_XO) {
                size_t ix = (size_t)xx * O + oo;
                if (resid) {
                    float4 rv = *(const float4*)(resid + (size_t)b * sC + ix);
                    vr[0] += rv.x; vr[1] += rv.y; vr[2] += rv.z; vr[3] += rv.w;
                }
                float4 ov = {vr[0], vr[1], vr[2], vr[3]};
                *(float4*)(Cb + ix) = ov;
            } else {
#pragma unroll
                for (int j = 0; j < 4; j++) {
                    size_t ix = (size_t)(oo + j) * X + xx;
                    float v = vr[j];
                    if (resid) v += resid[(size_t)b * sC + ix];
                    Cb[ix] = v;
                }
            }
        }
    }
}

// ---------------- KNN --------------------------------------------------------
__global__ __launch_bounds__(128)
void knn_kernel(const float* __restrict__ pf,
                const float* __restrict__ seed,
                int* __restrict__ idx_out)
{
    __shared__ float sx[MM], sy[MM], sz[MM], ss[MM];
    __shared__ float sd[4][MM];
    int b = blockIdx.y;
    const float* sb = seed + (size_t)b * MM * 3;
    for (int j = threadIdx.x; j < MM; j += 128) {
        float x = sb[j*3], y = sb[j*3+1], z = sb[j*3+2];
        sx[j] = x; sy[j] = y; sz[j] = z; ss[j] = x*x + y*y + z*z;
    }
    __syncthreads();
    int w = threadIdx.x >> 5, lane = threadIdx.x & 31;
    int n = blockIdx.x * 4 + w;
    const float* q = pf + ((size_t)b * NN + n) * 3;
    float qx = q[0], qy = q[1], qz = q[2];
    float qn = qx*qx + qy*qy + qz*qz;
    float* d = sd[w];
    for (int j = lane; j < MM; j += 32)
        d[j] = qn + ss[j] - 2.f * (qx*sx[j] + qy*sy[j] + qz*sz[j]);
    __syncwarp();
    int* out = idx_out + ((size_t)b * NN + n) * KNB;
    for (int t = 0; t < KNB; t++) {
        float best = 1e30f; int bi = 0;
        for (int j = lane; j < MM; j += 32) {
            float v = d[j];
            if (v < best || (v == best && j < bi)) { best = v; bi = j; }
        }
#pragma unroll
        for (int off = 16; off; off >>= 1) {
            float ov = __shfl_xor_sync(0xffffffffu, best, off);
            int   oi = __shfl_xor_sync(0xffffffffu, bi, off);
            if (ov < best || (ov == best && oi < bi)) { best = ov; bi = oi; }
        }
        if (lane == 0) out[t] = bi;
        if (lane == (bi & 31)) d[bi] = 1e30f;
        __syncwarp();
    }
}

// ---------------- geometry -> hrelu (R,64) fp16 ------------------------------
__global__ __launch_bounds__(256)
void geom_kernel(const float* __restrict__ pos,
                 const float* __restrict__ seed,
                 const int*   __restrict__ idxg,
                 const float* __restrict__ pw1,
                 const float* __restrict__ aP, const float* __restrict__ cP,
                 __half* __restrict__ hrelu)
{
    int r = blockIdx.x * 256 + threadIdx.x;
    int b = r >> 16;
    int n = (r >> 4) & (NN - 1);
    int j = idxg[r];
    float px = pos[((size_t)b * 3 + 0) * NN + n];
    float py = pos[((size_t)b * 3 + 1) * NN + n];
    float pz = pos[((size_t)b * 3 + 2) * NN + n];
    const float* sj = seed + ((size_t)b * MM + j) * 3;
    float rx = px - sj[0], ry = py - sj[1], rz = pz - sj[2];
    float ds = sqrtf(rx*rx + ry*ry + rz*rz);
    __half2* out = (__half2*)(hrelu + (size_t)r * PHD);
#pragma unroll
    for (int p0 = 0; p0 < PHD; p0 += 2) {
        float t[2];
#pragma unroll
        for (int u = 0; u < 2; u++) {
            int p = p0 + u;
            float raw = __ldg(&pw1[p*4]) * ds + __ldg(&pw1[p*4+1]) * rx
                      + __ldg(&pw1[p*4+2]) * ry + __ldg(&pw1[p*4+3]) * rz;
            t[u] = fmaxf(raw * __ldg(&aP[p]) + __ldg(&cP[p]), 0.f);
        }
        out[p0 >> 1] = __floats2half2_rn(t[0], t[1]);
    }
}

// ---------------- launch -----------------------------------------------------
extern "C" void kernel_launch(void* const* d_in, const int* in_sizes, int n_in,
                              void* d_out, int out_size)
{
    const float* pos      = (const float*)d_in[0];
    const float* pf       = (const float*)d_in[1];
    const float* fea      = (const float*)d_in[2];
    const float* seed     = (const float*)d_in[3];
    const float* seed_fea = (const float*)d_in[4];
    const float* w_start  = (const float*)d_in[5];
    const float* b_start  = (const float*)d_in[6];
    const float* w_key    = (const float*)d_in[7];
    const float* b_key    = (const float*)d_in[8];
    const float* w_value  = (const float*)d_in[9];
    const float* b_value  = (const float*)d_in[10];
    const float* w_query  = (const float*)d_in[11];
    const float* b_query  = (const float*)d_in[12];
    const float* pos_w1   = (const float*)d_in[13];
    const float* pos_b1   = (const float*)d_in[14];
    const float* pos_g1   = (const float*)d_in[15];
    const float* pos_beta1= (const float*)d_in[16];
    const float* pos_mu1  = (const float*)d_in[17];
    const float* pos_var1 = (const float*)d_in[18];
    const float* pos_w2   = (const float*)d_in[19];
    const float* pos_b2   = (const float*)d_in[20];
    const float* attn_w1  = (const float*)d_in[21];
    const float* attn_b1  = (const float*)d_in[22];
    const float* attn_g1  = (const float*)d_in[23];
    const float* attn_beta1=(const float*)d_in[24];
    const float* attn_mu1 = (const float*)d_in[25];
    const float* attn_var1= (const float*)d_in[26];
    const float* attn_w2  = (const float*)d_in[27];
    // d_in[28] = attn_b2: cancels in softmax over K
    const float* w_end    = (const float*)d_in[29];
    const float* b_end    = (const float*)d_in[30];

    float *valueT, *keyfT, *valftT, *queryT, *W1qt, *W1kt, *aggv, *pre1;
    float *aA, *cA, *aP, *cP;
    __half *hrelu, *hid, *pre1h, *w1h, *w2h, *pw2h;
    int* idx;
    cudaGetSymbolAddress((void**)&valueT, g_valueT);
    cudaGetSymbolAddress((void**)&keyfT,  g_keyfT);
    cudaGetSymbolAddress((void**)&valftT, g_valftT);
    cudaGetSymbolAddress((void**)&queryT, g_queryT);
    cudaGetSymbolAddress((void**)&W1qt,   g_W1qt);
    cudaGetSymbolAddress((void**)&W1kt,   g_W1kt);
    cudaGetSymbolAddress((void**)&idx,    g_idx);
    cudaGetSymbolAddress((void**)&hrelu,  g_hrelu);
    cudaGetSymbolAddress((void**)&hid,    g_hid);
    cudaGetSymbolAddress((void**)&aggv,   g_agg);
    cudaGetSymbolAddress((void**)&pre1,   g_pre1);
    cudaGetSymbolAddress((void**)&pre1h,  g_pre1h);
    cudaGetSymbolAddress((void**)&w1h,    g_w1h);
    cudaGetSymbolAddress((void**)&w2h,    g_w2h);
    cudaGetSymbolAddress((void**)&pw2h,   g_pw2h);
    cudaGetSymbolAddress((void**)&aA,     g_aA);
    cudaGetSymbolAddress((void**)&cA,     g_cA);
    cudaGetSymbolAddress((void**)&aP,     g_aP);
    cudaGetSymbolAddress((void**)&cP,     g_cP);

    precomp_kernel<<<AHD + 1, PHD>>>(attn_w1, pos_w2, pos_b2,
                                     attn_g1, attn_beta1, attn_mu1, attn_var1, attn_b1,
                                     pos_g1, pos_beta1, pos_mu1, pos_var1, pos_b1,
                                     pre1, pre1h, aA, cA, aP, cP);
    cvt_h_kernel<<<(AHD*DD + 255)/256, 256>>>(attn_w1, w1h, AHD*DD);
    cvt_h_kernel<<<(DD*AHD + 255)/256, 256>>>(attn_w2, w2h, DD*AHD);
    cvt_h_kernel<<<(DD*PHD + 255)/256, 256>>>(pos_w2, pw2h, DD*PHD);

    // front GEMMs (SIMT fp32, row-major outputs)
    gemm_k<false,true><<<dim3(MM/128, DD/128, BB), 256>>>(
        w_start, b_start, seed_fea, nullptr, valueT, DD, CC, MM,
        (size_t)CC*MM, (size_t)MM*DD);
    gemm_k<true,true><<<dim3(MM/128, DD/128, BB), 256>>>(
        w_key, b_key, valueT, nullptr, keyfT, DD, DD, MM,
        (size_t)MM*DD, (size_t)MM*DD);
    gemm_k<true,true><<<dim3(MM/128, DD/128, BB), 256>>>(
        w_value, b_value, valueT, nullptr, valftT, DD, DD, MM,
        (size_t)MM*DD, (size_t)MM*DD);
    gemm_k<false,true><<<dim3(NN/128, DD/128, BB), 256>>>(
        w_query, b_query, fea, nullptr, queryT, DD, CC, NN,
        (size_t)CC*NN, (size_t)NN*DD);

    // W1q / W1k via fp16 mma (A staged fp32->fp16)
    hgemm<512,256,0,false,false><<<dim3(4, BB*NN/128), 256>>>(
        w1h, nullptr, queryT, W1qt, nullptr, nullptr, nullptr, nullptr, nullptr);
    hgemm<512,256,0,false,false><<<dim3(4, BB*MM/128), 256>>>(
        w1h, nullptr, keyfT, W1kt, nullptr, nullptr, nullptr, nullptr, nullptr);

    // knn + geometry
    knn_kernel<<<dim3(NN/4, BB), 128>>>(pf, seed, idx);
    geom_kernel<<<RR/256, 256>>>(pos, seed, idx, pos_w1, aP, cP, hrelu);

    // hid = relu(aA*(pre1@hrelu + W1q - W1k) + cA)  -> fp16
    hgemm<512,64,1,true,true><<<dim3(4, RR/128), 256>>>(
        pre1h, nullptr, hrelu, hid, W1qt, W1kt, idx, aA, cA);

    // fused: logits + pe + softmax + gather + aggregate -> aggv
    fused_attn<<<dim3(2, RR/128), 256>>>(
        w2h, hid, pw2h, hrelu, pos_b2, valftT, idx, aggv);

    // out = w_end @ aggv + b_end + fea
    gemm_k<true,false><<<dim3(NN/128, CC/128, BB), 256>>>(
        w_end, b_end, aggv, fea, (float*)d_out, CC, DD, NN,
        (size_t)NN*DD, (size_t)CC*NN);
}

// round 9
// speedup vs baseline: 1.2280x; 1.2280x over previous
#include <cuda_runtime.h>
#include <cuda_fp16.h>
#include <cstdint>
#include <cstddef>

#define BB 4
#define NN 4096
#define MM 1024
#define CC 128
#define DD 256
#define PHD 64
#define AHD 512
#define KNB 16
#define RR (BB*NN*KNB)   // 262144 rows (b,n,k)

// ---------------- static scratch --------------------------------------------
__device__ float  g_valueT[BB*MM*DD];     // (B*M, D)
__device__ float  g_keyfT [BB*MM*DD];
__device__ float  g_valftT[BB*MM*DD];
__device__ float  g_queryT[BB*NN*DD];     // (B*N, D)
__device__ float  g_W1qt  [BB*NN*AHD];    // (B*N, AH) fp32
__device__ float  g_W1kt  [BB*MM*AHD];    // (B*M, AH) fp32
__device__ int    g_idx   [RR];
__device__ __half g_hrelu [16777216];     // (R, 64) fp16
__device__ __half g_hid   [134217728];    // (R, 512) fp16
__device__ float  g_agg   [BB*NN*DD];     // (B*N, 256) aggv
__device__ float  g_pre1  [AHD*PHD];
__device__ __half g_pre1h [AHD*PHD];
__device__ __half g_w1h   [AHD*DD];       // attn_w1 fp16
__device__ __half g_w2h   [DD*AHD];       // attn_w2 fp16
__device__ __half g_pw2h  [DD*PHD];       // pos_w2 fp16
__device__ float  g_aA[AHD], g_cA[AHD], g_aP[PHD], g_cP[PHD];

// ---------------- helpers ----------------------------------------------------
__device__ __forceinline__ void mma16816(float* d, const uint32_t* a,
                                         uint32_t b0, uint32_t b1) {
    asm volatile(
        "mma.sync.aligned.m16n8k16.row.col.f32.f16.f16.f32 "
        "{%0,%1,%2,%3},{%4,%5,%6,%7},{%8,%9},{%0,%1,%2,%3};"
        : "+f"(d[0]), "+f"(d[1]), "+f"(d[2]), "+f"(d[3])
        : "r"(a[0]), "r"(a[1]), "r"(a[2]), "r"(a[3]), "r"(b0), "r"(b1));
}
__device__ __forceinline__ uint32_t packh2(float x, float y) {
    __half2 h = __floats2half2_rn(x, y);
    return *(uint32_t*)&h;
}

// ---------------- fp16 mma GEMM (round-7 proven): C = A(rows,K)@W(O,K)^T -----
// BM=128, BN=128, BK=32. 256 threads = 8 warps (4M x 2N), warp tile 32x64.
// Smem: half2 words, [128][20] (16 data + 4 pad) -> conflict-free scalar LDS.
// EPI 0: C = acc (+bias fp32).   EPI 1: C = relu((acc+W1q-W1k)*aA+cA)
template<int O, int K, int EPI, bool AF16, bool OUTH>
__global__ __launch_bounds__(256)
void hgemm(const __half* __restrict__ Wh, const float* __restrict__ bias,
           const void* __restrict__ Ag, void* __restrict__ Cg,
           const float* __restrict__ W1q, const float* __restrict__ W1k,
           const int* __restrict__ idxg,
           const float* __restrict__ aA, const float* __restrict__ cA)
{
    constexpr int CCH = K / 32;
    __shared__ __align__(16) __half2 As2[128][20];
    __shared__ __align__(16) __half2 Bs2[128][20];
    const int row0 = blockIdx.y * 128;
    const int o0   = blockIdx.x * 128;
    const int tid  = threadIdx.x;
    const int lane = tid & 31;
    const int wid  = tid >> 5;
    const int wm = wid & 3;
    const int wn = wid >> 2;
    const int lq = lane >> 2;
    const int lr = lane & 3;

    float acc[2][8][4];
#pragma unroll
    for (int mt = 0; mt < 2; mt++)
#pragma unroll
        for (int nt = 0; nt < 8; nt++)
#pragma unroll
            for (int q = 0; q < 4; q++) acc[mt][nt][q] = 0.f;

    uint4  ra[2], rbv[2];
    float4 fa[2][2];

    auto fetch = [&](int c) {
        if (AF16) {
            const __half* s = (const __half*)Ag +
                (size_t)(row0 + (tid >> 1)) * K + c * 32 + (tid & 1) * 16;
            ra[0] = *(const uint4*)s;
            ra[1] = *(const uint4*)(s + 8);
        } else {
#pragma unroll
            for (int i = 0; i < 2; i++) {
                int lin = tid + i * 256;
                int r = lin >> 2, cq = (lin & 3) * 4;
                const float* s = (const float*)Ag +
                    (size_t)(row0 + r) * K + c * 32 + cq * 2;
                fa[i][0] = *(const float4*)s;
                fa[i][1] = *(const float4*)(s + 4);
            }
        }
        const __half* w = Wh + (size_t)(o0 + (tid >> 1)) * K + c * 32 + (tid & 1) * 16;
        rbv[0] = *(const uint4*)w;
        rbv[1] = *(const uint4*)(w + 8);
    };
    auto store = [&]() {
        int r = tid >> 1, c0 = (tid & 1) * 8;
        if (AF16) {
            *(uint4*)&As2[r][c0]     = ra[0];
            *(uint4*)&As2[r][c0 + 4] = ra[1];
        } else {
#pragma unroll
            for (int i = 0; i < 2; i++) {
                int lin = tid + i * 256;
                int rr = lin >> 2, cq = (lin & 3) * 4;
                uint4 u;
                u.x = packh2(fa[i][0].x, fa[i][0].y);
                u.y = packh2(fa[i][0].z, fa[i][0].w);
                u.z = packh2(fa[i][1].x, fa[i][1].y);
                u.w = packh2(fa[i][1].z, fa[i][1].w);
                *(uint4*)&As2[rr][cq] = u;
            }
        }
        *(uint4*)&Bs2[r][c0]     = rbv[0];
        *(uint4*)&Bs2[r][c0 + 4] = rbv[1];
    };

    fetch(0);
#pragma unroll 1
    for (int c = 0; c < CCH; c++) {
        store();
        __syncthreads();
        if (c + 1 < CCH) fetch(c + 1);
#pragma unroll
        for (int ks = 0; ks < 2; ks++) {
            const int kb = ks * 8 + lr;
            uint32_t bf[8][2];
#pragma unroll
            for (int nt = 0; nt < 8; nt++) {
                int cb = wn * 64 + nt * 8 + lq;
                bf[nt][0] = *(const uint32_t*)&Bs2[cb][kb];
                bf[nt][1] = *(const uint32_t*)&Bs2[cb][kb + 4];
            }
#pragma unroll
            for (int mt = 0; mt < 2; mt++) {
                int rb = wm * 32 + mt * 16 + lq;
                uint32_t a[4];
                a[0] = *(const uint32_t*)&As2[rb][kb];
                a[1] = *(const uint32_t*)&As2[rb + 8][kb];
                a[2] = *(const uint32_t*)&As2[rb][kb + 4];
                a[3] = *(const uint32_t*)&As2[rb + 8][kb + 4];
#pragma unroll
                for (int nt = 0; nt < 8; nt++)
                    mma16816(acc[mt][nt], a, bf[nt][0], bf[nt][1]);
            }
        }
        __syncthreads();
    }

    // ---- epilogue ----
#pragma unroll
    for (int mt = 0; mt < 2; mt++) {
#pragma unroll
        for (int h = 0; h < 2; h++) {
            int r = row0 + wm * 32 + mt * 16 + h * 8 + lq;
            const float* qp = nullptr;
            const float* kp = nullptr;
            if (EPI == 1) {
                int bbx = r >> 16;
                int jj = idxg[r];
                qp = W1q + (size_t)(r >> 4) * AHD;
                kp = W1k + ((size_t)bbx * MM + jj) * AHD;
            }
#pragma unroll
            for (int nt = 0; nt < 8; nt++) {
                int o = o0 + wn * 64 + nt * 8 + lr * 2;
                float v0 = acc[mt][nt][h * 2 + 0];
                float v1 = acc[mt][nt][h * 2 + 1];
                if (EPI == 0) {
                    if (bias) { v0 += bias[o]; v1 += bias[o + 1]; }
                } else {
                    float2 qv = *(const float2*)(qp + o);
                    float2 kv = *(const float2*)(kp + o);
                    float2 av = *(const float2*)(aA + o);
                    float2 cv = *(const float2*)(cA + o);
                    v0 = fmaxf((v0 + qv.x - kv.x) * av.x + cv.x, 0.f);
                    v1 = fmaxf((v1 + qv.y - kv.y) * av.y + cv.y, 0.f);
                }
                if (OUTH) {
                    __half2 hv = __floats2half2_rn(v0, v1);
                    *(__half2*)((__half*)Cg + (size_t)r * O + o) = hv;
                } else {
                    *(float2*)((float*)Cg + (size_t)r * O + o) = make_float2(v0, v1);
                }
            }
        }
    }
}

// ---------------- fused: pe GEMM -> smem, logits GEMM, softmax+gather+agg ----
// grid (2, RR/128), 256 thr, <=128 regs (2 CTAs/SM). Dynamic smem 55296 B.
__global__ __launch_bounds__(256, 2)
void fused_attn(const __half* __restrict__ w2h,    // (256,512)
                const __half* __restrict__ hid,    // (R,512)
                const __half* __restrict__ pw2h,   // (256,64)
                const __half* __restrict__ hrelu,  // (R,64)
                const float* __restrict__ pb2,     // (256)
                const float* __restrict__ valft,   // (B*M,256)
                const int*   __restrict__ idxg,
                float* __restrict__ aggv)          // (B*N,256)
{
    extern __shared__ char dsm[];
    __half2 (*As2)[20] = (__half2(*)[20])(dsm);            // 10240 B
    __half2 (*Bs2)[20] = (__half2(*)[20])(dsm + 10240);    // 10240 B
    __half2 (*sPE)[68] = (__half2(*)[68])(dsm + 20480);    // 34816 B
    __shared__ int sidx[128];
    const int row0 = blockIdx.y * 128;
    const int o0   = blockIdx.x * 128;
    const int tid  = threadIdx.x;
    const int lane = tid & 31;
    const int wid  = tid >> 5;
    const int wm = wid & 3;
    const int wn = wid >> 2;
    const int lq = lane >> 2;
    const int lr = lane & 3;

    if (tid < 128) sidx[tid] = idxg[row0 + tid];

    uint4 ra[2], rb[2];
    const __half* Ap;
    const __half* Wp;
    int Kd;
    auto fetch = [&](int c) {
        const __half* s = Ap + (size_t)(row0 + (tid >> 1)) * Kd + c * 32 + (tid & 1) * 16;
        ra[0] = *(const uint4*)s;
        ra[1] = *(const uint4*)(s + 8);
        const __half* w = Wp + (size_t)(o0 + (tid >> 1)) * Kd + c * 32 + (tid & 1) * 16;
        rb[0] = *(const uint4*)w;
        rb[1] = *(const uint4*)(w + 8);
    };
    auto store = [&]() {
        int r = tid >> 1, c0 = (tid & 1) * 8;
        *(uint4*)&As2[r][c0]     = ra[0];
        *(uint4*)&As2[r][c0 + 4] = ra[1];
        *(uint4*)&Bs2[r][c0]     = rb[0];
        *(uint4*)&Bs2[r][c0 + 4] = rb[1];
    };
    auto mma_all = [&](float (&acc)[2][8][4]) {
#pragma unroll
        for (int ks = 0; ks < 2; ks++) {
            const int kb = ks * 8 + lr;
            uint32_t bf[8][2];
#pragma unroll
            for (int nt = 0; nt < 8; nt++) {
                int cb = wn * 64 + nt * 8 + lq;
                bf[nt][0] = *(const uint32_t*)&Bs2[cb][kb];
                bf[nt][1] = *(const uint32_t*)&Bs2[cb][kb + 4];
            }
#pragma unroll
            for (int mt = 0; mt < 2; mt++) {
                int rb2 = wm * 32 + mt * 16 + lq;
                uint32_t a[4];
                a[0] = *(const uint32_t*)&As2[rb2][kb];
                a[1] = *(const uint32_t*)&As2[rb2 + 8][kb];
                a[2] = *(const uint32_t*)&As2[rb2][kb + 4];
                a[3] = *(const uint32_t*)&As2[rb2 + 8][kb + 4];
#pragma unroll
                for (int nt = 0; nt < 8; nt++)
                    mma16816(acc[mt][nt], a, bf[nt][0], bf[nt][1]);
            }
        }
    };

    // ---- phase 1: pe = pos_w2 @ hrelu -> sPE (fp16, +pb2) ----
    {
        float acc2[2][8][4];
#pragma unroll
        for (int mt = 0; mt < 2; mt++)
#pragma unroll
            for (int nt = 0; nt < 8; nt++)
#pragma unroll
                for (int q = 0; q < 4; q++) acc2[mt][nt][q] = 0.f;
        Ap = hrelu; Wp = pw2h; Kd = PHD;
        fetch(0);
#pragma unroll 1
        for (int c = 0; c < PHD / 32; c++) {
            store();
            __syncthreads();
            if (c + 1 < PHD / 32) fetch(c + 1);
            mma_all(acc2);
            __syncthreads();
        }
#pragma unroll
        for (int mt = 0; mt < 2; mt++)
#pragma unroll
            for (int nt = 0; nt < 8; nt++) {
                int cch = o0 + wn * 64 + nt * 8 + lr * 2;
                float2 pbv = *(const float2*)(pb2 + cch);
                sPE[wm*32 + mt*16 + lq][wn*32 + nt*4 + lr] =
                    __floats2half2_rn(acc2[mt][nt][0] + pbv.x, acc2[mt][nt][1] + pbv.y);
                sPE[wm*32 + mt*16 + 8 + lq][wn*32 + nt*4 + lr] =
                    __floats2half2_rn(acc2[mt][nt][2] + pbv.x, acc2[mt][nt][3] + pbv.y);
            }
    }

    // ---- phase 2: logits = attn_w2 @ hid ----
    float acc1[2][8][4];
#pragma unroll
    for (int mt = 0; mt < 2; mt++)
#pragma unroll
        for (int nt = 0; nt < 8; nt++)
#pragma unroll
            for (int q = 0; q < 4; q++) acc1[mt][nt][q] = 0.f;
    Ap = hid; Wp = w2h; Kd = AHD;
    fetch(0);
#pragma unroll 1
    for (int c = 0; c < AHD / 32; c++) {
        store();
        __syncthreads();
        if (c + 1 < AHD / 32) fetch(c + 1);
        mma_all(acc1);
        __syncthreads();
    }

    // ---- softmax over k (16 rows per point, within warp) + gather + agg ----
    const int bb = row0 >> 16;
#pragma unroll
    for (int mt = 0; mt < 2; mt++) {
        const int pt = (row0 + wm * 32 + mt * 16) >> 4;
        const int j0 = sidx[wm * 32 + mt * 16 + lq];
        const int j1 = sidx[wm * 32 + mt * 16 + 8 + lq];
        const float* v0b = valft + ((size_t)bb * MM + j0) * DD;
        const float* v1b = valft + ((size_t)bb * MM + j1) * DD;
#pragma unroll
        for (int nt = 0; nt < 8; nt++) {
            const int c = o0 + wn * 64 + nt * 8 + lr * 2;
            float2 vv0 = *(const float2*)(v0b + c);
            float2 vv1 = *(const float2*)(v1b + c);
            float2 p0 = __half22float2(sPE[wm*32 + mt*16 + lq][wn*32 + nt*4 + lr]);
            float2 p1 = __half22float2(sPE[wm*32 + mt*16 + 8 + lq][wn*32 + nt*4 + lr]);
            float outc[2];
#pragma unroll
            for (int j = 0; j < 2; j++) {
                float l0 = acc1[mt][nt][j];
                float l1 = acc1[mt][nt][2 + j];
                float m = fmaxf(l0, l1);
                m = fmaxf(m, __shfl_xor_sync(0xffffffffu, m, 4));
                m = fmaxf(m, __shfl_xor_sync(0xffffffffu, m, 8));
                m = fmaxf(m, __shfl_xor_sync(0xffffffffu, m, 16));
                float e0 = __expf(l0 - m), e1 = __expf(l1 - m);
                float S = e0 + e1;
                S += __shfl_xor_sync(0xffffffffu, S, 4);
                S += __shfl_xor_sync(0xffffffffu, S, 8);
                S += __shfl_xor_sync(0xffffffffu, S, 16);
                float pe0 = j ? p0.y : p0.x;
                float pe1 = j ? p1.y : p1.x;
                float va0 = j ? vv0.y : vv0.x;
                float va1 = j ? vv1.y : vv1.x;
                float T = e0 * (va0 + pe0) + e1 * (va1 + pe1);
                T += __shfl_xor_sync(0xffffffffu, T, 4);
                T += __shfl_xor_sync(0xffffffffu, T, 8);
                T += __shfl_xor_sync(0xffffffffu, T, 16);
                outc[j] = T / S;
            }
            if (lq == 0)
                *(float2*)(aggv + (size_t)pt * DD + c) = make_float2(outc[0], outc[1]);
        }
    }
}

// ---------------- precompute + weight conversions ----------------------------
__global__ void precomp_kernel(const float* __restrict__ w1,
                               const float* __restrict__ pw2,
                               const float* __restrict__ pb2,
                               const float* __restrict__ ag, const float* __restrict__ abeta,
                               const float* __restrict__ amu, const float* __restrict__ avar,
                               const float* __restrict__ ab1,
                               const float* __restrict__ pg, const float* __restrict__ pbeta,
                               const float* __restrict__ pmu, const float* __restrict__ pvar,
                               const float* __restrict__ pb1,
                               float* __restrict__ pre1, __half* __restrict__ pre1h,
                               float* __restrict__ aA,
                               float* __restrict__ cA, float* __restrict__ aP,
                               float* __restrict__ cP)
{
    int o = blockIdx.x;
    if (o < AHD) {
        int p = threadIdx.x;
        float s = 0.f;
        for (int c = 0; c < DD; c++) s += w1[o*DD + c] * pw2[c*PHD + p];
        pre1[o*PHD + p] = s;
        pre1h[o*PHD + p] = __float2half_rn(s);
        if (p == 0) {
            float vb = 0.f;
            for (int c = 0; c < DD; c++) vb += w1[o*DD + c] * pb2[c];
            float inv = ag[o] / sqrtf(avar[o] + 1e-5f);
            aA[o] = inv;
            cA[o] = (ab1[o] - amu[o]) * inv + abeta[o] + vb * inv;
        }
    } else {
        int p = threadIdx.x;
        float inv = pg[p] / sqrtf(pvar[p] + 1e-5f);
        aP[p] = inv;
        cP[p] = (pb1[p] - pmu[p]) * inv + pbeta[p];
    }
}

__global__ void cvt_h_kernel(const float* __restrict__ s, __half* __restrict__ d, int n)
{
    int i = blockIdx.x * 256 + threadIdx.x;
    if (i < n) d[i] = __float2half_rn(s[i]);
}

// ---------------- SIMT fp32 GEMM (small front/end GEMMs) ---------------------
constexpr int TBO = 128, TBX = 128, TBK = 16;

template<bool A_RM, bool OUT_XO>
__global__ __launch_bounds__(256)
void gemm_k(const float* __restrict__ W, const float* __restrict__ bias,
            const float* __restrict__ A, const float* __restrict__ resid,
            float* __restrict__ C, int O, int K, int X, size_t sA, size_t sC)
{
    __shared__ float As[TBK][TBX];
    __shared__ float Ws[TBK][TBO];
    const int bx = blockIdx.x * TBX;
    const int bo = blockIdx.y * TBO;
    const int b  = blockIdx.z;
    const float* Ab = A + (size_t)b * sA;
    float* Cb = C + (size_t)b * sC;
    const int tid = threadIdx.x;
    const int tco = (tid & 15) * 4;
    const int tcx = (tid >> 4) * 4;

    float acc[8][8];
#pragma unroll
    for (int i = 0; i < 8; i++)
#pragma unroll
        for (int j = 0; j < 8; j++) acc[i][j] = 0.f;

    for (int k0 = 0; k0 < K; k0 += TBK) {
        if (A_RM) {
            int row = tid >> 1, c0 = (tid & 1) * 8;
            const float* p = Ab + (size_t)(bx + row) * K + k0 + c0;
            float4 v0 = *(const float4*)p;
            float4 v1 = *(const float4*)(p + 4);
            As[c0+0][row] = v0.x; As[c0+1][row] = v0.y;
            As[c0+2][row] = v0.z; As[c0+3][row] = v0.w;
            As[c0+4][row] = v1.x; As[c0+5][row] = v1.y;
            As[c0+6][row] = v1.z; As[c0+7][row] = v1.w;
        } else {
            int kk = tid >> 4, x8 = (tid & 15) * 8;
            const float* p = Ab + (size_t)(k0 + kk) * X + bx + x8;
            float4 v0 = *(const float4*)p;
            float4 v1 = *(const float4*)(p + 4);
            *(float4*)&As[kk][x8]     = v0;
            *(float4*)&As[kk][x8 + 4] = v1;
        }
        {
            int row = tid >> 1, c0 = (tid & 1) * 8;
            const float* p = W + (size_t)(bo + row) * K + k0 + c0;
            float4 v0 = *(const float4*)p;
            float4 v1 = *(const float4*)(p + 4);
            Ws[c0+0][row] = v0.x; Ws[c0+1][row] = v0.y;
            Ws[c0+2][row] = v0.z; Ws[c0+3][row] = v0.w;
            Ws[c0+4][row] = v1.x; Ws[c0+5][row] = v1.y;
            Ws[c0+6][row] = v1.z; Ws[c0+7][row] = v1.w;
        }
        __syncthreads();
#pragma unroll
        for (int kk = 0; kk < TBK; kk++) {
            float4 a0 = *(const float4*)&As[kk][tcx];
            float4 a1 = *(const float4*)&As[kk][tcx + 64];
            float4 w0 = *(const float4*)&Ws[kk][tco];
            float4 w1 = *(const float4*)&Ws[kk][tco + 64];
            float a[8] = {a0.x, a0.y, a0.z, a0.w, a1.x, a1.y, a1.z, a1.w};
            float w[8] = {w0.x, w0.y, w0.z, w0.w, w1.x, w1.y, w1.z, w1.w};
#pragma unroll
            for (int i = 0; i < 8; i++)
#pragma unroll
                for (int j = 0; j < 8; j++)
                    acc[i][j] = fmaf(a[i], w[j], acc[i][j]);
        }
        __syncthreads();
    }
#pragma unroll
    for (int i = 0; i < 8; i++) {
        int xx = bx + (i < 4 ? tcx + i : 64 + tcx + (i - 4));
#pragma unroll
        for (int jh = 0; jh < 2; jh++) {
            int oo = bo + tco + jh * 64;
            float vr[4];
#pragma unroll
            for (int j = 0; j < 4; j++) vr[j] = acc[i][jh * 4 + j];
            if (bias) {
#pragma unroll
                for (int j = 0; j < 4; j++) vr[j] += bias[oo + j];
            }
            if (OUT_XO) {
                size_t ix = (size_t)xx * O + oo;
                if (resid) {
                    float4 rv = *(const float4*)(resid + (size_t)b * sC + ix);
                    vr[0] += rv.x; vr[1] += rv.y; vr[2] += rv.z; vr[3] += rv.w;
                }
                float4 ov = {vr[0], vr[1], vr[2], vr[3]};
                *(float4*)(Cb + ix) = ov;
            } else {
#pragma unroll
                for (int j = 0; j < 4; j++) {
                    size_t ix = (size_t)(oo + j) * X + xx;
                    float v = vr[j];
                    if (resid) v += resid[(size_t)b * sC + ix];
                    Cb[ix] = v;
                }
            }
        }
    }
}

// ---------------- KNN --------------------------------------------------------
__global__ __launch_bounds__(128)
void knn_kernel(const float* __restrict__ pf,
                const float* __restrict__ seed,
                int* __restrict__ idx_out)
{
    __shared__ float sx[MM], sy[MM], sz[MM], ss[MM];
    __shared__ float sd[4][MM];
    int b = blockIdx.y;
    const float* sb = seed + (size_t)b * MM * 3;
    for (int j = threadIdx.x; j < MM; j += 128) {
        float x = sb[j*3], y = sb[j*3+1], z = sb[j*3+2];
        sx[j] = x; sy[j] = y; sz[j] = z; ss[j] = x*x + y*y + z*z;
    }
    __syncthreads();
    int w = threadIdx.x >> 5, lane = threadIdx.x & 31;
    int n = blockIdx.x * 4 + w;
    const float* q = pf + ((size_t)b * NN + n) * 3;
    float qx = q[0], qy = q[1], qz = q[2];
    float qn = qx*qx + qy*qy + qz*qz;
    float* d = sd[w];
    for (int j = lane; j < MM; j += 32)
        d[j] = qn + ss[j] - 2.f * (qx*sx[j] + qy*sy[j] + qz*sz[j]);
    __syncwarp();
    int* out = idx_out + ((size_t)b * NN + n) * KNB;
    for (int t = 0; t < KNB; t++) {
        float best = 1e30f; int bi = 0;
        for (int j = lane; j < MM; j += 32) {
            float v = d[j];
            if (v < best || (v == best && j < bi)) { best = v; bi = j; }
        }
#pragma unroll
        for (int off = 16; off; off >>= 1) {
            float ov = __shfl_xor_sync(0xffffffffu, best, off);
            int   oi = __shfl_xor_sync(0xffffffffu, bi, off);
            if (ov < best || (ov == best && oi < bi)) { best = ov; bi = oi; }
        }
        if (lane == 0) out[t] = bi;
        if (lane == (bi & 31)) d[bi] = 1e30f;
        __syncwarp();
    }
}

// ---------------- geometry -> hrelu (R,64) fp16 ------------------------------
__global__ __launch_bounds__(256)
void geom_kernel(const float* __restrict__ pos,
                 const float* __restrict__ seed,
                 const int*   __restrict__ idxg,
                 const float* __restrict__ pw1,
                 const float* __restrict__ aP, const float* __restrict__ cP,
                 __half* __restrict__ hrelu)
{
    int r = blockIdx.x * 256 + threadIdx.x;
    int b = r >> 16;
    int n = (r >> 4) & (NN - 1);
    int j = idxg[r];
    float px = pos[((size_t)b * 3 + 0) * NN + n];
    float py = pos[((size_t)b * 3 + 1) * NN + n];
    float pz = pos[((size_t)b * 3 + 2) * NN + n];
    const float* sj = seed + ((size_t)b * MM + j) * 3;
    float rx = px - sj[0], ry = py - sj[1], rz = pz - sj[2];
    float ds = sqrtf(rx*rx + ry*ry + rz*rz);
    __half2* out = (__half2*)(hrelu + (size_t)r * PHD);
#pragma unroll
    for (int p0 = 0; p0 < PHD; p0 += 2) {
        float t[2];
#pragma unroll
        for (int u = 0; u < 2; u++) {
            int p = p0 + u;
            float raw = __ldg(&pw1[p*4]) * ds + __ldg(&pw1[p*4+1]) * rx
                      + __ldg(&pw1[p*4+2]) * ry + __ldg(&pw1[p*4+3]) * rz;
            t[u] = fmaxf(raw * __ldg(&aP[p]) + __ldg(&cP[p]), 0.f);
        }
        out[p0 >> 1] = __floats2half2_rn(t[0], t[1]);
    }
}

// ---------------- launch -----------------------------------------------------
extern "C" void kernel_launch(void* const* d_in, const int* in_sizes, int n_in,
                              void* d_out, int out_size)
{
    const float* pos      = (const float*)d_in[0];
    const float* pf       = (const float*)d_in[1];
    const float* fea      = (const float*)d_in[2];
    const float* seed     = (const float*)d_in[3];
    const float* seed_fea = (const float*)d_in[4];
    const float* w_start  = (const float*)d_in[5];
    const float* b_start  = (const float*)d_in[6];
    const float* w_key    = (const float*)d_in[7];
    const float* b_key    = (const float*)d_in[8];
    const float* w_value  = (const float*)d_in[9];
    const float* b_value  = (const float*)d_in[10];
    const float* w_query  = (const float*)d_in[11];
    const float* b_query  = (const float*)d_in[12];
    const float* pos_w1   = (const float*)d_in[13];
    const float* pos_b1   = (const float*)d_in[14];
    const float* pos_g1   = (const float*)d_in[15];
    const float* pos_beta1= (const float*)d_in[16];
    const float* pos_mu1  = (const float*)d_in[17];
    const float* pos_var1 = (const float*)d_in[18];
    const float* pos_w2   = (const float*)d_in[19];
    const float* pos_b2   = (const float*)d_in[20];
    const float* attn_w1  = (const float*)d_in[21];
    const float* attn_b1  = (const float*)d_in[22];
    const float* attn_g1  = (const float*)d_in[23];
    const float* attn_beta1=(const float*)d_in[24];
    const float* attn_mu1 = (const float*)d_in[25];
    const float* attn_var1= (const float*)d_in[26];
    const float* attn_w2  = (const float*)d_in[27];
    // d_in[28] = attn_b2: cancels in softmax over K
    const float* w_end    = (const float*)d_in[29];
    const float* b_end    = (const float*)d_in[30];

    float *valueT, *keyfT, *valftT, *queryT, *W1qt, *W1kt, *aggv, *pre1;
    float *aA, *cA, *aP, *cP;
    __half *hrelu, *hid, *pre1h, *w1h, *w2h, *pw2h;
    int* idx;
    cudaGetSymbolAddress((void**)&valueT, g_valueT);
    cudaGetSymbolAddress((void**)&keyfT,  g_keyfT);
    cudaGetSymbolAddress((void**)&valftT, g_valftT);
    cudaGetSymbolAddress((void**)&queryT, g_queryT);
    cudaGetSymbolAddress((void**)&W1qt,   g_W1qt);
    cudaGetSymbolAddress((void**)&W1kt,   g_W1kt);
    cudaGetSymbolAddress((void**)&idx,    g_idx);
    cudaGetSymbolAddress((void**)&hrelu,  g_hrelu);
    cudaGetSymbolAddress((void**)&hid,    g_hid);
    cudaGetSymbolAddress((void**)&aggv,   g_agg);
    cudaGetSymbolAddress((void**)&pre1,   g_pre1);
    cudaGetSymbolAddress((void**)&pre1h,  g_pre1h);
    cudaGetSymbolAddress((void**)&w1h,    g_w1h);
    cudaGetSymbolAddress((void**)&w2h,    g_w2h);
    cudaGetSymbolAddress((void**)&pw2h,   g_pw2h);
    cudaGetSymbolAddress((void**)&aA,     g_aA);
    cudaGetSymbolAddress((void**)&cA,     g_cA);
    cudaGetSymbolAddress((void**)&aP,     g_aP);
    cudaGetSymbolAddress((void**)&cP,     g_cP);

    cudaFuncSetAttribute(fused_attn, cudaFuncAttributeMaxDynamicSharedMemorySize, 55296);

    precomp_kernel<<<AHD + 1, PHD>>>(attn_w1, pos_w2, pos_b2,
                                     attn_g1, attn_beta1, attn_mu1, attn_var1, attn_b1,
                                     pos_g1, pos_beta1, pos_mu1, pos_var1, pos_b1,
                                     pre1, pre1h, aA, cA, aP, cP);
    cvt_h_kernel<<<(AHD*DD + 255)/256, 256>>>(attn_w1, w1h, AHD*DD);
    cvt_h_kernel<<<(DD*AHD + 255)/256, 256>>>(attn_w2, w2h, DD*AHD);
    cvt_h_kernel<<<(DD*PHD + 255)/256, 256>>>(pos_w2, pw2h, DD*PHD);

    // front GEMMs (SIMT fp32, row-major outputs)
    gemm_k<false,true><<<dim3(MM/128, DD/128, BB), 256>>>(
        w_start, b_start, seed_fea, nullptr, valueT, DD, CC, MM,
        (size_t)CC*MM, (size_t)MM*DD);
    gemm_k<true,true><<<dim3(MM/128, DD/128, BB), 256>>>(
        w_key, b_key, valueT, nullptr, keyfT, DD, DD, MM,
        (size_t)MM*DD, (size_t)MM*DD);
    gemm_k<true,true><<<dim3(MM/128, DD/128, BB), 256>>>(
        w_value, b_value, valueT, nullptr, valftT, DD, DD, MM,
        (size_t)MM*DD, (size_t)MM*DD);
    gemm_k<false,true><<<dim3(NN/128, DD/128, BB), 256>>>(
        w_query, b_query, fea, nullptr, queryT, DD, CC, NN,
        (size_t)CC*NN, (size_t)NN*DD);

    // W1q / W1k via fp16 mma (A staged fp32->fp16)
    hgemm<512,256,0,false,false><<<dim3(4, BB*NN/128), 256>>>(
        w1h, nullptr, queryT, W1qt, nullptr, nullptr, nullptr, nullptr, nullptr);
    hgemm<512,256,0,false,false><<<dim3(4, BB*MM/128), 256>>>(
        w1h, nullptr, keyfT, W1kt, nullptr, nullptr, nullptr, nullptr, nullptr);

    // knn + geometry
    knn_kernel<<<dim3(NN/4, BB), 128>>>(pf, seed, idx);
    geom_kernel<<<RR/256, 256>>>(pos, seed, idx, pos_w1, aP, cP, hrelu);

    // hid = relu(aA*(pre1@hrelu + W1q - W1k) + cA)  -> fp16
    hgemm<512,64,1,true,true><<<dim3(4, RR/128), 256>>>(
        pre1h, nullptr, hrelu, hid, W1qt, W1kt, idx, aA, cA);

    // fused: pe + logits + softmax + gather + aggregate -> aggv
    fused_attn<<<dim3(2, RR/128), 256, 55296>>>(
        w2h, hid, pw2h, hrelu, pos_b2, valftT, idx, aggv);

    // out = w_end @ aggv + b_end + fea
    gemm_k<true,false><<<dim3(NN/128, CC/128, BB), 256>>>(
        w_end, b_end, aggv, fea, (float*)d_out, CC, DD, NN,
        (size_t)NN*DD, (size_t)CC*NN);
}

// round 10
// speedup vs baseline: 1.2928x; 1.0527x over previous
#include <cuda_runtime.h>
#include <cuda_fp16.h>
#include <cstdint>
#include <cstddef>

#define BB 4
#define NN 4096
#define MM 1024
#define CC 128
#define DD 256
#define PHD 64
#define AHD 512
#define KNB 16
#define RR (BB*NN*KNB)   // 262144 rows (b,n,k)

// ---------------- static scratch --------------------------------------------
__device__ float  g_valueT[BB*MM*DD];     // (B*M, D)
__device__ float  g_keyfT [BB*MM*DD];
__device__ float  g_valftT[BB*MM*DD];
__device__ float  g_queryT[BB*NN*DD];     // (B*N, D)
__device__ __half g_W1qt  [BB*NN*AHD];    // (B*N, AH) fp16
__device__ __half g_W1kt  [BB*MM*AHD];    // (B*M, AH) fp16
__device__ int    g_idx   [RR];
__device__ __half g_hrelu [16777216];     // (R, 64) fp16
__device__ __half g_hid   [134217728];    // (R, 512) fp16
__device__ float  g_agg   [BB*NN*DD];     // (B*N, 256) aggv
__device__ float  g_pre1  [AHD*PHD];
__device__ __half g_pre1h [AHD*PHD];
__device__ __half g_w1h   [AHD*DD];       // attn_w1 fp16
__device__ __half g_w2h   [DD*AHD];       // attn_w2 fp16
__device__ __half g_pw2h  [DD*PHD];       // pos_w2 fp16
__device__ __half g_wkh   [DD*DD];        // w_key fp16
__device__ __half g_wvh   [DD*DD];        // w_value fp16
__device__ float  g_aA[AHD], g_cA[AHD], g_aP[PHD], g_cP[PHD];

// ---------------- helpers ----------------------------------------------------
__device__ __forceinline__ void mma16816(float* d, const uint32_t* a,
                                         uint32_t b0, uint32_t b1) {
    asm volatile(
        "mma.sync.aligned.m16n8k16.row.col.f32.f16.f16.f32 "
        "{%0,%1,%2,%3},{%4,%5,%6,%7},{%8,%9},{%0,%1,%2,%3};"
        : "+f"(d[0]), "+f"(d[1]), "+f"(d[2]), "+f"(d[3])
        : "r"(a[0]), "r"(a[1]), "r"(a[2]), "r"(a[3]), "r"(b0), "r"(b1));
}
__device__ __forceinline__ uint32_t packh2(float x, float y) {
    __half2 h = __floats2half2_rn(x, y);
    return *(uint32_t*)&h;
}

// ---------------- fp16 mma GEMM (round-7 proven): C = A(rows,K)@W(O,K)^T -----
// BM=128, BN=128, BK=32. 256 threads = 8 warps (4M x 2N), warp tile 32x64.
// Smem: half2 words, [128][20] (16 data + 4 pad) -> conflict-free scalar LDS.
// EPI 0: C = acc (+bias fp32).   EPI 1: C = relu((acc+W1q-W1k)*aA+cA), W1 fp16
template<int O, int K, int EPI, bool AF16, bool OUTH>
__global__ __launch_bounds__(256)
void hgemm(const __half* __restrict__ Wh, const float* __restrict__ bias,
           const void* __restrict__ Ag, void* __restrict__ Cg,
           const __half* __restrict__ W1q, const __half* __restrict__ W1k,
           const int* __restrict__ idxg,
           const float* __restrict__ aA, const float* __restrict__ cA)
{
    constexpr int CCH = K / 32;
    __shared__ __align__(16) __half2 As2[128][20];
    __shared__ __align__(16) __half2 Bs2[128][20];
    const int row0 = blockIdx.y * 128;
    const int o0   = blockIdx.x * 128;
    const int tid  = threadIdx.x;
    const int lane = tid & 31;
    const int wid  = tid >> 5;
    const int wm = wid & 3;
    const int wn = wid >> 2;
    const int lq = lane >> 2;
    const int lr = lane & 3;

    float acc[2][8][4];
#pragma unroll
    for (int mt = 0; mt < 2; mt++)
#pragma unroll
        for (int nt = 0; nt < 8; nt++)
#pragma unroll
            for (int q = 0; q < 4; q++) acc[mt][nt][q] = 0.f;

    uint4  ra[2], rbv[2];
    float4 fa[2][2];

    auto fetch = [&](int c) {
        if (AF16) {
            const __half* s = (const __half*)Ag +
                (size_t)(row0 + (tid >> 1)) * K + c * 32 + (tid & 1) * 16;
            ra[0] = *(const uint4*)s;
            ra[1] = *(const uint4*)(s + 8);
        } else {
#pragma unroll
            for (int i = 0; i < 2; i++) {
                int lin = tid + i * 256;
                int r = lin >> 2, cq = (lin & 3) * 4;
                const float* s = (const float*)Ag +
                    (size_t)(row0 + r) * K + c * 32 + cq * 2;
                fa[i][0] = *(const float4*)s;
                fa[i][1] = *(const float4*)(s + 4);
            }
        }
        const __half* w = Wh + (size_t)(o0 + (tid >> 1)) * K + c * 32 + (tid & 1) * 16;
        rbv[0] = *(const uint4*)w;
        rbv[1] = *(const uint4*)(w + 8);
    };
    auto store = [&]() {
        int r = tid >> 1, c0 = (tid & 1) * 8;
        if (AF16) {
            *(uint4*)&As2[r][c0]     = ra[0];
            *(uint4*)&As2[r][c0 + 4] = ra[1];
        } else {
#pragma unroll
            for (int i = 0; i < 2; i++) {
                int lin = tid + i * 256;
                int rr = lin >> 2, cq = (lin & 3) * 4;
                uint4 u;
                u.x = packh2(fa[i][0].x, fa[i][0].y);
                u.y = packh2(fa[i][0].z, fa[i][0].w);
                u.z = packh2(fa[i][1].x, fa[i][1].y);
                u.w = packh2(fa[i][1].z, fa[i][1].w);
                *(uint4*)&As2[rr][cq] = u;
            }
        }
        *(uint4*)&Bs2[r][c0]     = rbv[0];
        *(uint4*)&Bs2[r][c0 + 4] = rbv[1];
    };

    fetch(0);
#pragma unroll 1
    for (int c = 0; c < CCH; c++) {
        store();
        __syncthreads();
        if (c + 1 < CCH) fetch(c + 1);
#pragma unroll
        for (int ks = 0; ks < 2; ks++) {
            const int kb = ks * 8 + lr;
            uint32_t bf[8][2];
#pragma unroll
            for (int nt = 0; nt < 8; nt++) {
                int cb = wn * 64 + nt * 8 + lq;
                bf[nt][0] = *(const uint32_t*)&Bs2[cb][kb];
                bf[nt][1] = *(const uint32_t*)&Bs2[cb][kb + 4];
            }
#pragma unroll
            for (int mt = 0; mt < 2; mt++) {
                int rb = wm * 32 + mt * 16 + lq;
                uint32_t a[4];
                a[0] = *(const uint32_t*)&As2[rb][kb];
                a[1] = *(const uint32_t*)&As2[rb + 8][kb];
                a[2] = *(const uint32_t*)&As2[rb][kb + 4];
                a[3] = *(const uint32_t*)&As2[rb + 8][kb + 4];
#pragma unroll
                for (int nt = 0; nt < 8; nt++)
                    mma16816(acc[mt][nt], a, bf[nt][0], bf[nt][1]);
            }
        }
        __syncthreads();
    }

    // ---- epilogue ----
#pragma unroll
    for (int mt = 0; mt < 2; mt++) {
#pragma unroll
        for (int h = 0; h < 2; h++) {
            int r = row0 + wm * 32 + mt * 16 + h * 8 + lq;
            const __half* qp = nullptr;
            const __half* kp = nullptr;
            if (EPI == 1) {
                int bbx = r >> 16;
                int jj = idxg[r];
                qp = W1q + (size_t)(r >> 4) * AHD;
                kp = W1k + ((size_t)bbx * MM + jj) * AHD;
            }
#pragma unroll
            for (int nt = 0; nt < 8; nt++) {
                int o = o0 + wn * 64 + nt * 8 + lr * 2;
                float v0 = acc[mt][nt][h * 2 + 0];
                float v1 = acc[mt][nt][h * 2 + 1];
                if (EPI == 0) {
                    if (bias) { v0 += bias[o]; v1 += bias[o + 1]; }
                } else {
                    float2 qv = __half22float2(*(const __half2*)(qp + o));
                    float2 kv = __half22float2(*(const __half2*)(kp + o));
                    float2 av = *(const float2*)(aA + o);
                    float2 cv = *(const float2*)(cA + o);
                    v0 = fmaxf((v0 + qv.x - kv.x) * av.x + cv.x, 0.f);
                    v1 = fmaxf((v1 + qv.y - kv.y) * av.y + cv.y, 0.f);
                }
                if (OUTH) {
                    __half2 hv = __floats2half2_rn(v0, v1);
                    *(__half2*)((__half*)Cg + (size_t)r * O + o) = hv;
                } else {
                    *(float2*)((float*)Cg + (size_t)r * O + o) = make_float2(v0, v1);
                }
            }
        }
    }
}

// ---------------- fused: pe GEMM -> smem, logits GEMM, softmax+gather+agg ----
// grid (2, RR/128), 256 thr, <=128 regs (2 CTAs/SM). Dynamic smem 55296 B.
__global__ __launch_bounds__(256, 2)
void fused_attn(const __half* __restrict__ w2h,    // (256,512)
                const __half* __restrict__ hid,    // (R,512)
                const __half* __restrict__ pw2h,   // (256,64)
                const __half* __restrict__ hrelu,  // (R,64)
                const float* __restrict__ pb2,     // (256)
                const float* __restrict__ valft,   // (B*M,256)
                const int*   __restrict__ idxg,
                float* __restrict__ aggv)          // (B*N,256)
{
    extern __shared__ char dsm[];
    __half2 (*As2)[20] = (__half2(*)[20])(dsm);            // 10240 B
    __half2 (*Bs2)[20] = (__half2(*)[20])(dsm + 10240);    // 10240 B
    __half2 (*sPE)[68] = (__half2(*)[68])(dsm + 20480);    // 34816 B
    __shared__ int sidx[128];
    const int row0 = blockIdx.y * 128;
    const int o0   = blockIdx.x * 128;
    const int tid  = threadIdx.x;
    const int lane = tid & 31;
    const int wid  = tid >> 5;
    const int wm = wid & 3;
    const int wn = wid >> 2;
    const int lq = lane >> 2;
    const int lr = lane & 3;

    if (tid < 128) sidx[tid] = idxg[row0 + tid];

    uint4 ra[2], rb[2];
    const __half* Ap;
    const __half* Wp;
    int Kd;
    auto fetch = [&](int c) {
        const __half* s = Ap + (size_t)(row0 + (tid >> 1)) * Kd + c * 32 + (tid & 1) * 16;
        ra[0] = *(const uint4*)s;
        ra[1] = *(const uint4*)(s + 8);
        const __half* w = Wp + (size_t)(o0 + (tid >> 1)) * Kd + c * 32 + (tid & 1) * 16;
        rb[0] = *(const uint4*)w;
        rb[1] = *(const uint4*)(w + 8);
    };
    auto store = [&]() {
        int r = tid >> 1, c0 = (tid & 1) * 8;
        *(uint4*)&As2[r][c0]     = ra[0];
        *(uint4*)&As2[r][c0 + 4] = ra[1];
        *(uint4*)&Bs2[r][c0]     = rb[0];
        *(uint4*)&Bs2[r][c0 + 4] = rb[1];
    };
    auto mma_all = [&](float (&acc)[2][8][4]) {
#pragma unroll
        for (int ks = 0; ks < 2; ks++) {
            const int kb = ks * 8 + lr;
            uint32_t bf[8][2];
#pragma unroll
            for (int nt = 0; nt < 8; nt++) {
                int cb = wn * 64 + nt * 8 + lq;
                bf[nt][0] = *(const uint32_t*)&Bs2[cb][kb];
                bf[nt][1] = *(const uint32_t*)&Bs2[cb][kb + 4];
            }
#pragma unroll
            for (int mt = 0; mt < 2; mt++) {
                int rb2 = wm * 32 + mt * 16 + lq;
                uint32_t a[4];
                a[0] = *(const uint32_t*)&As2[rb2][kb];
                a[1] = *(const uint32_t*)&As2[rb2 + 8][kb];
                a[2] = *(const uint32_t*)&As2[rb2][kb + 4];
                a[3] = *(const uint32_t*)&As2[rb2 + 8][kb + 4];
#pragma unroll
                for (int nt = 0; nt < 8; nt++)
                    mma16816(acc[mt][nt], a, bf[nt][0], bf[nt][1]);
            }
        }
    };

    // ---- phase 1: pe = pos_w2 @ hrelu -> sPE (fp16, +pb2) ----
    {
        float acc2[2][8][4];
#pragma unroll
        for (int mt = 0; mt < 2; mt++)
#pragma unroll
            for (int nt = 0; nt < 8; nt++)
#pragma unroll
                for (int q = 0; q < 4; q++) acc2[mt][nt][q] = 0.f;
        Ap = hrelu; Wp = pw2h; Kd = PHD;
        fetch(0);
#pragma unroll 1
        for (int c = 0; c < PHD / 32; c++) {
            store();
            __syncthreads();
            if (c + 1 < PHD / 32) fetch(c + 1);
            mma_all(acc2);
            __syncthreads();
        }
#pragma unroll
        for (int mt = 0; mt < 2; mt++)
#pragma unroll
            for (int nt = 0; nt < 8; nt++) {
                int cch = o0 + wn * 64 + nt * 8 + lr * 2;
                float2 pbv = *(const float2*)(pb2 + cch);
                sPE[wm*32 + mt*16 + lq][wn*32 + nt*4 + lr] =
                    __floats2half2_rn(acc2[mt][nt][0] + pbv.x, acc2[mt][nt][1] + pbv.y);
                sPE[wm*32 + mt*16 + 8 + lq][wn*32 + nt*4 + lr] =
                    __floats2half2_rn(acc2[mt][nt][2] + pbv.x, acc2[mt][nt][3] + pbv.y);
            }
    }

    // ---- phase 2: logits = attn_w2 @ hid ----
    float acc1[2][8][4];
#pragma unroll
    for (int mt = 0; mt < 2; mt++)
#pragma unroll
        for (int nt = 0; nt < 8; nt++)
#pragma unroll
            for (int q = 0; q < 4; q++) acc1[mt][nt][q] = 0.f;
    Ap = hid; Wp = w2h; Kd = AHD;
    fetch(0);
#pragma unroll 1
    for (int c = 0; c < AHD / 32; c++) {
        store();
        __syncthreads();
        if (c + 1 < AHD / 32) fetch(c + 1);
        mma_all(acc1);
        __syncthreads();
    }

    // ---- softmax over k (16 rows per point, within warp) + gather + agg ----
    const int bb = row0 >> 16;
#pragma unroll
    for (int mt = 0; mt < 2; mt++) {
        const int pt = (row0 + wm * 32 + mt * 16) >> 4;
        const int j0 = sidx[wm * 32 + mt * 16 + lq];
        const int j1 = sidx[wm * 32 + mt * 16 + 8 + lq];
        const float* v0b = valft + ((size_t)bb * MM + j0) * DD;
        const float* v1b = valft + ((size_t)bb * MM + j1) * DD;
#pragma unroll
        for (int nt = 0; nt < 8; nt++) {
            const int c = o0 + wn * 64 + nt * 8 + lr * 2;
            float2 vv0 = *(const float2*)(v0b + c);
            float2 vv1 = *(const float2*)(v1b + c);
            float2 p0 = __half22float2(sPE[wm*32 + mt*16 + lq][wn*32 + nt*4 + lr]);
            float2 p1 = __half22float2(sPE[wm*32 + mt*16 + 8 + lq][wn*32 + nt*4 + lr]);
            float outc[2];
#pragma unroll
            for (int j = 0; j < 2; j++) {
                float l0 = acc1[mt][nt][j];
                float l1 = acc1[mt][nt][2 + j];
                float m = fmaxf(l0, l1);
                m = fmaxf(m, __shfl_xor_sync(0xffffffffu, m, 4));
                m = fmaxf(m, __shfl_xor_sync(0xffffffffu, m, 8));
                m = fmaxf(m, __shfl_xor_sync(0xffffffffu, m, 16));
                float e0 = __expf(l0 - m), e1 = __expf(l1 - m);
                float S = e0 + e1;
                S += __shfl_xor_sync(0xffffffffu, S, 4);
                S += __shfl_xor_sync(0xffffffffu, S, 8);
                S += __shfl_xor_sync(0xffffffffu, S, 16);
                float pe0 = j ? p0.y : p0.x;
                float pe1 = j ? p1.y : p1.x;
                float va0 = j ? vv0.y : vv0.x;
                float va1 = j ? vv1.y : vv1.x;
                float T = e0 * (va0 + pe0) + e1 * (va1 + pe1);
                T += __shfl_xor_sync(0xffffffffu, T, 4);
                T += __shfl_xor_sync(0xffffffffu, T, 8);
                T += __shfl_xor_sync(0xffffffffu, T, 16);
                outc[j] = T / S;
            }
            if (lq == 0)
                *(float2*)(aggv + (size_t)pt * DD + c) = make_float2(outc[0], outc[1]);
        }
    }
}

// ---------------- precompute + weight conversions ----------------------------
__global__ void precomp_kernel(const float* __restrict__ w1,
                               const float* __restrict__ pw2,
                               const float* __restrict__ pb2,
                               const float* __restrict__ ag, const float* __restrict__ abeta,
                               const float* __restrict__ amu, const float* __restrict__ avar,
                               const float* __restrict__ ab1,
                               const float* __restrict__ pg, const float* __restrict__ pbeta,
                               const float* __restrict__ pmu, const float* __restrict__ pvar,
                               const float* __restrict__ pb1,
                               float* __restrict__ pre1, __half* __restrict__ pre1h,
                               float* __restrict__ aA,
                               float* __restrict__ cA, float* __restrict__ aP,
                               float* __restrict__ cP)
{
    int o = blockIdx.x;
    if (o < AHD) {
        int p = threadIdx.x;
        float s = 0.f;
        for (int c = 0; c < DD; c++) s += w1[o*DD + c] * pw2[c*PHD + p];
        pre1[o*PHD + p] = s;
        pre1h[o*PHD + p] = __float2half_rn(s);
        if (p == 0) {
            float vb = 0.f;
            for (int c = 0; c < DD; c++) vb += w1[o*DD + c] * pb2[c];
            float inv = ag[o] / sqrtf(avar[o] + 1e-5f);
            aA[o] = inv;
            cA[o] = (ab1[o] - amu[o]) * inv + abeta[o] + vb * inv;
        }
    } else {
        int p = threadIdx.x;
        float inv = pg[p] / sqrtf(pvar[p] + 1e-5f);
        aP[p] = inv;
        cP[p] = (pb1[p] - pmu[p]) * inv + pbeta[p];
    }
}

__global__ void cvt_h_kernel(const float* __restrict__ s, __half* __restrict__ d, int n)
{
    int i = blockIdx.x * 256 + threadIdx.x;
    if (i < n) d[i] = __float2half_rn(s[i]);
}

// ---------------- SIMT fp32 GEMM (small front/end GEMMs) ---------------------
constexpr int TBO = 128, TBX = 128, TBK = 16;

template<bool A_RM, bool OUT_XO>
__global__ __launch_bounds__(256)
void gemm_k(const float* __restrict__ W, const float* __restrict__ bias,
            const float* __restrict__ A, const float* __restrict__ resid,
            float* __restrict__ C, int O, int K, int X, size_t sA, size_t sC)
{
    __shared__ float As[TBK][TBX];
    __shared__ float Ws[TBK][TBO];
    const int bx = blockIdx.x * TBX;
    const int bo = blockIdx.y * TBO;
    const int b  = blockIdx.z;
    const float* Ab = A + (size_t)b * sA;
    float* Cb = C + (size_t)b * sC;
    const int tid = threadIdx.x;
    const int tco = (tid & 15) * 4;
    const int tcx = (tid >> 4) * 4;

    float acc[8][8];
#pragma unroll
    for (int i = 0; i < 8; i++)
#pragma unroll
        for (int j = 0; j < 8; j++) acc[i][j] = 0.f;

    for (int k0 = 0; k0 < K; k0 += TBK) {
        if (A_RM) {
            int row = tid >> 1, c0 = (tid & 1) * 8;
            const float* p = Ab + (size_t)(bx + row) * K + k0 + c0;
            float4 v0 = *(const float4*)p;
            float4 v1 = *(const float4*)(p + 4);
            As[c0+0][row] = v0.x; As[c0+1][row] = v0.y;
            As[c0+2][row] = v0.z; As[c0+3][row] = v0.w;
            As[c0+4][row] = v1.x; As[c0+5][row] = v1.y;
            As[c0+6][row] = v1.z; As[c0+7][row] = v1.w;
        } else {
            int kk = tid >> 4, x8 = (tid & 15) * 8;
            const float* p = Ab + (size_t)(k0 + kk) * X + bx + x8;
            float4 v0 = *(const float4*)p;
            float4 v1 = *(const float4*)(p + 4);
            *(float4*)&As[kk][x8]     = v0;
            *(float4*)&As[kk][x8 + 4] = v1;
        }
        {
            int row = tid >> 1, c0 = (tid & 1) * 8;
            const float* p = W + (size_t)(bo + row) * K + k0 + c0;
            float4 v0 = *(const float4*)p;
            float4 v1 = *(const float4*)(p + 4);
            Ws[c0+0][row] = v0.x; Ws[c0+1][row] = v0.y;
            Ws[c0+2][row] = v0.z; Ws[c0+3][row] = v0.w;
            Ws[c0+4][row] = v1.x; Ws[c0+5][row] = v1.y;
            Ws[c0+6][row] = v1.z; Ws[c0+7][row] = v1.w;
        }
        __syncthreads();
#pragma unroll
        for (int kk = 0; kk < TBK; kk++) {
            float4 a0 = *(const float4*)&As[kk][tcx];
            float4 a1 = *(const float4*)&As[kk][tcx + 64];
            float4 w0 = *(const float4*)&Ws[kk][tco];
            float4 w1 = *(const float4*)&Ws[kk][tco + 64];
            float a[8] = {a0.x, a0.y, a0.z, a0.w, a1.x, a1.y, a1.z, a1.w};
            float w[8] = {w0.x, w0.y, w0.z, w0.w, w1.x, w1.y, w1.z, w1.w};
#pragma unroll
            for (int i = 0; i < 8; i++)
#pragma unroll
                for (int j = 0; j < 8; j++)
                    acc[i][j] = fmaf(a[i], w[j], acc[i][j]);
        }
        __syncthreads();
    }
#pragma unroll
    for (int i = 0; i < 8; i++) {
        int xx = bx + (i < 4 ? tcx + i : 64 + tcx + (i - 4));
#pragma unroll
        for (int jh = 0; jh < 2; jh++) {
            int oo = bo + tco + jh * 64;
            float vr[4];
#pragma unroll
            for (int j = 0; j < 4; j++) vr[j] = acc[i][jh * 4 + j];
            if (bias) {
#pragma unroll
                for (int j = 0; j < 4; j++) vr[j] += bias[oo + j];
            }
            if (OUT_XO) {
                size_t ix = (size_t)xx * O + oo;
                if (resid) {
                    float4 rv = *(const float4*)(resid + (size_t)b * sC + ix);
                    vr[0] += rv.x; vr[1] += rv.y; vr[2] += rv.z; vr[3] += rv.w;
                }
                float4 ov = {vr[0], vr[1], vr[2], vr[3]};
                *(float4*)(Cb + ix) = ov;
            } else {
#pragma unroll
                for (int j = 0; j < 4; j++) {
                    size_t ix = (size_t)(oo + j) * X + xx;
                    float v = vr[j];
                    if (resid) v += resid[(size_t)b * sC + ix];
                    Cb[ix] = v;
                }
            }
        }
    }
}

// ---------------- KNN --------------------------------------------------------
__global__ __launch_bounds__(128)
void knn_kernel(const float* __restrict__ pf,
                const float* __restrict__ seed,
                int* __restrict__ idx_out)
{
    __shared__ float sx[MM], sy[MM], sz[MM], ss[MM];
    __shared__ float sd[4][MM];
    int b = blockIdx.y;
    const float* sb = seed + (size_t)b * MM * 3;
    for (int j = threadIdx.x; j < MM; j += 128) {
        float x = sb[j*3], y = sb[j*3+1], z = sb[j*3+2];
        sx[j] = x; sy[j] = y; sz[j] = z; ss[j] = x*x + y*y + z*z;
    }
    __syncthreads();
    int w = threadIdx.x >> 5, lane = threadIdx.x & 31;
    int n = blockIdx.x * 4 + w;
    const float* q = pf + ((size_t)b * NN + n) * 3;
    float qx = q[0], qy = q[1], qz = q[2];
    float qn = qx*qx + qy*qy + qz*qz;
    float* d = sd[w];
    for (int j = lane; j < MM; j += 32)
        d[j] = qn + ss[j] - 2.f * (qx*sx[j] + qy*sy[j] + qz*sz[j]);
    __syncwarp();
    int* out = idx_out + ((size_t)b * NN + n) * KNB;
    for (int t = 0; t < KNB; t++) {
        float best = 1e30f; int bi = 0;
        for (int j = lane; j < MM; j += 32) {
            float v = d[j];
            if (v < best || (v == best && j < bi)) { best = v; bi = j; }
        }
#pragma unroll
        for (int off = 16; off; off >>= 1) {
            float ov = __shfl_xor_sync(0xffffffffu, best, off);
            int   oi = __shfl_xor_sync(0xffffffffu, bi, off);
            if (ov < best || (ov == best && oi < bi)) { best = ov; bi = oi; }
        }
        if (lane == 0) out[t] = bi;
        if (lane == (bi & 31)) d[bi] = 1e30f;
        __syncwarp();
    }
}

// ---------------- geometry -> hrelu (R,64) fp16 ------------------------------
__global__ __launch_bounds__(256)
void geom_kernel(const float* __restrict__ pos,
                 const float* __restrict__ seed,
                 const int*   __restrict__ idxg,
                 const float* __restrict__ pw1,
                 const float* __restrict__ aP, const float* __restrict__ cP,
                 __half* __restrict__ hrelu)
{
    int r = blockIdx.x * 256 + threadIdx.x;
    int b = r >> 16;
    int n = (r >> 4) & (NN - 1);
    int j = idxg[r];
    float px = pos[((size_t)b * 3 + 0) * NN + n];
    float py = pos[((size_t)b * 3 + 1) * NN + n];
    float pz = pos[((size_t)b * 3 + 2) * NN + n];
    const float* sj = seed + ((size_t)b * MM + j) * 3;
    float rx = px - sj[0], ry = py - sj[1], rz = pz - sj[2];
    float ds = sqrtf(rx*rx + ry*ry + rz*rz);
    __half2* out = (__half2*)(hrelu + (size_t)r * PHD);
#pragma unroll
    for (int p0 = 0; p0 < PHD; p0 += 2) {
        float t[2];
#pragma unroll
        for (int u = 0; u < 2; u++) {
            int p = p0 + u;
            float raw = __ldg(&pw1[p*4]) * ds + __ldg(&pw1[p*4+1]) * rx
                      + __ldg(&pw1[p*4+2]) * ry + __ldg(&pw1[p*4+3]) * rz;
            t[u] = fmaxf(raw * __ldg(&aP[p]) + __ldg(&cP[p]), 0.f);
        }
        out[p0 >> 1] = __floats2half2_rn(t[0], t[1]);
    }
}

// ---------------- launch -----------------------------------------------------
extern "C" void kernel_launch(void* const* d_in, const int* in_sizes, int n_in,
                              void* d_out, int out_size)
{
    const float* pos      = (const float*)d_in[0];
    const float* pf       = (const float*)d_in[1];
    const float* fea      = (const float*)d_in[2];
    const float* seed     = (const float*)d_in[3];
    const float* seed_fea = (const float*)d_in[4];
    const float* w_start  = (const float*)d_in[5];
    const float* b_start  = (const float*)d_in[6];
    const float* w_key    = (const float*)d_in[7];
    const float* b_key    = (const float*)d_in[8];
    const float* w_value  = (const float*)d_in[9];
    const float* b_value  = (const float*)d_in[10];
    const float* w_query  = (const float*)d_in[11];
    const float* b_query  = (const float*)d_in[12];
    const float* pos_w1   = (const float*)d_in[13];
    const float* pos_b1   = (const float*)d_in[14];
    const float* pos_g1   = (const float*)d_in[15];
    const float* pos_beta1= (const float*)d_in[16];
    const float* pos_mu1  = (const float*)d_in[17];
    const float* pos_var1 = (const float*)d_in[18];
    const float* pos_w2   = (const float*)d_in[19];
    const float* pos_b2   = (const float*)d_in[20];
    const float* attn_w1  = (const float*)d_in[21];
    const float* attn_b1  = (const float*)d_in[22];
    const float* attn_g1  = (const float*)d_in[23];
    const float* attn_beta1=(const float*)d_in[24];
    const float* attn_mu1 = (const float*)d_in[25];
    const float* attn_var1= (const float*)d_in[26];
    const float* attn_w2  = (const float*)d_in[27];
    // d_in[28] = attn_b2: cancels in softmax over K
    const float* w_end    = (const float*)d_in[29];
    const float* b_end    = (const float*)d_in[30];

    float *valueT, *keyfT, *valftT, *queryT, *aggv, *pre1;
    float *aA, *cA, *aP, *cP;
    __half *W1qt, *W1kt, *hrelu, *hid, *pre1h, *w1h, *w2h, *pw2h, *wkh, *wvh;
    int* idx;
    cudaGetSymbolAddress((void**)&valueT, g_valueT);
    cudaGetSymbolAddress((void**)&keyfT,  g_keyfT);
    cudaGetSymbolAddress((void**)&valftT, g_valftT);
    cudaGetSymbolAddress((void**)&queryT, g_queryT);
    cudaGetSymbolAddress((void**)&W1qt,   g_W1qt);
    cudaGetSymbolAddress((void**)&W1kt,   g_W1kt);
    cudaGetSymbolAddress((void**)&idx,    g_idx);
    cudaGetSymbolAddress((void**)&hrelu,  g_hrelu);
    cudaGetSymbolAddress((void**)&hid,    g_hid);
    cudaGetSymbolAddress((void**)&aggv,   g_agg);
    cudaGetSymbolAddress((void**)&pre1,   g_pre1);
    cudaGetSymbolAddress((void**)&pre1h,  g_pre1h);
    cudaGetSymbolAddress((void**)&w1h,    g_w1h);
    cudaGetSymbolAddress((void**)&w2h,    g_w2h);
    cudaGetSymbolAddress((void**)&pw2h,   g_pw2h);
    cudaGetSymbolAddress((void**)&wkh,    g_wkh);
    cudaGetSymbolAddress((void**)&wvh,    g_wvh);
    cudaGetSymbolAddress((void**)&aA,     g_aA);
    cudaGetSymbolAddress((void**)&cA,     g_cA);
    cudaGetSymbolAddress((void**)&aP,     g_aP);
    cudaGetSymbolAddress((void**)&cP,     g_cP);

    cudaFuncSetAttribute(fused_attn, cudaFuncAttributeMaxDynamicSharedMemorySize, 55296);

    precomp_kernel<<<AHD + 1, PHD>>>(attn_w1, pos_w2, pos_b2,
                                     attn_g1, attn_beta1, attn_mu1, attn_var1, attn_b1,
                                     pos_g1, pos_beta1, pos_mu1, pos_var1, pos_b1,
                                     pre1, pre1h, aA, cA, aP, cP);
    cvt_h_kernel<<<(AHD*DD + 255)/256, 256>>>(attn_w1, w1h, AHD*DD);
    cvt_h_kernel<<<(DD*AHD + 255)/256, 256>>>(attn_w2, w2h, DD*AHD);
    cvt_h_kernel<<<(DD*PHD + 255)/256, 256>>>(pos_w2, pw2h, DD*PHD);
    cvt_h_kernel<<<(DD*DD + 255)/256, 256>>>(w_key, wkh, DD*DD);
    cvt_h_kernel<<<(DD*DD + 255)/256, 256>>>(w_value, wvh, DD*DD);

    // value = w_start @ seed_fea  (SIMT, channel-major A), row-major out
    gemm_k<false,true><<<dim3(MM/128, DD/128, BB), 256>>>(
        w_start, b_start, seed_fea, nullptr, valueT, DD, CC, MM,
        (size_t)CC*MM, (size_t)MM*DD);
    // key/val via fp16 mma (A = valueT fp32 row-major)
    hgemm<256,256,0,false,false><<<dim3(2, BB*MM/128), 256>>>(
        wkh, b_key, valueT, keyfT, nullptr, nullptr, nullptr, nullptr, nullptr);
    hgemm<256,256,0,false,false><<<dim3(2, BB*MM/128), 256>>>(
        wvh, b_value, valueT, valftT, nullptr, nullptr, nullptr, nullptr, nullptr);
    // query (SIMT, channel-major A)
    gemm_k<false,true><<<dim3(NN/128, DD/128, BB), 256>>>(
        w_query, b_query, fea, nullptr, queryT, DD, CC, NN,
        (size_t)CC*NN, (size_t)NN*DD);

    // W1q / W1k via fp16 mma -> fp16 outputs
    hgemm<512,256,0,false,true><<<dim3(4, BB*NN/128), 256>>>(
        w1h, nullptr, queryT, W1qt, nullptr, nullptr, nullptr, nullptr, nullptr);
    hgemm<512,256,0,false,true><<<dim3(4, BB*MM/128), 256>>>(
        w1h, nullptr, keyfT, W1kt, nullptr, nullptr, nullptr, nullptr, nullptr);

    // knn + geometry
    knn_kernel<<<dim3(NN/4, BB), 128>>>(pf, seed, idx);
    geom_kernel<<<RR/256, 256>>>(pos, seed, idx, pos_w1, aP, cP, hrelu);

    // hid = relu(aA*(pre1@hrelu + W1q - W1k) + cA)  -> fp16
    hgemm<512,64,1,true,true><<<dim3(4, RR/128), 256>>>(
        pre1h, nullptr, hrelu, hid, W1qt, W1kt, idx, aA, cA);

    // fused: pe + logits + softmax + gather + aggregate -> aggv
    fused_attn<<<dim3(2, RR/128), 256, 55296>>>(
        w2h, hid, pw2h, hrelu, pos_b2, valftT, idx, aggv);

    // out = w_end @ aggv + b_end + fea
    gemm_k<true,false><<<dim3(NN/128, CC/128, BB), 256>>>(
        w_end, b_end, aggv, fea, (float*)d_out, CC, DD, NN,
        (size_t)NN*DD, (size_t)CC*NN);
}

// round 11
// speedup vs baseline: 1.3251x; 1.0250x over previous
#include <cuda_runtime.h>
#include <cuda_fp16.h>
#include <cstdint>
#include <cstddef>

#define BB 4
#define NN 4096
#define MM 1024
#define CC 128
#define DD 256
#define PHD 64
#define AHD 512
#define KNB 16
#define RR (BB*NN*KNB)   // 262144 rows (b,n,k)

// ---------------- static scratch --------------------------------------------
__device__ float  g_valueT[BB*MM*DD];     // (B*M, D)
__device__ float  g_keyfT [BB*MM*DD];
__device__ float  g_valftT[BB*MM*DD];
__device__ float  g_queryT[BB*NN*DD];     // (B*N, D)
__device__ __half g_W1qt  [BB*NN*AHD];    // (B*N, AH) fp16
__device__ __half g_W1kt  [BB*MM*AHD];    // (B*M, AH) fp16
__device__ int    g_idx   [RR];
__device__ __half g_hrelu [16777216];     // (R, 64) fp16
__device__ __half g_hid   [134217728];    // (R, 512) fp16
__device__ float  g_agg   [BB*NN*DD];     // (B*N, 256) aggv
__device__ float  g_pre1  [AHD*PHD];
__device__ __half g_pre1h [AHD*PHD];
__device__ __half g_w1h   [AHD*DD];       // attn_w1 fp16
__device__ __half g_w2h   [DD*AHD];       // attn_w2 fp16
__device__ __half g_pw2h  [DD*PHD];       // pos_w2 fp16
__device__ __half g_wkh   [DD*DD];        // w_key fp16
__device__ __half g_wvh   [DD*DD];        // w_value fp16
__device__ float  g_aA[AHD], g_cA[AHD], g_aP[PHD], g_cP[PHD];

// ---------------- helpers ----------------------------------------------------
__device__ __forceinline__ void mma16816(float* d, const uint32_t* a,
                                         uint32_t b0, uint32_t b1) {
    asm volatile(
        "mma.sync.aligned.m16n8k16.row.col.f32.f16.f16.f32 "
        "{%0,%1,%2,%3},{%4,%5,%6,%7},{%8,%9},{%0,%1,%2,%3};"
        : "+f"(d[0]), "+f"(d[1]), "+f"(d[2]), "+f"(d[3])
        : "r"(a[0]), "r"(a[1]), "r"(a[2]), "r"(a[3]), "r"(b0), "r"(b1));
}
__device__ __forceinline__ uint32_t packh2(float x, float y) {
    __half2 h = __floats2half2_rn(x, y);
    return *(uint32_t*)&h;
}

// ---------------- fp16 mma GEMM (round-7 proven): C = A(rows,K)@W(O,K)^T -----
// BM=128, BN=128, BK=32. 256 threads = 8 warps (4M x 2N), warp tile 32x64.
// Smem: half2 words, [128][20] (16 data + 4 pad) -> conflict-free scalar LDS.
// EPI 0: C = acc (+bias fp32).   EPI 1: C = relu((acc+W1q-W1k)*aA+cA), W1 fp16
template<int O, int K, int EPI, bool AF16, bool OUTH>
__global__ __launch_bounds__(256)
void hgemm(const __half* __restrict__ Wh, const float* __restrict__ bias,
           const void* __restrict__ Ag, void* __restrict__ Cg,
           const __half* __restrict__ W1q, const __half* __restrict__ W1k,
           const int* __restrict__ idxg,
           const float* __restrict__ aA, const float* __restrict__ cA)
{
    constexpr int CCH = K / 32;
    __shared__ __align__(16) __half2 As2[128][20];
    __shared__ __align__(16) __half2 Bs2[128][20];
    const int row0 = blockIdx.y * 128;
    const int o0   = blockIdx.x * 128;
    const int tid  = threadIdx.x;
    const int lane = tid & 31;
    const int wid  = tid >> 5;
    const int wm = wid & 3;
    const int wn = wid >> 2;
    const int lq = lane >> 2;
    const int lr = lane & 3;

    float acc[2][8][4];
#pragma unroll
    for (int mt = 0; mt < 2; mt++)
#pragma unroll
        for (int nt = 0; nt < 8; nt++)
#pragma unroll
            for (int q = 0; q < 4; q++) acc[mt][nt][q] = 0.f;

    uint4  ra[2], rbv[2];
    float4 fa[2][2];

    auto fetch = [&](int c) {
        if (AF16) {
            const __half* s = (const __half*)Ag +
                (size_t)(row0 + (tid >> 1)) * K + c * 32 + (tid & 1) * 16;
            ra[0] = *(const uint4*)s;
            ra[1] = *(const uint4*)(s + 8);
        } else {
#pragma unroll
            for (int i = 0; i < 2; i++) {
                int lin = tid + i * 256;
                int r = lin >> 2, cq = (lin & 3) * 4;
                const float* s = (const float*)Ag +
                    (size_t)(row0 + r) * K + c * 32 + cq * 2;
                fa[i][0] = *(const float4*)s;
                fa[i][1] = *(const float4*)(s + 4);
            }
        }
        const __half* w = Wh + (size_t)(o0 + (tid >> 1)) * K + c * 32 + (tid & 1) * 16;
        rbv[0] = *(const uint4*)w;
        rbv[1] = *(const uint4*)(w + 8);
    };
    auto store = [&]() {
        int r = tid >> 1, c0 = (tid & 1) * 8;
        if (AF16) {
            *(uint4*)&As2[r][c0]     = ra[0];
            *(uint4*)&As2[r][c0 + 4] = ra[1];
        } else {
#pragma unroll
            for (int i = 0; i < 2; i++) {
                int lin = tid + i * 256;
                int rr = lin >> 2, cq = (lin & 3) * 4;
                uint4 u;
                u.x = packh2(fa[i][0].x, fa[i][0].y);
                u.y = packh2(fa[i][0].z, fa[i][0].w);
                u.z = packh2(fa[i][1].x, fa[i][1].y);
                u.w = packh2(fa[i][1].z, fa[i][1].w);
                *(uint4*)&As2[rr][cq] = u;
            }
        }
        *(uint4*)&Bs2[r][c0]     = rbv[0];
        *(uint4*)&Bs2[r][c0 + 4] = rbv[1];
    };

    fetch(0);
#pragma unroll 1
    for (int c = 0; c < CCH; c++) {
        store();
        __syncthreads();
        if (c + 1 < CCH) fetch(c + 1);
#pragma unroll
        for (int ks = 0; ks < 2; ks++) {
            const int kb = ks * 8 + lr;
            uint32_t bf[8][2];
#pragma unroll
            for (int nt = 0; nt < 8; nt++) {
                int cb = wn * 64 + nt * 8 + lq;
                bf[nt][0] = *(const uint32_t*)&Bs2[cb][kb];
                bf[nt][1] = *(const uint32_t*)&Bs2[cb][kb + 4];
            }
#pragma unroll
            for (int mt = 0; mt < 2; mt++) {
                int rb = wm * 32 + mt * 16 + lq;
                uint32_t a[4];
                a[0] = *(const uint32_t*)&As2[rb][kb];
                a[1] = *(const uint32_t*)&As2[rb + 8][kb];
                a[2] = *(const uint32_t*)&As2[rb][kb + 4];
                a[3] = *(const uint32_t*)&As2[rb + 8][kb + 4];
#pragma unroll
                for (int nt = 0; nt < 8; nt++)
                    mma16816(acc[mt][nt], a, bf[nt][0], bf[nt][1]);
            }
        }
        __syncthreads();
    }

    // ---- epilogue ----
#pragma unroll
    for (int mt = 0; mt < 2; mt++) {
#pragma unroll
        for (int h = 0; h < 2; h++) {
            int r = row0 + wm * 32 + mt * 16 + h * 8 + lq;
            const __half* qp = nullptr;
            const __half* kp = nullptr;
            if (EPI == 1) {
                int bbx = r >> 16;
                int jj = idxg[r];
                qp = W1q + (size_t)(r >> 4) * AHD;
                kp = W1k + ((size_t)bbx * MM + jj) * AHD;
            }
#pragma unroll
            for (int nt = 0; nt < 8; nt++) {
                int o = o0 + wn * 64 + nt * 8 + lr * 2;
                float v0 = acc[mt][nt][h * 2 + 0];
                float v1 = acc[mt][nt][h * 2 + 1];
                if (EPI == 0) {
                    if (bias) { v0 += bias[o]; v1 += bias[o + 1]; }
                } else {
                    float2 qv = __half22float2(*(const __half2*)(qp + o));
                    float2 kv = __half22float2(*(const __half2*)(kp + o));
                    float2 av = *(const float2*)(aA + o);
                    float2 cv = *(const float2*)(cA + o);
                    v0 = fmaxf((v0 + qv.x - kv.x) * av.x + cv.x, 0.f);
                    v1 = fmaxf((v1 + qv.y - kv.y) * av.y + cv.y, 0.f);
                }
                if (OUTH) {
                    __half2 hv = __floats2half2_rn(v0, v1);
                    *(__half2*)((__half*)Cg + (size_t)r * O + o) = hv;
                } else {
                    *(float2*)((float*)Cg + (size_t)r * O + o) = make_float2(v0, v1);
                }
            }
        }
    }
}

// ---------------- fused: pe GEMM -> smem, logits GEMM, softmax+gather+agg ----
// grid (2, RR/128), 256 thr, <=128 regs (2 CTAs/SM).
// Double-buffered smem, ONE sync per K-chunk. Dynamic smem 75776 B.
__global__ __launch_bounds__(256, 2)
void fused_attn(const __half* __restrict__ w2h,    // (256,512)
                const __half* __restrict__ hid,    // (R,512)
                const __half* __restrict__ pw2h,   // (256,64)
                const __half* __restrict__ hrelu,  // (R,64)
                const float* __restrict__ pb2,     // (256)
                const float* __restrict__ valft,   // (B*M,256)
                const int*   __restrict__ idxg,
                float* __restrict__ aggv)          // (B*N,256)
{
    extern __shared__ char dsm[];
    __half2 (*As2)[128][20] = (__half2(*)[128][20])(dsm);           // 2*10240 B
    __half2 (*Bs2)[128][20] = (__half2(*)[128][20])(dsm + 20480);   // 2*10240 B
    __half2 (*sPE)[68]      = (__half2(*)[68])(dsm + 40960);        // 34816 B
    __shared__ int sidx[128];
    const int row0 = blockIdx.y * 128;
    const int o0   = blockIdx.x * 128;
    const int tid  = threadIdx.x;
    const int lane = tid & 31;
    const int wid  = tid >> 5;
    const int wm = wid & 3;
    const int wn = wid >> 2;
    const int lq = lane >> 2;
    const int lr = lane & 3;

    if (tid < 128) sidx[tid] = idxg[row0 + tid];

    uint4 ra[2], rb[2];
    const __half* Ap;
    const __half* Wp;
    int Kd;
    auto fetch = [&](int c) {
        const __half* s = Ap + (size_t)(row0 + (tid >> 1)) * Kd + c * 32 + (tid & 1) * 16;
        ra[0] = *(const uint4*)s;
        ra[1] = *(const uint4*)(s + 8);
        const __half* w = Wp + (size_t)(o0 + (tid >> 1)) * Kd + c * 32 + (tid & 1) * 16;
        rb[0] = *(const uint4*)w;
        rb[1] = *(const uint4*)(w + 8);
    };
    auto store = [&](int bufi) {
        int r = tid >> 1, c0 = (tid & 1) * 8;
        *(uint4*)&As2[bufi][r][c0]     = ra[0];
        *(uint4*)&As2[bufi][r][c0 + 4] = ra[1];
        *(uint4*)&Bs2[bufi][r][c0]     = rb[0];
        *(uint4*)&Bs2[bufi][r][c0 + 4] = rb[1];
    };
    auto mma_all = [&](int p, float (&acc)[2][8][4]) {
#pragma unroll
        for (int ks = 0; ks < 2; ks++) {
            const int kb = ks * 8 + lr;
            uint32_t bf[8][2];
#pragma unroll
            for (int nt = 0; nt < 8; nt++) {
                int cb = wn * 64 + nt * 8 + lq;
                bf[nt][0] = *(const uint32_t*)&Bs2[p][cb][kb];
                bf[nt][1] = *(const uint32_t*)&Bs2[p][cb][kb + 4];
            }
#pragma unroll
            for (int mt = 0; mt < 2; mt++) {
                int rb2 = wm * 32 + mt * 16 + lq;
                uint32_t a[4];
                a[0] = *(const uint32_t*)&As2[p][rb2][kb];
                a[1] = *(const uint32_t*)&As2[p][rb2 + 8][kb];
                a[2] = *(const uint32_t*)&As2[p][rb2][kb + 4];
                a[3] = *(const uint32_t*)&As2[p][rb2 + 8][kb + 4];
#pragma unroll
                for (int nt = 0; nt < 8; nt++)
                    mma16816(acc[mt][nt], a, bf[nt][0], bf[nt][1]);
            }
        }
    };

    // ---- phase 1: pe = pos_w2 @ hrelu -> sPE (fp16, +pb2) ----
    {
        float acc2[2][8][4];
#pragma unroll
        for (int mt = 0; mt < 2; mt++)
#pragma unroll
            for (int nt = 0; nt < 8; nt++)
#pragma unroll
                for (int q = 0; q < 4; q++) acc2[mt][nt][q] = 0.f;
        Ap = hrelu; Wp = pw2h; Kd = PHD;
        fetch(0);
        store(0);
        __syncthreads();
#pragma unroll 1
        for (int c = 0; c < PHD / 32; c++) {
            if (c + 1 < PHD / 32) fetch(c + 1);
            mma_all(c & 1, acc2);
            if (c + 1 < PHD / 32) store((c + 1) & 1);
            __syncthreads();
        }
#pragma unroll
        for (int mt = 0; mt < 2; mt++)
#pragma unroll
            for (int nt = 0; nt < 8; nt++) {
                int cch = o0 + wn * 64 + nt * 8 + lr * 2;
                float2 pbv = *(const float2*)(pb2 + cch);
                sPE[wm*32 + mt*16 + lq][wn*32 + nt*4 + lr] =
                    __floats2half2_rn(acc2[mt][nt][0] + pbv.x, acc2[mt][nt][1] + pbv.y);
                sPE[wm*32 + mt*16 + 8 + lq][wn*32 + nt*4 + lr] =
                    __floats2half2_rn(acc2[mt][nt][2] + pbv.x, acc2[mt][nt][3] + pbv.y);
            }
    }

    // ---- phase 2: logits = attn_w2 @ hid ----
    float acc1[2][8][4];
#pragma unroll
    for (int mt = 0; mt < 2; mt++)
#pragma unroll
        for (int nt = 0; nt < 8; nt++)
#pragma unroll
            for (int q = 0; q < 4; q++) acc1[mt][nt][q] = 0.f;
    Ap = hid; Wp = w2h; Kd = AHD;
    fetch(0);
    store(0);
    __syncthreads();
#pragma unroll 1
    for (int c = 0; c < AHD / 32; c++) {
        if (c + 1 < AHD / 32) fetch(c + 1);
        mma_all(c & 1, acc1);
        if (c + 1 < AHD / 32) store((c + 1) & 1);
        __syncthreads();
    }

    // ---- softmax over k (16 rows per point, within warp) + gather + agg ----
    const int bb = row0 >> 16;
#pragma unroll
    for (int mt = 0; mt < 2; mt++) {
        const int pt = (row0 + wm * 32 + mt * 16) >> 4;
        const int j0 = sidx[wm * 32 + mt * 16 + lq];
        const int j1 = sidx[wm * 32 + mt * 16 + 8 + lq];
        const float* v0b = valft + ((size_t)bb * MM + j0) * DD;
        const float* v1b = valft + ((size_t)bb * MM + j1) * DD;
#pragma unroll
        for (int nt = 0; nt < 8; nt++) {
            const int c = o0 + wn * 64 + nt * 8 + lr * 2;
            float2 vv0 = *(const float2*)(v0b + c);
            float2 vv1 = *(const float2*)(v1b + c);
            float2 p0 = __half22float2(sPE[wm*32 + mt*16 + lq][wn*32 + nt*4 + lr]);
            float2 p1 = __half22float2(sPE[wm*32 + mt*16 + 8 + lq][wn*32 + nt*4 + lr]);
            float outc[2];
#pragma unroll
            for (int j = 0; j < 2; j++) {
                float l0 = acc1[mt][nt][j];
                float l1 = acc1[mt][nt][2 + j];
                float m = fmaxf(l0, l1);
                m = fmaxf(m, __shfl_xor_sync(0xffffffffu, m, 4));
                m = fmaxf(m, __shfl_xor_sync(0xffffffffu, m, 8));
                m = fmaxf(m, __shfl_xor_sync(0xffffffffu, m, 16));
                float e0 = __expf(l0 - m), e1 = __expf(l1 - m);
                float S = e0 + e1;
                S += __shfl_xor_sync(0xffffffffu, S, 4);
                S += __shfl_xor_sync(0xffffffffu, S, 8);
                S += __shfl_xor_sync(0xffffffffu, S, 16);
                float pe0 = j ? p0.y : p0.x;
                float pe1 = j ? p1.y : p1.x;
                float va0 = j ? vv0.y : vv0.x;
                float va1 = j ? vv1.y : vv1.x;
                float T = e0 * (va0 + pe0) + e1 * (va1 + pe1);
                T += __shfl_xor_sync(0xffffffffu, T, 4);
                T += __shfl_xor_sync(0xffffffffu, T, 8);
                T += __shfl_xor_sync(0xffffffffu, T, 16);
                outc[j] = T / S;
            }
            if (lq == 0)
                *(float2*)(aggv + (size_t)pt * DD + c) = make_float2(outc[0], outc[1]);
        }
    }
}

// ---------------- precompute + weight conversions ----------------------------
__global__ void precomp_kernel(const float* __restrict__ w1,
                               const float* __restrict__ pw2,
                               const float* __restrict__ pb2,
                               const float* __restrict__ ag, const float* __restrict__ abeta,
                               const float* __restrict__ amu, const float* __restrict__ avar,
                               const float* __restrict__ ab1,
                               const float* __restrict__ pg, const float* __restrict__ pbeta,
                               const float* __restrict__ pmu, const float* __restrict__ pvar,
                               const float* __restrict__ pb1,
                               float* __restrict__ pre1, __half* __restrict__ pre1h,
                               float* __restrict__ aA,
                               float* __restrict__ cA, float* __restrict__ aP,
                               float* __restrict__ cP)
{
    int o = blockIdx.x;
    if (o < AHD) {
        int p = threadIdx.x;
        float s = 0.f;
        for (int c = 0; c < DD; c++) s += w1[o*DD + c] * pw2[c*PHD + p];
        pre1[o*PHD + p] = s;
        pre1h[o*PHD + p] = __float2half_rn(s);
        if (p == 0) {
            float vb = 0.f;
            for (int c = 0; c < DD; c++) vb += w1[o*DD + c] * pb2[c];
            float inv = ag[o] / sqrtf(avar[o] + 1e-5f);
            aA[o] = inv;
            cA[o] = (ab1[o] - amu[o]) * inv + abeta[o] + vb * inv;
        }
    } else {
        int p = threadIdx.x;
        float inv = pg[p] / sqrtf(pvar[p] + 1e-5f);
        aP[p] = inv;
        cP[p] = (pb1[p] - pmu[p]) * inv + pbeta[p];
    }
}

// one launch converts all five weight matrices to fp16
#define CV1 (AHD*DD)
#define CV2 (CV1 + DD*AHD)
#define CV3 (CV2 + DD*PHD)
#define CV4 (CV3 + DD*DD)
#define CV5 (CV4 + DD*DD)
__global__ void cvt_all_kernel(const float* __restrict__ w1, const float* __restrict__ w2,
                               const float* __restrict__ pw2, const float* __restrict__ wk,
                               const float* __restrict__ wv,
                               __half* __restrict__ w1h, __half* __restrict__ w2h,
                               __half* __restrict__ pw2h, __half* __restrict__ wkh,
                               __half* __restrict__ wvh)
{
    int i = blockIdx.x * 256 + threadIdx.x;
    if (i < CV1)      w1h [i]       = __float2half_rn(w1 [i]);
    else if (i < CV2) w2h [i - CV1] = __float2half_rn(w2 [i - CV1]);
    else if (i < CV3) pw2h[i - CV2] = __float2half_rn(pw2[i - CV2]);
    else if (i < CV4) wkh [i - CV3] = __float2half_rn(wk [i - CV3]);
    else if (i < CV5) wvh [i - CV4] = __float2half_rn(wv [i - CV4]);
}

// ---------------- SIMT fp32 GEMM (small front/end GEMMs) ---------------------
constexpr int TBO = 128, TBX = 128, TBK = 16;

template<bool A_RM, bool OUT_XO>
__global__ __launch_bounds__(256)
void gemm_k(const float* __restrict__ W, const float* __restrict__ bias,
            const float* __restrict__ A, const float* __restrict__ resid,
            float* __restrict__ C, int O, int K, int X, size_t sA, size_t sC)
{
    __shared__ float As[TBK][TBX];
    __shared__ float Ws[TBK][TBO];
    const int bx = blockIdx.x * TBX;
    const int bo = blockIdx.y * TBO;
    const int b  = blockIdx.z;
    const float* Ab = A + (size_t)b * sA;
    float* Cb = C + (size_t)b * sC;
    const int tid = threadIdx.x;
    const int tco = (tid & 15) * 4;
    const int tcx = (tid >> 4) * 4;

    float acc[8][8];
#pragma unroll
    for (int i = 0; i < 8; i++)
#pragma unroll
        for (int j = 0; j < 8; j++) acc[i][j] = 0.f;

    for (int k0 = 0; k0 < K; k0 += TBK) {
        if (A_RM) {
            int row = tid >> 1, c0 = (tid & 1) * 8;
            const float* p = Ab + (size_t)(bx + row) * K + k0 + c0;
            float4 v0 = *(const float4*)p;
            float4 v1 = *(const float4*)(p + 4);
            As[c0+0][row] = v0.x; As[c0+1][row] = v0.y;
            As[c0+2][row] = v0.z; As[c0+3][row] = v0.w;
            As[c0+4][row] = v1.x; As[c0+5][row] = v1.y;
            As[c0+6][row] = v1.z; As[c0+7][row] = v1.w;
        } else {
            int kk = tid >> 4, x8 = (tid & 15) * 8;
            const float* p = Ab + (size_t)(k0 + kk) * X + bx + x8;
            float4 v0 = *(const float4*)p;
            float4 v1 = *(const float4*)(p + 4);
            *(float4*)&As[kk][x8]     = v0;
            *(float4*)&As[kk][x8 + 4] = v1;
        }
        {
            int row = tid >> 1, c0 = (tid & 1) * 8;
            const float* p = W + (size_t)(bo + row) * K + k0 + c0;
            float4 v0 = *(const float4*)p;
            float4 v1 = *(const float4*)(p + 4);
            Ws[c0+0][row] = v0.x; Ws[c0+1][row] = v0.y;
            Ws[c0+2][row] = v0.z; Ws[c0+3][row] = v0.w;
            Ws[c0+4][row] = v1.x; Ws[c0+5][row] = v1.y;
            Ws[c0+6][row] = v1.z; Ws[c0+7][row] = v1.w;
        }
        __syncthreads();
#pragma unroll
        for (int kk = 0; kk < TBK; kk++) {
            float4 a0 = *(const float4*)&As[kk][tcx];
            float4 a1 = *(const float4*)&As[kk][tcx + 64];
            float4 w0 = *(const float4*)&Ws[kk][tco];
            float4 w1 = *(const float4*)&Ws[kk][tco + 64];
            float a[8] = {a0.x, a0.y, a0.z, a0.w, a1.x, a1.y, a1.z, a1.w};
            float w[8] = {w0.x, w0.y, w0.z, w0.w, w1.x, w1.y, w1.z, w1.w};
#pragma unroll
            for (int i = 0; i < 8; i++)
#pragma unroll
                for (int j = 0; j < 8; j++)
                    acc[i][j] = fmaf(a[i], w[j], acc[i][j]);
        }
        __syncthreads();
    }
#pragma unroll
    for (int i = 0; i < 8; i++) {
        int xx = bx + (i < 4 ? tcx + i : 64 + tcx + (i - 4));
#pragma unroll
        for (int jh = 0; jh < 2; jh++) {
            int oo = bo + tco + jh * 64;
            float vr[4];
#pragma unroll
            for (int j = 0; j < 4; j++) vr[j] = acc[i][jh * 4 + j];
            if (bias) {
#pragma unroll
                for (int j = 0; j < 4; j++) vr[j] += bias[oo + j];
            }
            if (OUT_XO) {
                size_t ix = (size_t)xx * O + oo;
                if (resid) {
                    float4 rv = *(const float4*)(resid + (size_t)b * sC + ix);
                    vr[0] += rv.x; vr[1] += rv.y; vr[2] += rv.z; vr[3] += rv.w;
                }
                float4 ov = {vr[0], vr[1], vr[2], vr[3]};
                *(float4*)(Cb + ix) = ov;
            } else {
#pragma unroll
                for (int j = 0; j < 4; j++) {
                    size_t ix = (size_t)(oo + j) * X + xx;
                    float v = vr[j];
                    if (resid) v += resid[(size_t)b * sC + ix];
                    Cb[ix] = v;
                }
            }
        }
    }
}

// ---------------- KNN --------------------------------------------------------
__global__ __launch_bounds__(128)
void knn_kernel(const float* __restrict__ pf,
                const float* __restrict__ seed,
                int* __restrict__ idx_out)
{
    __shared__ float sx[MM], sy[MM], sz[MM], ss[MM];
    __shared__ float sd[4][MM];
    int b = blockIdx.y;
    const float* sb = seed + (size_t)b * MM * 3;
    for (int j = threadIdx.x; j < MM; j += 128) {
        float x = sb[j*3], y = sb[j*3+1], z = sb[j*3+2];
        sx[j] = x; sy[j] = y; sz[j] = z; ss[j] = x*x + y*y + z*z;
    }
    __syncthreads();
    int w = threadIdx.x >> 5, lane = threadIdx.x & 31;
    int n = blockIdx.x * 4 + w;
    const float* q = pf + ((size_t)b * NN + n) * 3;
    float qx = q[0], qy = q[1], qz = q[2];
    float qn = qx*qx + qy*qy + qz*qz;
    float* d = sd[w];
    for (int j = lane; j < MM; j += 32)
        d[j] = qn + ss[j] - 2.f * (qx*sx[j] + qy*sy[j] + qz*sz[j]);
    __syncwarp();
    int* out = idx_out + ((size_t)b * NN + n) * KNB;
    for (int t = 0; t < KNB; t++) {
        float best = 1e30f; int bi = 0;
        for (int j = lane; j < MM; j += 32) {
            float v = d[j];
            if (v < best || (v == best && j < bi)) { best = v; bi = j; }
        }
#pragma unroll
        for (int off = 16; off; off >>= 1) {
            float ov = __shfl_xor_sync(0xffffffffu, best, off);
            int   oi = __shfl_xor_sync(0xffffffffu, bi, off);
            if (ov < best || (ov == best && oi < bi)) { best = ov; bi = oi; }
        }
        if (lane == 0) out[t] = bi;
        if (lane == (bi & 31)) d[bi] = 1e30f;
        __syncwarp();
    }
}

// ---------------- geometry -> hrelu (R,64) fp16 ------------------------------
__global__ __launch_bounds__(256)
void geom_kernel(const float* __restrict__ pos,
                 const float* __restrict__ seed,
                 const int*   __restrict__ idxg,
                 const float* __restrict__ pw1,
                 const float* __restrict__ aP, const float* __restrict__ cP,
                 __half* __restrict__ hrelu)
{
    int r = blockIdx.x * 256 + threadIdx.x;
    int b = r >> 16;
    int n = (r >> 4) & (NN - 1);
    int j = idxg[r];
    float px = pos[((size_t)b * 3 + 0) * NN + n];
    float py = pos[((size_t)b * 3 + 1) * NN + n];
    float pz = pos[((size_t)b * 3 + 2) * NN + n];
    const float* sj = seed + ((size_t)b * MM + j) * 3;
    float rx = px - sj[0], ry = py - sj[1], rz = pz - sj[2];
    float ds = sqrtf(rx*rx + ry*ry + rz*rz);
    __half2* out = (__half2*)(hrelu + (size_t)r * PHD);
#pragma unroll
    for (int p0 = 0; p0 < PHD; p0 += 2) {
        float t[2];
#pragma unroll
        for (int u = 0; u < 2; u++) {
            int p = p0 + u;
            float raw = __ldg(&pw1[p*4]) * ds + __ldg(&pw1[p*4+1]) * rx
                      + __ldg(&pw1[p*4+2]) * ry + __ldg(&pw1[p*4+3]) * rz;
            t[u] = fmaxf(raw * __ldg(&aP[p]) + __ldg(&cP[p]), 0.f);
        }
        out[p0 >> 1] = __floats2half2_rn(t[0], t[1]);
    }
}

// ---------------- launch -----------------------------------------------------
extern "C" void kernel_launch(void* const* d_in, const int* in_sizes, int n_in,
                              void* d_out, int out_size)
{
    const float* pos      = (const float*)d_in[0];
    const float* pf       = (const float*)d_in[1];
    const float* fea      = (const float*)d_in[2];
    const float* seed     = (const float*)d_in[3];
    const float* seed_fea = (const float*)d_in[4];
    const float* w_start  = (const float*)d_in[5];
    const float* b_start  = (const float*)d_in[6];
    const float* w_key    = (const float*)d_in[7];
    const float* b_key    = (const float*)d_in[8];
    const float* w_value  = (const float*)d_in[9];
    const float* b_value  = (const float*)d_in[10];
    const float* w_query  = (const float*)d_in[11];
    const float* b_query  = (const float*)d_in[12];
    const float* pos_w1   = (const float*)d_in[13];
    const float* pos_b1   = (const float*)d_in[14];
    const float* pos_g1   = (const float*)d_in[15];
    const float* pos_beta1= (const float*)d_in[16];
    const float* pos_mu1  = (const float*)d_in[17];
    const float* pos_var1 = (const float*)d_in[18];
    const float* pos_w2   = (const float*)d_in[19];
    const float* pos_b2   = (const float*)d_in[20];
    const float* attn_w1  = (const float*)d_in[21];
    const float* attn_b1  = (const float*)d_in[22];
    const float* attn_g1  = (const float*)d_in[23];
    const float* attn_beta1=(const float*)d_in[24];
    const float* attn_mu1 = (const float*)d_in[25];
    const float* attn_var1= (const float*)d_in[26];
    const float* attn_w2  = (const float*)d_in[27];
    // d_in[28] = attn_b2: cancels in softmax over K
    const float* w_end    = (const float*)d_in[29];
    const float* b_end    = (const float*)d_in[30];

    float *valueT, *keyfT, *valftT, *queryT, *aggv, *pre1;
    float *aA, *cA, *aP, *cP;
    __half *W1qt, *W1kt, *hrelu, *hid, *pre1h, *w1h, *w2h, *pw2h, *wkh, *wvh;
    int* idx;
    cudaGetSymbolAddress((void**)&valueT, g_valueT);
    cudaGetSymbolAddress((void**)&keyfT,  g_keyfT);
    cudaGetSymbolAddress((void**)&valftT, g_valftT);
    cudaGetSymbolAddress((void**)&queryT, g_queryT);
    cudaGetSymbolAddress((void**)&W1qt,   g_W1qt);
    cudaGetSymbolAddress((void**)&W1kt,   g_W1kt);
    cudaGetSymbolAddress((void**)&idx,    g_idx);
    cudaGetSymbolAddress((void**)&hrelu,  g_hrelu);
    cudaGetSymbolAddress((void**)&hid,    g_hid);
    cudaGetSymbolAddress((void**)&aggv,   g_agg);
    cudaGetSymbolAddress((void**)&pre1,   g_pre1);
    cudaGetSymbolAddress((void**)&pre1h,  g_pre1h);
    cudaGetSymbolAddress((void**)&w1h,    g_w1h);
    cudaGetSymbolAddress((void**)&w2h,    g_w2h);
    cudaGetSymbolAddress((void**)&pw2h,   g_pw2h);
    cudaGetSymbolAddress((void**)&wkh,    g_wkh);
    cudaGetSymbolAddress((void**)&wvh,    g_wvh);
    cudaGetSymbolAddress((void**)&aA,     g_aA);
    cudaGetSymbolAddress((void**)&cA,     g_cA);
    cudaGetSymbolAddress((void**)&aP,     g_aP);
    cudaGetSymbolAddress((void**)&cP,     g_cP);

    cudaFuncSetAttribute(fused_attn, cudaFuncAttributeMaxDynamicSharedMemorySize, 75776);

    precomp_kernel<<<AHD + 1, PHD>>>(attn_w1, pos_w2, pos_b2,
                                     attn_g1, attn_beta1, attn_mu1, attn_var1, attn_b1,
                                     pos_g1, pos_beta1, pos_mu1, pos_var1, pos_b1,
                                     pre1, pre1h, aA, cA, aP, cP);
    cvt_all_kernel<<<(CV5 + 255)/256, 256>>>(attn_w1, attn_w2, pos_w2, w_key, w_value,
                                             w1h, w2h, pw2h, wkh, wvh);

    // value = w_start @ seed_fea  (SIMT, channel-major A), row-major out
    gemm_k<false,true><<<dim3(MM/128, DD/128, BB), 256>>>(
        w_start, b_start, seed_fea, nullptr, valueT, DD, CC, MM,
        (size_t)CC*MM, (size_t)MM*DD);
    // key/val via fp16 mma (A = valueT fp32 row-major)
    hgemm<256,256,0,false,false><<<dim3(2, BB*MM/128), 256>>>(
        wkh, b_key, valueT, keyfT, nullptr, nullptr, nullptr, nullptr, nullptr);
    hgemm<256,256,0,false,false><<<dim3(2, BB*MM/128), 256>>>(
        wvh, b_value, valueT, valftT, nullptr, nullptr, nullptr, nullptr, nullptr);
    // query (SIMT, channel-major A)
    gemm_k<false,true><<<dim3(NN/128, DD/128, BB), 256>>>(
        w_query, b_query, fea, nullptr, queryT, DD, CC, NN,
        (size_t)CC*NN, (size_t)NN*DD);

    // W1q / W1k via fp16 mma -> fp16 outputs
    hgemm<512,256,0,false,true><<<dim3(4, BB*NN/128), 256>>>(
        w1h, nullptr, queryT, W1qt, nullptr, nullptr, nullptr, nullptr, nullptr);
    hgemm<512,256,0,false,true><<<dim3(4, BB*MM/128), 256>>>(
        w1h, nullptr, keyfT, W1kt, nullptr, nullptr, nullptr, nullptr, nullptr);

    // knn + geometry
    knn_kernel<<<dim3(NN/4, BB), 128>>>(pf, seed, idx);
    geom_kernel<<<RR/256, 256>>>(pos, seed, idx, pos_w1, aP, cP, hrelu);

    // hid = relu(aA*(pre1@hrelu + W1q - W1k) + cA)  -> fp16
    hgemm<512,64,1,true,true><<<dim3(4, RR/128), 256>>>(
        pre1h, nullptr, hrelu, hid, W1qt, W1kt, idx, aA, cA);

    // fused: pe + logits + softmax + gather + aggregate -> aggv
    fused_attn<<<dim3(2, RR/128), 256, 75776>>>(
        w2h, hid, pw2h, hrelu, pos_b2, valftT, idx, aggv);

    // out = w_end @ aggv + b_end + fea
    gemm_k<true,false><<<dim3(NN/128, CC/128, BB), 256>>>(
        w_end, b_end, aggv, fea, (float*)d_out, CC, DD, NN,
        (size_t)NN*DD, (size_t)CC*NN);
}

// round 12
// speedup vs baseline: 1.3652x; 1.0303x over previous
#include <cuda_runtime.h>
#include <cuda_fp16.h>
#include <cstdint>
#include <cstddef>

#define BB 4
#define NN 4096
#define MM 1024
#define CC 128
#define DD 256
#define PHD 64
#define AHD 512
#define KNB 16
#define RR (BB*NN*KNB)   // 262144 rows (b,n,k)

// ---------------- static scratch --------------------------------------------
__device__ float  g_valueT[BB*MM*DD];     // (B*M, D)
__device__ float  g_keyfT [BB*MM*DD];
__device__ float  g_valftT[BB*MM*DD];
__device__ float  g_queryT[BB*NN*DD];     // (B*N, D)
__device__ __half g_W1qt  [BB*NN*AHD];    // (B*N, AH) fp16
__device__ __half g_W1kt  [BB*MM*AHD];    // (B*M, AH) fp16
__device__ int    g_idx   [RR];
__device__ __half g_hrelu [16777216];     // (R, 64) fp16
__device__ __half g_hid   [134217728];    // (R, 512) fp16
__device__ float  g_agg   [BB*NN*DD];     // (B*N, 256) aggv
__device__ float  g_pre1  [AHD*PHD];
__device__ __half g_pre1h [AHD*PHD];
__device__ __half g_w1h   [AHD*DD];       // attn_w1 fp16
__device__ __half g_w2h   [DD*AHD];       // attn_w2 fp16
__device__ __half g_pw2h  [DD*PHD];       // pos_w2 fp16
__device__ __half g_wkh   [DD*DD];        // w_key fp16
__device__ __half g_wvh   [DD*DD];        // w_value fp16
__device__ float  g_aA[AHD], g_cA[AHD], g_aP[PHD], g_cP[PHD];

// ---------------- helpers ----------------------------------------------------
__device__ __forceinline__ void mma16816(float* d, const uint32_t* a,
                                         uint32_t b0, uint32_t b1) {
    asm volatile(
        "mma.sync.aligned.m16n8k16.row.col.f32.f16.f16.f32 "
        "{%0,%1,%2,%3},{%4,%5,%6,%7},{%8,%9},{%0,%1,%2,%3};"
        : "+f"(d[0]), "+f"(d[1]), "+f"(d[2]), "+f"(d[3])
        : "r"(a[0]), "r"(a[1]), "r"(a[2]), "r"(a[3]), "r"(b0), "r"(b1));
}
__device__ __forceinline__ uint32_t packh2(float x, float y) {
    __half2 h = __floats2half2_rn(x, y);
    return *(uint32_t*)&h;
}
__device__ __forceinline__ uint32_t smem_u32(const void* p) {
    uint32_t a;
    asm("{ .reg .u64 t; cvta.to.shared.u64 t, %1; cvt.u32.u64 %0, t; }"
        : "=r"(a) : "l"(p));
    return a;
}
__device__ __forceinline__ void cp16(uint32_t dst, const void* src) {
    asm volatile("cp.async.cg.shared.global [%0], [%1], 16;"
                 :: "r"(dst), "l"(src) : "memory");
}
#define CP_COMMIT() asm volatile("cp.async.commit_group;" ::: "memory")
#define CP_WAIT(n)  asm volatile("cp.async.wait_group %0;" :: "n"(n) : "memory")

// ---------------- fp16 mma GEMM (round-7 proven): C = A(rows,K)@W(O,K)^T -----
// BM=128, BN=128, BK=32. 256 threads = 8 warps (4M x 2N), warp tile 32x64.
// EPI 0: C = acc (+bias fp32).   EPI 1: C = relu((acc+W1q-W1k)*aA+cA), W1 fp16
template<int O, int K, int EPI, bool AF16, bool OUTH>
__global__ __launch_bounds__(256)
void hgemm(const __half* __restrict__ Wh, const float* __restrict__ bias,
           const void* __restrict__ Ag, void* __restrict__ Cg,
           const __half* __restrict__ W1q, const __half* __restrict__ W1k,
           const int* __restrict__ idxg,
           const float* __restrict__ aA, const float* __restrict__ cA)
{
    constexpr int CCH = K / 32;
    __shared__ __align__(16) __half2 As2[128][20];
    __shared__ __align__(16) __half2 Bs2[128][20];
    const int row0 = blockIdx.y * 128;
    const int o0   = blockIdx.x * 128;
    const int tid  = threadIdx.x;
    const int lane = tid & 31;
    const int wid  = tid >> 5;
    const int wm = wid & 3;
    const int wn = wid >> 2;
    const int lq = lane >> 2;
    const int lr = lane & 3;

    float acc[2][8][4];
#pragma unroll
    for (int mt = 0; mt < 2; mt++)
#pragma unroll
        for (int nt = 0; nt < 8; nt++)
#pragma unroll
            for (int q = 0; q < 4; q++) acc[mt][nt][q] = 0.f;

    uint4  ra[2], rbv[2];
    float4 fa[2][2];

    auto fetch = [&](int c) {
        if (AF16) {
            const __half* s = (const __half*)Ag +
                (size_t)(row0 + (tid >> 1)) * K + c * 32 + (tid & 1) * 16;
            ra[0] = *(const uint4*)s;
            ra[1] = *(const uint4*)(s + 8);
        } else {
#pragma unroll
            for (int i = 0; i < 2; i++) {
                int lin = tid + i * 256;
                int r = lin >> 2, cq = (lin & 3) * 4;
                const float* s = (const float*)Ag +
                    (size_t)(row0 + r) * K + c * 32 + cq * 2;
                fa[i][0] = *(const float4*)s;
                fa[i][1] = *(const float4*)(s + 4);
            }
        }
        const __half* w = Wh + (size_t)(o0 + (tid >> 1)) * K + c * 32 + (tid & 1) * 16;
        rbv[0] = *(const uint4*)w;
        rbv[1] = *(const uint4*)(w + 8);
    };
    auto store = [&]() {
        int r = tid >> 1, c0 = (tid & 1) * 8;
        if (AF16) {
            *(uint4*)&As2[r][c0]     = ra[0];
            *(uint4*)&As2[r][c0 + 4] = ra[1];
        } else {
#pragma unroll
            for (int i = 0; i < 2; i++) {
                int lin = tid + i * 256;
                int rr = lin >> 2, cq = (lin & 3) * 4;
                uint4 u;
                u.x = packh2(fa[i][0].x, fa[i][0].y);
                u.y = packh2(fa[i][0].z, fa[i][0].w);
                u.z = packh2(fa[i][1].x, fa[i][1].y);
                u.w = packh2(fa[i][1].z, fa[i][1].w);
                *(uint4*)&As2[rr][cq] = u;
            }
        }
        *(uint4*)&Bs2[r][c0]     = rbv[0];
        *(uint4*)&Bs2[r][c0 + 4] = rbv[1];
    };

    fetch(0);
#pragma unroll 1
    for (int c = 0; c < CCH; c++) {
        store();
        __syncthreads();
        if (c + 1 < CCH) fetch(c + 1);
#pragma unroll
        for (int ks = 0; ks < 2; ks++) {
            const int kb = ks * 8 + lr;
            uint32_t bf[8][2];
#pragma unroll
            for (int nt = 0; nt < 8; nt++) {
                int cb = wn * 64 + nt * 8 + lq;
                bf[nt][0] = *(const uint32_t*)&Bs2[cb][kb];
                bf[nt][1] = *(const uint32_t*)&Bs2[cb][kb + 4];
            }
#pragma unroll
            for (int mt = 0; mt < 2; mt++) {
                int rb = wm * 32 + mt * 16 + lq;
                uint32_t a[4];
                a[0] = *(const uint32_t*)&As2[rb][kb];
                a[1] = *(const uint32_t*)&As2[rb + 8][kb];
                a[2] = *(const uint32_t*)&As2[rb][kb + 4];
                a[3] = *(const uint32_t*)&As2[rb + 8][kb + 4];
#pragma unroll
                for (int nt = 0; nt < 8; nt++)
                    mma16816(acc[mt][nt], a, bf[nt][0], bf[nt][1]);
            }
        }
        __syncthreads();
    }

    // ---- epilogue ----
#pragma unroll
    for (int mt = 0; mt < 2; mt++) {
#pragma unroll
        for (int h = 0; h < 2; h++) {
            int r = row0 + wm * 32 + mt * 16 + h * 8 + lq;
            const __half* qp = nullptr;
            const __half* kp = nullptr;
            if (EPI == 1) {
                int bbx = r >> 16;
                int jj = idxg[r];
                qp = W1q + (size_t)(r >> 4) * AHD;
                kp = W1k + ((size_t)bbx * MM + jj) * AHD;
            }
#pragma unroll
            for (int nt = 0; nt < 8; nt++) {
                int o = o0 + wn * 64 + nt * 8 + lr * 2;
                float v0 = acc[mt][nt][h * 2 + 0];
                float v1 = acc[mt][nt][h * 2 + 1];
                if (EPI == 0) {
                    if (bias) { v0 += bias[o]; v1 += bias[o + 1]; }
                } else {
                    float2 qv = __half22float2(*(const __half2*)(qp + o));
                    float2 kv = __half22float2(*(const __half2*)(kp + o));
                    float2 av = *(const float2*)(aA + o);
                    float2 cv = *(const float2*)(cA + o);
                    v0 = fmaxf((v0 + qv.x - kv.x) * av.x + cv.x, 0.f);
                    v1 = fmaxf((v1 + qv.y - kv.y) * av.y + cv.y, 0.f);
                }
                if (OUTH) {
                    __half2 hv = __floats2half2_rn(v0, v1);
                    *(__half2*)((__half*)Cg + (size_t)r * O + o) = hv;
                } else {
                    *(float2*)((float*)Cg + (size_t)r * O + o) = make_float2(v0, v1);
                }
            }
        }
    }
}

// ---------------- fused: pe GEMM -> smem, logits GEMM, softmax+gather+agg ----
// grid (2, RR/128), 256 thr, 2 CTAs/SM. cp.async 3-stage, 1 sync/chunk.
// Dynamic smem: As 3*10240 + Bs 3*10240 + sPE 34816 = 96256 B.
__global__ __launch_bounds__(256, 2)
void fused_attn(const __half* __restrict__ w2h,    // (256,512)
                const __half* __restrict__ hid,    // (R,512)
                const __half* __restrict__ pw2h,   // (256,64)
                const __half* __restrict__ hrelu,  // (R,64)
                const float* __restrict__ pb2,     // (256)
                const float* __restrict__ valft,   // (B*M,256)
                const int*   __restrict__ idxg,
                float* __restrict__ aggv)          // (B*N,256)
{
    extern __shared__ char dsm[];
    __half2 (*As2)[128][20] = (__half2(*)[128][20])(dsm);           // 3*10240 B
    __half2 (*Bs2)[128][20] = (__half2(*)[128][20])(dsm + 30720);   // 3*10240 B
    __half2 (*sPE)[68]      = (__half2(*)[68])(dsm + 61440);        // 34816 B
    __shared__ int sidx[128];
    const uint32_t sA = smem_u32(dsm);
    const uint32_t sB = sA + 30720;
    const int row0 = blockIdx.y * 128;
    const int o0   = blockIdx.x * 128;
    const int tid  = threadIdx.x;
    const int lane = tid & 31;
    const int wid  = tid >> 5;
    const int wm = wid & 3;
    const int wn = wid >> 2;
    const int lq = lane >> 2;
    const int lr = lane & 3;

    if (tid < 128) sidx[tid] = idxg[row0 + tid];

    const __half* Ap;
    const __half* Wp;
    int Kd;
    // async copy of chunk c into stage buf (A row tile + B weight tile)
    auto fetch_async = [&](int c, int buf) {
        const int r = tid >> 1;
        const uint32_t off = (uint32_t)buf * 10240 + (uint32_t)r * 80 + (tid & 1) * 32;
        const __half* sa = Ap + (size_t)(row0 + r) * Kd + c * 32 + (tid & 1) * 16;
        cp16(sA + off, sa);
        cp16(sA + off + 16, sa + 8);
        const __half* sw = Wp + (size_t)(o0 + r) * Kd + c * 32 + (tid & 1) * 16;
        cp16(sB + off, sw);
        cp16(sB + off + 16, sw + 8);
    };
    auto mma_all = [&](int p, float (&acc)[2][8][4]) {
#pragma unroll
        for (int ks = 0; ks < 2; ks++) {
            const int kb = ks * 8 + lr;
            uint32_t bf[8][2];
#pragma unroll
            for (int nt = 0; nt < 8; nt++) {
                int cb = wn * 64 + nt * 8 + lq;
                bf[nt][0] = *(const uint32_t*)&Bs2[p][cb][kb];
                bf[nt][1] = *(const uint32_t*)&Bs2[p][cb][kb + 4];
            }
#pragma unroll
            for (int mt = 0; mt < 2; mt++) {
                int rb2 = wm * 32 + mt * 16 + lq;
                uint32_t a[4];
                a[0] = *(const uint32_t*)&As2[p][rb2][kb];
                a[1] = *(const uint32_t*)&As2[p][rb2 + 8][kb];
                a[2] = *(const uint32_t*)&As2[p][rb2][kb + 4];
                a[3] = *(const uint32_t*)&As2[p][rb2 + 8][kb + 4];
#pragma unroll
                for (int nt = 0; nt < 8; nt++)
                    mma16816(acc[mt][nt], a, bf[nt][0], bf[nt][1]);
            }
        }
    };
    // pipelined GEMM over CCH chunks (3-stage, 2 in flight, 1 sync/chunk)
    auto run_gemm = [&](int CCH, float (&acc)[2][8][4]) {
        fetch_async(0, 0);
        CP_COMMIT();
        if (CCH > 1) { fetch_async(1, 1); }
        CP_COMMIT();
#pragma unroll 1
        for (int c = 0; c < CCH; c++) {
            if (c + 1 < CCH) { CP_WAIT(1); } else { CP_WAIT(0); }
            __syncthreads();
            if (c + 2 < CCH) { fetch_async(c + 2, (c + 2) % 3); }
            CP_COMMIT();
            mma_all(c % 3, acc);
        }
        __syncthreads();   // protect stage buffers before next phase refill
    };

    // ---- phase 1: pe = pos_w2 @ hrelu -> sPE (fp16, +pb2) ----
    {
        float acc2[2][8][4];
#pragma unroll
        for (int mt = 0; mt < 2; mt++)
#pragma unroll
            for (int nt = 0; nt < 8; nt++)
#pragma unroll
                for (int q = 0; q < 4; q++) acc2[mt][nt][q] = 0.f;
        Ap = hrelu; Wp = pw2h; Kd = PHD;
        run_gemm(PHD / 32, acc2);
#pragma unroll
        for (int mt = 0; mt < 2; mt++)
#pragma unroll
            for (int nt = 0; nt < 8; nt++) {
                int cch = o0 + wn * 64 + nt * 8 + lr * 2;
                float2 pbv = *(const float2*)(pb2 + cch);
                sPE[wm*32 + mt*16 + lq][wn*32 + nt*4 + lr] =
                    __floats2half2_rn(acc2[mt][nt][0] + pbv.x, acc2[mt][nt][1] + pbv.y);
                sPE[wm*32 + mt*16 + 8 + lq][wn*32 + nt*4 + lr] =
                    __floats2half2_rn(acc2[mt][nt][2] + pbv.x, acc2[mt][nt][3] + pbv.y);
            }
    }

    // ---- phase 2: logits = attn_w2 @ hid ----
    float acc1[2][8][4];
#pragma unroll
    for (int mt = 0; mt < 2; mt++)
#pragma unroll
        for (int nt = 0; nt < 8; nt++)
#pragma unroll
            for (int q = 0; q < 4; q++) acc1[mt][nt][q] = 0.f;
    Ap = hid; Wp = w2h; Kd = AHD;
    run_gemm(AHD / 32, acc1);

    // ---- softmax over k (16 rows per point, within warp) + gather + agg ----
    const int bb = row0 >> 16;
#pragma unroll
    for (int mt = 0; mt < 2; mt++) {
        const int pt = (row0 + wm * 32 + mt * 16) >> 4;
        const int j0 = sidx[wm * 32 + mt * 16 + lq];
        const int j1 = sidx[wm * 32 + mt * 16 + 8 + lq];
        const float* v0b = valft + ((size_t)bb * MM + j0) * DD;
        const float* v1b = valft + ((size_t)bb * MM + j1) * DD;
#pragma unroll
        for (int nt = 0; nt < 8; nt++) {
            const int c = o0 + wn * 64 + nt * 8 + lr * 2;
            float2 vv0 = *(const float2*)(v0b + c);
            float2 vv1 = *(const float2*)(v1b + c);
            float2 p0 = __half22float2(sPE[wm*32 + mt*16 + lq][wn*32 + nt*4 + lr]);
            float2 p1 = __half22float2(sPE[wm*32 + mt*16 + 8 + lq][wn*32 + nt*4 + lr]);
            float outc[2];
#pragma unroll
            for (int j = 0; j < 2; j++) {
                float l0 = acc1[mt][nt][j];
                float l1 = acc1[mt][nt][2 + j];
                float m = fmaxf(l0, l1);
                m = fmaxf(m, __shfl_xor_sync(0xffffffffu, m, 4));
                m = fmaxf(m, __shfl_xor_sync(0xffffffffu, m, 8));
                m = fmaxf(m, __shfl_xor_sync(0xffffffffu, m, 16));
                float e0 = __expf(l0 - m), e1 = __expf(l1 - m);
                float S = e0 + e1;
                S += __shfl_xor_sync(0xffffffffu, S, 4);
                S += __shfl_xor_sync(0xffffffffu, S, 8);
                S += __shfl_xor_sync(0xffffffffu, S, 16);
                float pe0 = j ? p0.y : p0.x;
                float pe1 = j ? p1.y : p1.x;
                float va0 = j ? vv0.y : vv0.x;
                float va1 = j ? vv1.y : vv1.x;
                float T = e0 * (va0 + pe0) + e1 * (va1 + pe1);
                T += __shfl_xor_sync(0xffffffffu, T, 4);
                T += __shfl_xor_sync(0xffffffffu, T, 8);
                T += __shfl_xor_sync(0xffffffffu, T, 16);
                outc[j] = T / S;
            }
            if (lq == 0)
                *(float2*)(aggv + (size_t)pt * DD + c) = make_float2(outc[0], outc[1]);
        }
    }
}

// ---------------- precompute + weight conversions ----------------------------
__global__ void precomp_kernel(const float* __restrict__ w1,
                               const float* __restrict__ pw2,
                               const float* __restrict__ pb2,
                               const float* __restrict__ ag, const float* __restrict__ abeta,
                               const float* __restrict__ amu, const float* __restrict__ avar,
                               const float* __restrict__ ab1,
                               const float* __restrict__ pg, const float* __restrict__ pbeta,
                               const float* __restrict__ pmu, const float* __restrict__ pvar,
                               const float* __restrict__ pb1,
                               float* __restrict__ pre1, __half* __restrict__ pre1h,
                               float* __restrict__ aA,
                               float* __restrict__ cA, float* __restrict__ aP,
                               float* __restrict__ cP)
{
    int o = blockIdx.x;
    if (o < AHD) {
        int p = threadIdx.x;
        float s = 0.f;
        for (int c = 0; c < DD; c++) s += w1[o*DD + c] * pw2[c*PHD + p];
        pre1[o*PHD + p] = s;
        pre1h[o*PHD + p] = __float2half_rn(s);
        if (p == 0) {
            float vb = 0.f;
            for (int c = 0; c < DD; c++) vb += w1[o*DD + c] * pb2[c];
            float inv = ag[o] / sqrtf(avar[o] + 1e-5f);
            aA[o] = inv;
            cA[o] = (ab1[o] - amu[o]) * inv + abeta[o] + vb * inv;
        }
    } else {
        int p = threadIdx.x;
        float inv = pg[p] / sqrtf(pvar[p] + 1e-5f);
        aP[p] = inv;
        cP[p] = (pb1[p] - pmu[p]) * inv + pbeta[p];
    }
}

// one launch converts all five weight matrices to fp16
#define CV1 (AHD*DD)
#define CV2 (CV1 + DD*AHD)
#define CV3 (CV2 + DD*PHD)
#define CV4 (CV3 + DD*DD)
#define CV5 (CV4 + DD*DD)
__global__ void cvt_all_kernel(const float* __restrict__ w1, const float* __restrict__ w2,
                               const float* __restrict__ pw2, const float* __restrict__ wk,
                               const float* __restrict__ wv,
                               __half* __restrict__ w1h, __half* __restrict__ w2h,
                               __half* __restrict__ pw2h, __half* __restrict__ wkh,
                               __half* __restrict__ wvh)
{
    int i = blockIdx.x * 256 + threadIdx.x;
    if (i < CV1)      w1h [i]       = __float2half_rn(w1 [i]);
    else if (i < CV2) w2h [i - CV1] = __float2half_rn(w2 [i - CV1]);
    else if (i < CV3) pw2h[i - CV2] = __float2half_rn(pw2[i - CV2]);
    else if (i < CV4) wkh [i - CV3] = __float2half_rn(wk [i - CV3]);
    else if (i < CV5) wvh [i - CV4] = __float2half_rn(wv [i - CV4]);
}

// ---------------- SIMT fp32 GEMM (small front/end GEMMs) ---------------------
constexpr int TBO = 128, TBX = 128, TBK = 16;

template<bool A_RM, bool OUT_XO>
__global__ __launch_bounds__(256)
void gemm_k(const float* __restrict__ W, const float* __restrict__ bias,
            const float* __restrict__ A, const float* __restrict__ resid,
            float* __restrict__ C, int O, int K, int X, size_t sA, size_t sC)
{
    __shared__ float As[TBK][TBX];
    __shared__ float Ws[TBK][TBO];
    const int bx = blockIdx.x * TBX;
    const int bo = blockIdx.y * TBO;
    const int b  = blockIdx.z;
    const float* Ab = A + (size_t)b * sA;
    float* Cb = C + (size_t)b * sC;
    const int tid = threadIdx.x;
    const int tco = (tid & 15) * 4;
    const int tcx = (tid >> 4) * 4;

    float acc[8][8];
#pragma unroll
    for (int i = 0; i < 8; i++)
#pragma unroll
        for (int j = 0; j < 8; j++) acc[i][j] = 0.f;

    for (int k0 = 0; k0 < K; k0 += TBK) {
        if (A_RM) {
            int row = tid >> 1, c0 = (tid & 1) * 8;
            const float* p = Ab + (size_t)(bx + row) * K + k0 + c0;
            float4 v0 = *(const float4*)p;
            float4 v1 = *(const float4*)(p + 4);
            As[c0+0][row] = v0.x; As[c0+1][row] = v0.y;
            As[c0+2][row] = v0.z; As[c0+3][row] = v0.w;
            As[c0+4][row] = v1.x; As[c0+5][row] = v1.y;
            As[c0+6][row] = v1.z; As[c0+7][row] = v1.w;
        } else {
            int kk = tid >> 4, x8 = (tid & 15) * 8;
            const float* p = Ab + (size_t)(k0 + kk) * X + bx + x8;
            float4 v0 = *(const float4*)p;
            float4 v1 = *(const float4*)(p + 4);
            *(float4*)&As[kk][x8]     = v0;
            *(float4*)&As[kk][x8 + 4] = v1;
        }
        {
            int row = tid >> 1, c0 = (tid & 1) * 8;
            const float* p = W + (size_t)(bo + row) * K + k0 + c0;
            float4 v0 = *(const float4*)p;
            float4 v1 = *(const float4*)(p + 4);
            Ws[c0+0][row] = v0.x; Ws[c0+1][row] = v0.y;
            Ws[c0+2][row] = v0.z; Ws[c0+3][row] = v0.w;
            Ws[c0+4][row] = v1.x; Ws[c0+5][row] = v1.y;
            Ws[c0+6][row] = v1.z; Ws[c0+7][row] = v1.w;
        }
        __syncthreads();
#pragma unroll
        for (int kk = 0; kk < TBK; kk++) {
            float4 a0 = *(const float4*)&As[kk][tcx];
            float4 a1 = *(const float4*)&As[kk][tcx + 64];
            float4 w0 = *(const float4*)&Ws[kk][tco];
            float4 w1 = *(const float4*)&Ws[kk][tco + 64];
            float a[8] = {a0.x, a0.y, a0.z, a0.w, a1.x, a1.y, a1.z, a1.w};
            float w[8] = {w0.x, w0.y, w0.z, w0.w, w1.x, w1.y, w1.z, w1.w};
#pragma unroll
            for (int i = 0; i < 8; i++)
#pragma unroll
                for (int j = 0; j < 8; j++)
                    acc[i][j] = fmaf(a[i], w[j], acc[i][j]);
        }
        __syncthreads();
    }
#pragma unroll
    for (int i = 0; i < 8; i++) {
        int xx = bx + (i < 4 ? tcx + i : 64 + tcx + (i - 4));
#pragma unroll
        for (int jh = 0; jh < 2; jh++) {
            int oo = bo + tco + jh * 64;
            float vr[4];
#pragma unroll
            for (int j = 0; j < 4; j++) vr[j] = acc[i][jh * 4 + j];
            if (bias) {
#pragma unroll
                for (int j = 0; j < 4; j++) vr[j] += bias[oo + j];
            }
            if (OUT_XO) {
                size_t ix = (size_t)xx * O + oo;
                if (resid) {
                    float4 rv = *(const float4*)(resid + (size_t)b * sC + ix);
                    vr[0] += rv.x; vr[1] += rv.y; vr[2] += rv.z; vr[3] += rv.w;
                }
                float4 ov = {vr[0], vr[1], vr[2], vr[3]};
                *(float4*)(Cb + ix) = ov;
            } else {
#pragma unroll
                for (int j = 0; j < 4; j++) {
                    size_t ix = (size_t)(oo + j) * X + xx;
                    float v = vr[j];
                    if (resid) v += resid[(size_t)b * sC + ix];
                    Cb[ix] = v;
                }
            }
        }
    }
}

// ---------------- KNN --------------------------------------------------------
__global__ __launch_bounds__(128)
void knn_kernel(const float* __restrict__ pf,
                const float* __restrict__ seed,
                int* __restrict__ idx_out)
{
    __shared__ float sx[MM], sy[MM], sz[MM], ss[MM];
    __shared__ float sd[4][MM];
    int b = blockIdx.y;
    const float* sb = seed + (size_t)b * MM * 3;
    for (int j = threadIdx.x; j < MM; j += 128) {
        float x = sb[j*3], y = sb[j*3+1], z = sb[j*3+2];
        sx[j] = x; sy[j] = y; sz[j] = z; ss[j] = x*x + y*y + z*z;
    }
    __syncthreads();
    int w = threadIdx.x >> 5, lane = threadIdx.x & 31;
    int n = blockIdx.x * 4 + w;
    const float* q = pf + ((size_t)b * NN + n) * 3;
    float qx = q[0], qy = q[1], qz = q[2];
    float qn = qx*qx + qy*qy + qz*qz;
    float* d = sd[w];
    for (int j = lane; j < MM; j += 32)
        d[j] = qn + ss[j] - 2.f * (qx*sx[j] + qy*sy[j] + qz*sz[j]);
    __syncwarp();
    int* out = idx_out + ((size_t)b * NN + n) * KNB;
    for (int t = 0; t < KNB; t++) {
        float best = 1e30f; int bi = 0;
        for (int j = lane; j < MM; j += 32) {
            float v = d[j];
            if (v < best || (v == best && j < bi)) { best = v; bi = j; }
        }
#pragma unroll
        for (int off = 16; off; off >>= 1) {
            float ov = __shfl_xor_sync(0xffffffffu, best, off);
            int   oi = __shfl_xor_sync(0xffffffffu, bi, off);
            if (ov < best || (ov == best && oi < bi)) { best = ov; bi = oi; }
        }
        if (lane == 0) out[t] = bi;
        if (lane == (bi & 31)) d[bi] = 1e30f;
        __syncwarp();
    }
}

// ---------------- geometry -> hrelu (R,64) fp16 ------------------------------
__global__ __launch_bounds__(256)
void geom_kernel(const float* __restrict__ pos,
                 const float* __restrict__ seed,
                 const int*   __restrict__ idxg,
                 const float* __restrict__ pw1,
                 const float* __restrict__ aP, const float* __restrict__ cP,
                 __half* __restrict__ hrelu)
{
    int r = blockIdx.x * 256 + threadIdx.x;
    int b = r >> 16;
    int n = (r >> 4) & (NN - 1);
    int j = idxg[r];
    float px = pos[((size_t)b * 3 + 0) * NN + n];
    float py = pos[((size_t)b * 3 + 1) * NN + n];
    float pz = pos[((size_t)b * 3 + 2) * NN + n];
    const float* sj = seed + ((size_t)b * MM + j) * 3;
    float rx = px - sj[0], ry = py - sj[1], rz = pz - sj[2];
    float ds = sqrtf(rx*rx + ry*ry + rz*rz);
    __half2* out = (__half2*)(hrelu + (size_t)r * PHD);
#pragma unroll
    for (int p0 = 0; p0 < PHD; p0 += 2) {
        float t[2];
#pragma unroll
        for (int u = 0; u < 2; u++) {
            int p = p0 + u;
            float raw = __ldg(&pw1[p*4]) * ds + __ldg(&pw1[p*4+1]) * rx
                      + __ldg(&pw1[p*4+2]) * ry + __ldg(&pw1[p*4+3]) * rz;
            t[u] = fmaxf(raw * __ldg(&aP[p]) + __ldg(&cP[p]), 0.f);
        }
        out[p0 >> 1] = __floats2half2_rn(t[0], t[1]);
    }
}

// ---------------- launch -----------------------------------------------------
extern "C" void kernel_launch(void* const* d_in, const int* in_sizes, int n_in,
                              void* d_out, int out_size)
{
    const float* pos      = (const float*)d_in[0];
    const float* pf       = (const float*)d_in[1];
    const float* fea      = (const float*)d_in[2];
    const float* seed     = (const float*)d_in[3];
    const float* seed_fea = (const float*)d_in[4];
    const float* w_start  = (const float*)d_in[5];
    const float* b_start  = (const float*)d_in[6];
    const float* w_key    = (const float*)d_in[7];
    const float* b_key    = (const float*)d_in[8];
    const float* w_value  = (const float*)d_in[9];
    const float* b_value  = (const float*)d_in[10];
    const float* w_query  = (const float*)d_in[11];
    const float* b_query  = (const float*)d_in[12];
    const float* pos_w1   = (const float*)d_in[13];
    const float* pos_b1   = (const float*)d_in[14];
    const float* pos_g1   = (const float*)d_in[15];
    const float* pos_beta1= (const float*)d_in[16];
    const float* pos_mu1  = (const float*)d_in[17];
    const float* pos_var1 = (const float*)d_in[18];
    const float* pos_w2   = (const float*)d_in[19];
    const float* pos_b2   = (const float*)d_in[20];
    const float* attn_w1  = (const float*)d_in[21];
    const float* attn_b1  = (const float*)d_in[22];
    const float* attn_g1  = (const float*)d_in[23];
    const float* attn_beta1=(const float*)d_in[24];
    const float* attn_mu1 = (const float*)d_in[25];
    const float* attn_var1= (const float*)d_in[26];
    const float* attn_w2  = (const float*)d_in[27];
    // d_in[28] = attn_b2: cancels in softmax over K
    const float* w_end    = (const float*)d_in[29];
    const float* b_end    = (const float*)d_in[30];

    float *valueT, *keyfT, *valftT, *queryT, *aggv, *pre1;
    float *aA, *cA, *aP, *cP;
    __half *W1qt, *W1kt, *hrelu, *hid, *pre1h, *w1h, *w2h, *pw2h, *wkh, *wvh;
    int* idx;
    cudaGetSymbolAddress((void**)&valueT, g_valueT);
    cudaGetSymbolAddress((void**)&keyfT,  g_keyfT);
    cudaGetSymbolAddress((void**)&valftT, g_valftT);
    cudaGetSymbolAddress((void**)&queryT, g_queryT);
    cudaGetSymbolAddress((void**)&W1qt,   g_W1qt);
    cudaGetSymbolAddress((void**)&W1kt,   g_W1kt);
    cudaGetSymbolAddress((void**)&idx,    g_idx);
    cudaGetSymbolAddress((void**)&hrelu,  g_hrelu);
    cudaGetSymbolAddress((void**)&hid,    g_hid);
    cudaGetSymbolAddress((void**)&aggv,   g_agg);
    cudaGetSymbolAddress((void**)&pre1,   g_pre1);
    cudaGetSymbolAddress((void**)&pre1h,  g_pre1h);
    cudaGetSymbolAddress((void**)&w1h,    g_w1h);
    cudaGetSymbolAddress((void**)&w2h,    g_w2h);
    cudaGetSymbolAddress((void**)&pw2h,   g_pw2h);
    cudaGetSymbolAddress((void**)&wkh,    g_wkh);
    cudaGetSymbolAddress((void**)&wvh,    g_wvh);
    cudaGetSymbolAddress((void**)&aA,     g_aA);
    cudaGetSymbolAddress((void**)&cA,     g_cA);
    cudaGetSymbolAddress((void**)&aP,     g_aP);
    cudaGetSymbolAddress((void**)&cP,     g_cP);

    cudaFuncSetAttribute(fused_attn, cudaFuncAttributeMaxDynamicSharedMemorySize, 96256);

    precomp_kernel<<<AHD + 1, PHD>>>(attn_w1, pos_w2, pos_b2,
                                     attn_g1, attn_beta1, attn_mu1, attn_var1, attn_b1,
                                     pos_g1, pos_beta1, pos_mu1, pos_var1, pos_b1,
                                     pre1, pre1h, aA, cA, aP, cP);
    cvt_all_kernel<<<(CV5 + 255)/256, 256>>>(attn_w1, attn_w2, pos_w2, w_key, w_value,
                                             w1h, w2h, pw2h, wkh, wvh);

    // value = w_start @ seed_fea  (SIMT, channel-major A), row-major out
    gemm_k<false,true><<<dim3(MM/128, DD/128, BB), 256>>>(
        w_start, b_start, seed_fea, nullptr, valueT, DD, CC, MM,
        (size_t)CC*MM, (size_t)MM*DD);
    // key/val via fp16 mma (A = valueT fp32 row-major)
    hgemm<256,256,0,false,false><<<dim3(2, BB*MM/128), 256>>>(
        wkh, b_key, valueT, keyfT, nullptr, nullptr, nullptr, nullptr, nullptr);
    hgemm<256,256,0,false,false><<<dim3(2, BB*MM/128), 256>>>(
        wvh, b_value, valueT, valftT, nullptr, nullptr, nullptr, nullptr, nullptr);
    // query (SIMT, channel-major A)
    gemm_k<false,true><<<dim3(NN/128, DD/128, BB), 256>>>(
        w_query, b_query, fea, nullptr, queryT, DD, CC, NN,
        (size_t)CC*NN, (size_t)NN*DD);

    // W1q / W1k via fp16 mma -> fp16 outputs
    hgemm<512,256,0,false,true><<<dim3(4, BB*NN/128), 256>>>(
        w1h, nullptr, queryT, W1qt, nullptr, nullptr, nullptr, nullptr, nullptr);
    hgemm<512,256,0,false,true><<<dim3(4, BB*MM/128), 256>>>(
        w1h, nullptr, keyfT, W1kt, nullptr, nullptr, nullptr, nullptr, nullptr);

    // knn + geometry
    knn_kernel<<<dim3(NN/4, BB), 128>>>(pf, seed, idx);
    geom_kernel<<<RR/256, 256>>>(pos, seed, idx, pos_w1, aP, cP, hrelu);

    // hid = relu(aA*(pre1@hrelu + W1q - W1k) + cA)  -> fp16
    hgemm<512,64,1,true,true><<<dim3(4, RR/128), 256>>>(
        pre1h, nullptr, hrelu, hid, W1qt, W1kt, idx, aA, cA);

    // fused: pe + logits + softmax + gather + aggregate -> aggv
    fused_attn<<<dim3(2, RR/128), 256, 96256>>>(
        w2h, hid, pw2h, hrelu, pos_b2, valftT, idx, aggv);

    // out = w_end @ aggv + b_end + fea
    gemm_k<true,false><<<dim3(NN/128, CC/128, BB), 256>>>(
        w_end, b_end, aggv, fea, (float*)d_out, CC, DD, NN,
        (size_t)NN*DD, (size_t)CC*NN);
}

// round 13
// speedup vs baseline: 1.3822x; 1.0124x over previous
#include <cuda_runtime.h>
#include <cuda_fp16.h>
#include <cstdint>
#include <cstddef>

#define BB 4
#define NN 4096
#define MM 1024
#define CC 128
#define DD 256
#define PHD 64
#define AHD 512
#define KNB 16
#define RR (BB*NN*KNB)   // 262144 rows (b,n,k)

// ---------------- static scratch --------------------------------------------
__device__ float  g_valueT[BB*MM*DD];     // (B*M, D)
__device__ float  g_keyfT [BB*MM*DD];
__device__ float  g_valftT[BB*MM*DD];
__device__ float  g_queryT[BB*NN*DD];     // (B*N, D)
__device__ __half g_W1qt  [BB*NN*AHD];    // (B*N, AH) fp16
__device__ __half g_W1kt  [BB*MM*AHD];    // (B*M, AH) fp16
__device__ int    g_idx   [RR];
__device__ __half g_hrelu [16777216];     // (R, 64) fp16
__device__ __half g_hid   [134217728];    // (R, 512) fp16
__device__ float  g_agg   [BB*NN*DD];     // (B*N, 256) aggv
__device__ float  g_pre1  [AHD*PHD];
__device__ __half g_pre1h [AHD*PHD];
__device__ __half g_w1h   [AHD*DD];       // attn_w1 fp16
__device__ __half g_w2h   [DD*AHD];       // attn_w2 fp16
__device__ __half g_pw2h  [DD*PHD];       // pos_w2 fp16
__device__ __half g_wkh   [DD*DD];        // w_key fp16
__device__ __half g_wvh   [DD*DD];        // w_value fp16
__device__ float  g_aA[AHD], g_cA[AHD], g_aP[PHD], g_cP[PHD];

// ---------------- helpers ----------------------------------------------------
__device__ __forceinline__ void mma16816(float* d, const uint32_t* a,
                                         uint32_t b0, uint32_t b1) {
    asm volatile(
        "mma.sync.aligned.m16n8k16.row.col.f32.f16.f16.f32 "
        "{%0,%1,%2,%3},{%4,%5,%6,%7},{%8,%9},{%0,%1,%2,%3};"
        : "+f"(d[0]), "+f"(d[1]), "+f"(d[2]), "+f"(d[3])
        : "r"(a[0]), "r"(a[1]), "r"(a[2]), "r"(a[3]), "r"(b0), "r"(b1));
}
__device__ __forceinline__ uint32_t packh2(float x, float y) {
    __half2 h = __floats2half2_rn(x, y);
    return *(uint32_t*)&h;
}
__device__ __forceinline__ uint32_t smem_u32(const void* p) {
    uint32_t a;
    asm("{ .reg .u64 t; cvta.to.shared.u64 t, %1; cvt.u32.u64 %0, t; }"
        : "=r"(a) : "l"(p));
    return a;
}
__device__ __forceinline__ void ldsm4(uint32_t* r, uint32_t addr) {
    asm volatile("ldmatrix.sync.aligned.m8n8.x4.shared.b16 {%0,%1,%2,%3}, [%4];"
                 : "=r"(r[0]), "=r"(r[1]), "=r"(r[2]), "=r"(r[3]) : "r"(addr));
}
__device__ __forceinline__ void cp16(uint32_t dst, const void* src) {
    asm volatile("cp.async.cg.shared.global [%0], [%1], 16;"
                 :: "r"(dst), "l"(src) : "memory");
}
#define CP_COMMIT() asm volatile("cp.async.commit_group;" ::: "memory")
#define CP_WAIT(n)  asm volatile("cp.async.wait_group %0;" :: "n"(n) : "memory")

// ---------------- fp16 mma GEMM: C = A(rows,K)@W(O,K)^T ----------------------
// BM=128, BN=128, BK=32. 256 threads = 8 warps (4M x 2N), warp tile 32x64.
// Fragments via ldmatrix.x4 on the proven [128][20] half2 layout.
// EPI 0: C = acc (+bias fp32).   EPI 1: C = relu((acc+W1q-W1k)*aA+cA), W1 fp16
template<int O, int K, int EPI, bool AF16, bool OUTH>
__global__ __launch_bounds__(256)
void hgemm(const __half* __restrict__ Wh, const float* __restrict__ bias,
           const void* __restrict__ Ag, void* __restrict__ Cg,
           const __half* __restrict__ W1q, const __half* __restrict__ W1k,
           const int* __restrict__ idxg,
           const float* __restrict__ aA, const float* __restrict__ cA)
{
    constexpr int CCH = K / 32;
    __shared__ __align__(16) __half2 As2[128][20];
    __shared__ __align__(16) __half2 Bs2[128][20];
    const int row0 = blockIdx.y * 128;
    const int o0   = blockIdx.x * 128;
    const int tid  = threadIdx.x;
    const int lane = tid & 31;
    const int wid  = tid >> 5;
    const int wm = wid & 3;
    const int wn = wid >> 2;
    const int lq = lane >> 2;
    const int lr = lane & 3;
    const int rsel = lane & 15;            // ldmatrix row select
    const int wofs = (lane >> 4) << 2;     // ldmatrix word select (+0 / +4)

    float acc[2][8][4];
#pragma unroll
    for (int mt = 0; mt < 2; mt++)
#pragma unroll
        for (int nt = 0; nt < 8; nt++)
#pragma unroll
            for (int q = 0; q < 4; q++) acc[mt][nt][q] = 0.f;

    uint4  ra[2], rbv[2];
    float4 fa[2][2];

    auto fetch = [&](int c) {
        if (AF16) {
            const __half* s = (const __half*)Ag +
                (size_t)(row0 + (tid >> 1)) * K + c * 32 + (tid & 1) * 16;
            ra[0] = *(const uint4*)s;
            ra[1] = *(const uint4*)(s + 8);
        } else {
#pragma unroll
            for (int i = 0; i < 2; i++) {
                int lin = tid + i * 256;
                int r = lin >> 2, cq = (lin & 3) * 4;
                const float* s = (const float*)Ag +
                    (size_t)(row0 + r) * K + c * 32 + cq * 2;
                fa[i][0] = *(const float4*)s;
                fa[i][1] = *(const float4*)(s + 4);
            }
        }
        const __half* w = Wh + (size_t)(o0 + (tid >> 1)) * K + c * 32 + (tid & 1) * 16;
        rbv[0] = *(const uint4*)w;
        rbv[1] = *(const uint4*)(w + 8);
    };
    auto store = [&]() {
        int r = tid >> 1, c0 = (tid & 1) * 8;
        if (AF16) {
            *(uint4*)&As2[r][c0]     = ra[0];
            *(uint4*)&As2[r][c0 + 4] = ra[1];
        } else {
#pragma unroll
            for (int i = 0; i < 2; i++) {
                int lin = tid + i * 256;
                int rr = lin >> 2, cq = (lin & 3) * 4;
                uint4 u;
                u.x = packh2(fa[i][0].x, fa[i][0].y);
                u.y = packh2(fa[i][0].z, fa[i][0].w);
                u.z = packh2(fa[i][1].x, fa[i][1].y);
                u.w = packh2(fa[i][1].z, fa[i][1].w);
                *(uint4*)&As2[rr][cq] = u;
            }
        }
        *(uint4*)&Bs2[r][c0]     = rbv[0];
        *(uint4*)&Bs2[r][c0 + 4] = rbv[1];
    };

    fetch(0);
#pragma unroll 1
    for (int c = 0; c < CCH; c++) {
        store();
        __syncthreads();
        if (c + 1 < CCH) fetch(c + 1);
#pragma unroll
        for (int ks = 0; ks < 2; ks++) {
            const int wsel = ks * 8 + wofs;
            uint32_t bf[8][2];
#pragma unroll
            for (int np = 0; np < 4; np++) {
                uint32_t q[4];
                ldsm4(q, smem_u32(&Bs2[wn * 64 + np * 16 + rsel][wsel]));
                bf[np*2][0]   = q[0];
                bf[np*2+1][0] = q[1];
                bf[np*2][1]   = q[2];
                bf[np*2+1][1] = q[3];
            }
#pragma unroll
            for (int mt = 0; mt < 2; mt++) {
                uint32_t a[4];
                ldsm4(a, smem_u32(&As2[wm * 32 + mt * 16 + rsel][wsel]));
#pragma unroll
                for (int nt = 0; nt < 8; nt++)
                    mma16816(acc[mt][nt], a, bf[nt][0], bf[nt][1]);
            }
        }
        __syncthreads();
    }

    // ---- epilogue ----
#pragma unroll
    for (int mt = 0; mt < 2; mt++) {
#pragma unroll
        for (int h = 0; h < 2; h++) {
            int r = row0 + wm * 32 + mt * 16 + h * 8 + lq;
            const __half* qp = nullptr;
            const __half* kp = nullptr;
            if (EPI == 1) {
                int bbx = r >> 16;
                int jj = idxg[r];
                qp = W1q + (size_t)(r >> 4) * AHD;
                kp = W1k + ((size_t)bbx * MM + jj) * AHD;
            }
#pragma unroll
            for (int nt = 0; nt < 8; nt++) {
                int o = o0 + wn * 64 + nt * 8 + lr * 2;
                float v0 = acc[mt][nt][h * 2 + 0];
                float v1 = acc[mt][nt][h * 2 + 1];
                if (EPI == 0) {
                    if (bias) { v0 += bias[o]; v1 += bias[o + 1]; }
                } else {
                    float2 qv = __half22float2(*(const __half2*)(qp + o));
                    float2 kv = __half22float2(*(const __half2*)(kp + o));
                    float2 av = *(const float2*)(aA + o);
                    float2 cv = *(const float2*)(cA + o);
                    v0 = fmaxf((v0 + qv.x - kv.x) * av.x + cv.x, 0.f);
                    v1 = fmaxf((v1 + qv.y - kv.y) * av.y + cv.y, 0.f);
                }
                if (OUTH) {
                    __half2 hv = __floats2half2_rn(v0, v1);
                    *(__half2*)((__half*)Cg + (size_t)r * O + o) = hv;
                } else {
                    *(float2*)((float*)Cg + (size_t)r * O + o) = make_float2(v0, v1);
                }
            }
        }
    }
}

// ---------------- fused: pe GEMM -> smem, logits GEMM, softmax+gather+agg ----
// grid (2, RR/128), 256 thr, 2 CTAs/SM. cp.async 3-stage, 1 sync/chunk.
// ldmatrix fragment loads. Dynamic smem 96256 B.
__global__ __launch_bounds__(256, 2)
void fused_attn(const __half* __restrict__ w2h,    // (256,512)
                const __half* __restrict__ hid,    // (R,512)
                const __half* __restrict__ pw2h,   // (256,64)
                const __half* __restrict__ hrelu,  // (R,64)
                const float* __restrict__ pb2,     // (256)
                const float* __restrict__ valft,   // (B*M,256)
                const int*   __restrict__ idxg,
                float* __restrict__ aggv)          // (B*N,256)
{
    extern __shared__ char dsm[];
    __half2 (*As2)[128][20] = (__half2(*)[128][20])(dsm);           // 3*10240 B
    __half2 (*Bs2)[128][20] = (__half2(*)[128][20])(dsm + 30720);   // 3*10240 B
    __half2 (*sPE)[68]      = (__half2(*)[68])(dsm + 61440);        // 34816 B
    __shared__ int sidx[128];
    const uint32_t sA = smem_u32(dsm);
    const uint32_t sB = sA + 30720;
    const int row0 = blockIdx.y * 128;
    const int o0   = blockIdx.x * 128;
    const int tid  = threadIdx.x;
    const int lane = tid & 31;
    const int wid  = tid >> 5;
    const int wm = wid & 3;
    const int wn = wid >> 2;
    const int lq = lane >> 2;
    const int lr = lane & 3;
    const int rsel = lane & 15;
    const int wofs = (lane >> 4) << 2;

    if (tid < 128) sidx[tid] = idxg[row0 + tid];

    const __half* Ap;
    const __half* Wp;
    int Kd;
    auto fetch_async = [&](int c, int buf) {
        const int r = tid >> 1;
        const uint32_t off = (uint32_t)buf * 10240 + (uint32_t)r * 80 + (tid & 1) * 32;
        const __half* sa = Ap + (size_t)(row0 + r) * Kd + c * 32 + (tid & 1) * 16;
        cp16(sA + off, sa);
        cp16(sA + off + 16, sa + 8);
        const __half* sw = Wp + (size_t)(o0 + r) * Kd + c * 32 + (tid & 1) * 16;
        cp16(sB + off, sw);
        cp16(sB + off + 16, sw + 8);
    };
    auto mma_all = [&](int p, float (&acc)[2][8][4]) {
#pragma unroll
        for (int ks = 0; ks < 2; ks++) {
            const int wsel = ks * 8 + wofs;
            uint32_t bf[8][2];
#pragma unroll
            for (int np = 0; np < 4; np++) {
                uint32_t q[4];
                ldsm4(q, smem_u32(&Bs2[p][wn * 64 + np * 16 + rsel][wsel]));
                bf[np*2][0]   = q[0];
                bf[np*2+1][0] = q[1];
                bf[np*2][1]   = q[2];
                bf[np*2+1][1] = q[3];
            }
#pragma unroll
            for (int mt = 0; mt < 2; mt++) {
                uint32_t a[4];
                ldsm4(a, smem_u32(&As2[p][wm * 32 + mt * 16 + rsel][wsel]));
#pragma unroll
                for (int nt = 0; nt < 8; nt++)
                    mma16816(acc[mt][nt], a, bf[nt][0], bf[nt][1]);
            }
        }
    };
    auto run_gemm = [&](int CCH, float (&acc)[2][8][4]) {
        fetch_async(0, 0);
        CP_COMMIT();
        if (CCH > 1) { fetch_async(1, 1); }
        CP_COMMIT();
#pragma unroll 1
        for (int c = 0; c < CCH; c++) {
            if (c + 1 < CCH) { CP_WAIT(1); } else { CP_WAIT(0); }
            __syncthreads();
            if (c + 2 < CCH) { fetch_async(c + 2, (c + 2) % 3); }
            CP_COMMIT();
            mma_all(c % 3, acc);
        }
        __syncthreads();
    };

    // ---- phase 1: pe = pos_w2 @ hrelu -> sPE (fp16, +pb2) ----
    {
        float acc2[2][8][4];
#pragma unroll
        for (int mt = 0; mt < 2; mt++)
#pragma unroll
            for (int nt = 0; nt < 8; nt++)
#pragma unroll
                for (int q = 0; q < 4; q++) acc2[mt][nt][q] = 0.f;
        Ap = hrelu; Wp = pw2h; Kd = PHD;
        run_gemm(PHD / 32, acc2);
#pragma unroll
        for (int mt = 0; mt < 2; mt++)
#pragma unroll
            for (int nt = 0; nt < 8; nt++) {
                int cch = o0 + wn * 64 + nt * 8 + lr * 2;
                float2 pbv = *(const float2*)(pb2 + cch);
                sPE[wm*32 + mt*16 + lq][wn*32 + nt*4 + lr] =
                    __floats2half2_rn(acc2[mt][nt][0] + pbv.x, acc2[mt][nt][1] + pbv.y);
                sPE[wm*32 + mt*16 + 8 + lq][wn*32 + nt*4 + lr] =
                    __floats2half2_rn(acc2[mt][nt][2] + pbv.x, acc2[mt][nt][3] + pbv.y);
            }
    }

    // ---- phase 2: logits = attn_w2 @ hid ----
    float acc1[2][8][4];
#pragma unroll
    for (int mt = 0; mt < 2; mt++)
#pragma unroll
        for (int nt = 0; nt < 8; nt++)
#pragma unroll
            for (int q = 0; q < 4; q++) acc1[mt][nt][q] = 0.f;
    Ap = hid; Wp = w2h; Kd = AHD;
    run_gemm(AHD / 32, acc1);

    // ---- softmax over k (16 rows per point, within warp) + gather + agg ----
    const int bb = row0 >> 16;
#pragma unroll
    for (int mt = 0; mt < 2; mt++) {
        const int pt = (row0 + wm * 32 + mt * 16) >> 4;
        const int j0 = sidx[wm * 32 + mt * 16 + lq];
        const int j1 = sidx[wm * 32 + mt * 16 + 8 + lq];
        const float* v0b = valft + ((size_t)bb * MM + j0) * DD;
        const float* v1b = valft + ((size_t)bb * MM + j1) * DD;
#pragma unroll
        for (int nt = 0; nt < 8; nt++) {
            const int c = o0 + wn * 64 + nt * 8 + lr * 2;
            float2 vv0 = *(const float2*)(v0b + c);
            float2 vv1 = *(const float2*)(v1b + c);
            float2 p0 = __half22float2(sPE[wm*32 + mt*16 + lq][wn*32 + nt*4 + lr]);
            float2 p1 = __half22float2(sPE[wm*32 + mt*16 + 8 + lq][wn*32 + nt*4 + lr]);
            float outc[2];
#pragma unroll
            for (int j = 0; j < 2; j++) {
                float l0 = acc1[mt][nt][j];
                float l1 = acc1[mt][nt][2 + j];
                float m = fmaxf(l0, l1);
                m = fmaxf(m, __shfl_xor_sync(0xffffffffu, m, 4));
                m = fmaxf(m, __shfl_xor_sync(0xffffffffu, m, 8));
                m = fmaxf(m, __shfl_xor_sync(0xffffffffu, m, 16));
                float e0 = __expf(l0 - m), e1 = __expf(l1 - m);
                float S = e0 + e1;
                S += __shfl_xor_sync(0xffffffffu, S, 4);
                S += __shfl_xor_sync(0xffffffffu, S, 8);
                S += __shfl_xor_sync(0xffffffffu, S, 16);
                float pe0 = j ? p0.y : p0.x;
                float pe1 = j ? p1.y : p1.x;
                float va0 = j ? vv0.y : vv0.x;
                float va1 = j ? vv1.y : vv1.x;
                float T = e0 * (va0 + pe0) + e1 * (va1 + pe1);
                T += __shfl_xor_sync(0xffffffffu, T, 4);
                T += __shfl_xor_sync(0xffffffffu, T, 8);
                T += __shfl_xor_sync(0xffffffffu, T, 16);
                outc[j] = T / S;
            }
            if (lq == 0)
                *(float2*)(aggv + (size_t)pt * DD + c) = make_float2(outc[0], outc[1]);
        }
    }
}

// ---------------- precompute + weight conversions ----------------------------
__global__ void precomp_kernel(const float* __restrict__ w1,
                               const float* __restrict__ pw2,
                               const float* __restrict__ pb2,
                               const float* __restrict__ ag, const float* __restrict__ abeta,
                               const float* __restrict__ amu, const float* __restrict__ avar,
                               const float* __restrict__ ab1,
                               const float* __restrict__ pg, const float* __restrict__ pbeta,
                               const float* __restrict__ pmu, const float* __restrict__ pvar,
                               const float* __restrict__ pb1,
                               float* __restrict__ pre1, __half* __restrict__ pre1h,
                               float* __restrict__ aA,
                               float* __restrict__ cA, float* __restrict__ aP,
                               float* __restrict__ cP)
{
    int o = blockIdx.x;
    if (o < AHD) {
        int p = threadIdx.x;
        float s = 0.f;
        for (int c = 0; c < DD; c++) s += w1[o*DD + c] * pw2[c*PHD + p];
        pre1[o*PHD + p] = s;
        pre1h[o*PHD + p] = __float2half_rn(s);
        if (p == 0) {
            float vb = 0.f;
            for (int c = 0; c < DD; c++) vb += w1[o*DD + c] * pb2[c];
            float inv = ag[o] / sqrtf(avar[o] + 1e-5f);
            aA[o] = inv;
            cA[o] = (ab1[o] - amu[o]) * inv + abeta[o] + vb * inv;
        }
    } else {
        int p = threadIdx.x;
        float inv = pg[p] / sqrtf(pvar[p] + 1e-5f);
        aP[p] = inv;
        cP[p] = (pb1[p] - pmu[p]) * inv + pbeta[p];
    }
}

// one launch converts all five weight matrices to fp16
#define CV1 (AHD*DD)
#define CV2 (CV1 + DD*AHD)
#define CV3 (CV2 + DD*PHD)
#define CV4 (CV3 + DD*DD)
#define CV5 (CV4 + DD*DD)
__global__ void cvt_all_kernel(const float* __restrict__ w1, const float* __restrict__ w2,
                               const float* __restrict__ pw2, const float* __restrict__ wk,
                               const float* __restrict__ wv,
                               __half* __restrict__ w1h, __half* __restrict__ w2h,
                               __half* __restrict__ pw2h, __half* __restrict__ wkh,
                               __half* __restrict__ wvh)
{
    int i = blockIdx.x * 256 + threadIdx.x;
    if (i < CV1)      w1h [i]       = __float2half_rn(w1 [i]);
    else if (i < CV2) w2h [i - CV1] = __float2half_rn(w2 [i - CV1]);
    else if (i < CV3) pw2h[i - CV2] = __float2half_rn(pw2[i - CV2]);
    else if (i < CV4) wkh [i - CV3] = __float2half_rn(wk [i - CV3]);
    else if (i < CV5) wvh [i - CV4] = __float2half_rn(wv [i - CV4]);
}

// ---------------- SIMT fp32 GEMM (small front/end GEMMs) ---------------------
constexpr int TBO = 128, TBX = 128, TBK = 16;

template<bool A_RM, bool OUT_XO>
__global__ __launch_bounds__(256)
void gemm_k(const float* __restrict__ W, const float* __restrict__ bias,
            const float* __restrict__ A, const float* __restrict__ resid,
            float* __restrict__ C, int O, int K, int X, size_t sA, size_t sC)
{
    __shared__ float As[TBK][TBX];
    __shared__ float Ws[TBK][TBO];
    const int bx = blockIdx.x * TBX;
    const int bo = blockIdx.y * TBO;
    const int b  = blockIdx.z;
    const float* Ab = A + (size_t)b * sA;
    float* Cb = C + (size_t)b * sC;
    const int tid = threadIdx.x;
    const int tco = (tid & 15) * 4;
    const int tcx = (tid >> 4) * 4;

    float acc[8][8];
#pragma unroll
    for (int i = 0; i < 8; i++)
#pragma unroll
        for (int j = 0; j < 8; j++) acc[i][j] = 0.f;

    for (int k0 = 0; k0 < K; k0 += TBK) {
        if (A_RM) {
            int row = tid >> 1, c0 = (tid & 1) * 8;
            const float* p = Ab + (size_t)(bx + row) * K + k0 + c0;
            float4 v0 = *(const float4*)p;
            float4 v1 = *(const float4*)(p + 4);
            As[c0+0][row] = v0.x; As[c0+1][row] = v0.y;
            As[c0+2][row] = v0.z; As[c0+3][row] = v0.w;
            As[c0+4][row] = v1.x; As[c0+5][row] = v1.y;
            As[c0+6][row] = v1.z; As[c0+7][row] = v1.w;
        } else {
            int kk = tid >> 4, x8 = (tid & 15) * 8;
            const float* p = Ab + (size_t)(k0 + kk) * X + bx + x8;
            float4 v0 = *(const float4*)p;
            float4 v1 = *(const float4*)(p + 4);
            *(float4*)&As[kk][x8]     = v0;
            *(float4*)&As[kk][x8 + 4] = v1;
        }
        {
            int row = tid >> 1, c0 = (tid & 1) * 8;
            const float* p = W + (size_t)(bo + row) * K + k0 + c0;
            float4 v0 = *(const float4*)p;
            float4 v1 = *(const float4*)(p + 4);
            Ws[c0+0][row] = v0.x; Ws[c0+1][row] = v0.y;
            Ws[c0+2][row] = v0.z; Ws[c0+3][row] = v0.w;
            Ws[c0+4][row] = v1.x; Ws[c0+5][row] = v1.y;
            Ws[c0+6][row] = v1.z; Ws[c0+7][row] = v1.w;
        }
        __syncthreads();
#pragma unroll
        for (int kk = 0; kk < TBK; kk++) {
            float4 a0 = *(const float4*)&As[kk][tcx];
            float4 a1 = *(const float4*)&As[kk][tcx + 64];
            float4 w0 = *(const float4*)&Ws[kk][tco];
            float4 w1 = *(const float4*)&Ws[kk][tco + 64];
            float a[8] = {a0.x, a0.y, a0.z, a0.w, a1.x, a1.y, a1.z, a1.w};
            float w[8] = {w0.x, w0.y, w0.z, w0.w, w1.x, w1.y, w1.z, w1.w};
#pragma unroll
            for (int i = 0; i < 8; i++)
#pragma unroll
                for (int j = 0; j < 8; j++)
                    acc[i][j] = fmaf(a[i], w[j], acc[i][j]);
        }
        __syncthreads();
    }
#pragma unroll
    for (int i = 0; i < 8; i++) {
        int xx = bx + (i < 4 ? tcx + i : 64 + tcx + (i - 4));
#pragma unroll
        for (int jh = 0; jh < 2; jh++) {
            int oo = bo + tco + jh * 64;
            float vr[4];
#pragma unroll
            for (int j = 0; j < 4; j++) vr[j] = acc[i][jh * 4 + j];
            if (bias) {
#pragma unroll
                for (int j = 0; j < 4; j++) vr[j] += bias[oo + j];
            }
            if (OUT_XO) {
                size_t ix = (size_t)xx * O + oo;
                if (resid) {
                    float4 rv = *(const float4*)(resid + (size_t)b * sC + ix);
                    vr[0] += rv.x; vr[1] += rv.y; vr[2] += rv.z; vr[3] += rv.w;
                }
                float4 ov = {vr[0], vr[1], vr[2], vr[3]};
                *(float4*)(Cb + ix) = ov;
            } else {
#pragma unroll
                for (int j = 0; j < 4; j++) {
                    size_t ix = (size_t)(oo + j) * X + xx;
                    float v = vr[j];
                    if (resid) v += resid[(size_t)b * sC + ix];
                    Cb[ix] = v;
                }
            }
        }
    }
}

// ---------------- KNN --------------------------------------------------------
__global__ __launch_bounds__(128)
void knn_kernel(const float* __restrict__ pf,
                const float* __restrict__ seed,
                int* __restrict__ idx_out)
{
    __shared__ float sx[MM], sy[MM], sz[MM], ss[MM];
    __shared__ float sd[4][MM];
    int b = blockIdx.y;
    const float* sb = seed + (size_t)b * MM * 3;
    for (int j = threadIdx.x; j < MM; j += 128) {
        float x = sb[j*3], y = sb[j*3+1], z = sb[j*3+2];
        sx[j] = x; sy[j] = y; sz[j] = z; ss[j] = x*x + y*y + z*z;
    }
    __syncthreads();
    int w = threadIdx.x >> 5, lane = threadIdx.x & 31;
    int n = blockIdx.x * 4 + w;
    const float* q = pf + ((size_t)b * NN + n) * 3;
    float qx = q[0], qy = q[1], qz = q[2];
    float qn = qx*qx + qy*qy + qz*qz;
    float* d = sd[w];
    for (int j = lane; j < MM; j += 32)
        d[j] = qn + ss[j] - 2.f * (qx*sx[j] + qy*sy[j] + qz*sz[j]);
    __syncwarp();
    int* out = idx_out + ((size_t)b * NN + n) * KNB;
    for (int t = 0; t < KNB; t++) {
        float best = 1e30f; int bi = 0;
        for (int j = lane; j < MM; j += 32) {
            float v = d[j];
            if (v < best || (v == best && j < bi)) { best = v; bi = j; }
        }
#pragma unroll
        for (int off = 16; off; off >>= 1) {
            float ov = __shfl_xor_sync(0xffffffffu, best, off);
            int   oi = __shfl_xor_sync(0xffffffffu, bi, off);
            if (ov < best || (ov == best && oi < bi)) { best = ov; bi = oi; }
        }
        if (lane == 0) out[t] = bi;
        if (lane == (bi & 31)) d[bi] = 1e30f;
        __syncwarp();
    }
}

// ---------------- geometry -> hrelu (R,64) fp16 ------------------------------
__global__ __launch_bounds__(256)
void geom_kernel(const float* __restrict__ pos,
                 const float* __restrict__ seed,
                 const int*   __restrict__ idxg,
                 const float* __restrict__ pw1,
                 const float* __restrict__ aP, const float* __restrict__ cP,
                 __half* __restrict__ hrelu)
{
    int r = blockIdx.x * 256 + threadIdx.x;
    int b = r >> 16;
    int n = (r >> 4) & (NN - 1);
    int j = idxg[r];
    float px = pos[((size_t)b * 3 + 0) * NN + n];
    float py = pos[((size_t)b * 3 + 1) * NN + n];
    float pz = pos[((size_t)b * 3 + 2) * NN + n];
    const float* sj = seed + ((size_t)b * MM + j) * 3;
    float rx = px - sj[0], ry = py - sj[1], rz = pz - sj[2];
    float ds = sqrtf(rx*rx + ry*ry + rz*rz);
    __half2* out = (__half2*)(hrelu + (size_t)r * PHD);
#pragma unroll
    for (int p0 = 0; p0 < PHD; p0 += 2) {
        float t[2];
#pragma unroll
        for (int u = 0; u < 2; u++) {
            int p = p0 + u;
            float raw = __ldg(&pw1[p*4]) * ds + __ldg(&pw1[p*4+1]) * rx
                      + __ldg(&pw1[p*4+2]) * ry + __ldg(&pw1[p*4+3]) * rz;
            t[u] = fmaxf(raw * __ldg(&aP[p]) + __ldg(&cP[p]), 0.f);
        }
        out[p0 >> 1] = __floats2half2_rn(t[0], t[1]);
    }
}

// ---------------- launch -----------------------------------------------------
extern "C" void kernel_launch(void* const* d_in, const int* in_sizes, int n_in,
                              void* d_out, int out_size)
{
    const float* pos      = (const float*)d_in[0];
    const float* pf       = (const float*)d_in[1];
    const float* fea      = (const float*)d_in[2];
    const float* seed     = (const float*)d_in[3];
    const float* seed_fea = (const float*)d_in[4];
    const float* w_start  = (const float*)d_in[5];
    const float* b_start  = (const float*)d_in[6];
    const float* w_key    = (const float*)d_in[7];
    const float* b_key    = (const float*)d_in[8];
    const float* w_value  = (const float*)d_in[9];
    const float* b_value  = (const float*)d_in[10];
    const float* w_query  = (const float*)d_in[11];
    const float* b_query  = (const float*)d_in[12];
    const float* pos_w1   = (const float*)d_in[13];
    const float* pos_b1   = (const float*)d_in[14];
    const float* pos_g1   = (const float*)d_in[15];
    const float* pos_beta1= (const float*)d_in[16];
    const float* pos_mu1  = (const float*)d_in[17];
    const float* pos_var1 = (const float*)d_in[18];
    const float* pos_w2   = (const float*)d_in[19];
    const float* pos_b2   = (const float*)d_in[20];
    const float* attn_w1  = (const float*)d_in[21];
    const float* attn_b1  = (const float*)d_in[22];
    const float* attn_g1  = (const float*)d_in[23];
    const float* attn_beta1=(const float*)d_in[24];
    const float* attn_mu1 = (const float*)d_in[25];
    const float* attn_var1= (const float*)d_in[26];
    const float* attn_w2  = (const float*)d_in[27];
    // d_in[28] = attn_b2: cancels in softmax over K
    const float* w_end    = (const float*)d_in[29];
    const float* b_end    = (const float*)d_in[30];

    float *valueT, *keyfT, *valftT, *queryT, *aggv, *pre1;
    float *aA, *cA, *aP, *cP;
    __half *W1qt, *W1kt, *hrelu, *hid, *pre1h, *w1h, *w2h, *pw2h, *wkh, *wvh;
    int* idx;
    cudaGetSymbolAddress((void**)&valueT, g_valueT);
    cudaGetSymbolAddress((void**)&keyfT,  g_keyfT);
    cudaGetSymbolAddress((void**)&valftT, g_valftT);
    cudaGetSymbolAddress((void**)&queryT, g_queryT);
    cudaGetSymbolAddress((void**)&W1qt,   g_W1qt);
    cudaGetSymbolAddress((void**)&W1kt,   g_W1kt);
    cudaGetSymbolAddress((void**)&idx,    g_idx);
    cudaGetSymbolAddress((void**)&hrelu,  g_hrelu);
    cudaGetSymbolAddress((void**)&hid,    g_hid);
    cudaGetSymbolAddress((void**)&aggv,   g_agg);
    cudaGetSymbolAddress((void**)&pre1,   g_pre1);
    cudaGetSymbolAddress((void**)&pre1h,  g_pre1h);
    cudaGetSymbolAddress((void**)&w1h,    g_w1h);
    cudaGetSymbolAddress((void**)&w2h,    g_w2h);
    cudaGetSymbolAddress((void**)&pw2h,   g_pw2h);
    cudaGetSymbolAddress((void**)&wkh,    g_wkh);
    cudaGetSymbolAddress((void**)&wvh,    g_wvh);
    cudaGetSymbolAddress((void**)&aA,     g_aA);
    cudaGetSymbolAddress((void**)&cA,     g_cA);
    cudaGetSymbolAddress((void**)&aP,     g_aP);
    cudaGetSymbolAddress((void**)&cP,     g_cP);

    cudaFuncSetAttribute(fused_attn, cudaFuncAttributeMaxDynamicSharedMemorySize, 96256);

    precomp_kernel<<<AHD + 1, PHD>>>(attn_w1, pos_w2, pos_b2,
                                     attn_g1, attn_beta1, attn_mu1, attn_var1, attn_b1,
                                     pos_g1, pos_beta1, pos_mu1, pos_var1, pos_b1,
                                     pre1, pre1h, aA, cA, aP, cP);
    cvt_all_kernel<<<(CV5 + 255)/256, 256>>>(attn_w1, attn_w2, pos_w2, w_key, w_value,
                                             w1h, w2h, pw2h, wkh, wvh);

    // value = w_start @ seed_fea  (SIMT, channel-major A), row-major out
    gemm_k<false,true><<<dim3(MM/128, DD/128, BB), 256>>>(
        w_start, b_start, seed_fea, nullptr, valueT, DD, CC, MM,
        (size_t)CC*MM, (size_t)MM*DD);
    // key/val via fp16 mma (A = valueT fp32 row-major)
    hgemm<256,256,0,false,false><<<dim3(2, BB*MM/128), 256>>>(
        wkh, b_key, valueT, keyfT, nullptr, nullptr, nullptr, nullptr, nullptr);
    hgemm<256,256,0,false,false><<<dim3(2, BB*MM/128), 256>>>(
        wvh, b_value, valueT, valftT, nullptr, nullptr, nullptr, nullptr, nullptr);
    // query (SIMT, channel-major A)
    gemm_k<false,true><<<dim3(NN/128, DD/128, BB), 256>>>(
        w_query, b_query, fea, nullptr, queryT, DD, CC, NN,
        (size_t)CC*NN, (size_t)NN*DD);

    // W1q / W1k via fp16 mma -> fp16 outputs
    hgemm<512,256,0,false,true><<<dim3(4, BB*NN/128), 256>>>(
        w1h, nullptr, queryT, W1qt, nullptr, nullptr, nullptr, nullptr, nullptr);
    hgemm<512,256,0,false,true><<<dim3(4, BB*MM/128), 256>>>(
        w1h, nullptr, keyfT, W1kt, nullptr, nullptr, nullptr, nullptr, nullptr);

    // knn + geometry
    knn_kernel<<<dim3(NN/4, BB), 128>>>(pf, seed, idx);
    geom_kernel<<<RR/256, 256>>>(pos, seed, idx, pos_w1, aP, cP, hrelu);

    // hid = relu(aA*(pre1@hrelu + W1q - W1k) + cA)  -> fp16
    hgemm<512,64,1,true,true><<<dim3(4, RR/128), 256>>>(
        pre1h, nullptr, hrelu, hid, W1qt, W1kt, idx, aA, cA);

    // fused: pe + logits + softmax + gather + aggregate -> aggv
    fused_attn<<<dim3(2, RR/128), 256, 96256>>>(
        w2h, hid, pw2h, hrelu, pos_b2, valftT, idx, aggv);

    // out = w_end @ aggv + b_end + fea
    gemm_k<true,false><<<dim3(NN/128, CC/128, BB), 256>>>(
        w_end, b_end, aggv, fea, (float*)d_out, CC, DD, NN,
        (size_t)NN*DD, (size_t)CC*NN);
}

// round 15
// speedup vs baseline: 1.4549x; 1.0527x over previous
#include <cuda_runtime.h>
#include <cuda_fp16.h>
#include <cstdint>
#include <cstddef>

#define BB 4
#define NN 4096
#define MM 1024
#define CC 128
#define DD 256
#define PHD 64
#define AHD 512
#define KNB 16
#define RR (BB*NN*KNB)   // 262144 rows (b,n,k)

// ---------------- static scratch --------------------------------------------
__device__ float  g_valueT[BB*MM*DD];     // (B*M, D)
__device__ float  g_keyfT [BB*MM*DD];
__device__ float  g_valftT[BB*MM*DD];
__device__ float  g_queryT[BB*NN*DD];     // (B*N, D)
__device__ __half g_W1qt  [BB*NN*AHD];    // (B*N, AH) fp16
__device__ __half g_W1kt  [BB*MM*AHD];    // (B*M, AH) fp16
__device__ int    g_idx   [RR];
__device__ __half g_hrelu [16777216];     // (R, 64) fp16
__device__ float  g_agg   [BB*NN*DD];     // (B*N, 256) aggv
__device__ float  g_pre1  [AHD*PHD];
__device__ __half g_pre1h [AHD*PHD];
__device__ __half g_w1h   [AHD*DD];       // attn_w1 fp16
__device__ __half g_w2h   [DD*AHD];       // attn_w2 fp16
__device__ __half g_pw2h  [DD*PHD];       // pos_w2 fp16
__device__ __half g_wkh   [DD*DD];        // w_key fp16
__device__ __half g_wvh   [DD*DD];        // w_value fp16
__device__ float  g_aA[AHD], g_cA[AHD], g_aP[PHD], g_cP[PHD];

// ---------------- helpers ----------------------------------------------------
__device__ __forceinline__ void mma16816(float* d, const uint32_t* a,
                                         uint32_t b0, uint32_t b1) {
    asm volatile(
        "mma.sync.aligned.m16n8k16.row.col.f32.f16.f16.f32 "
        "{%0,%1,%2,%3},{%4,%5,%6,%7},{%8,%9},{%0,%1,%2,%3};"
        : "+f"(d[0]), "+f"(d[1]), "+f"(d[2]), "+f"(d[3])
        : "r"(a[0]), "r"(a[1]), "r"(a[2]), "r"(a[3]), "r"(b0), "r"(b1));
}
__device__ __forceinline__ uint32_t packh2(float x, float y) {
    __half2 h = __floats2half2_rn(x, y);
    return *(uint32_t*)&h;
}
__device__ __forceinline__ uint32_t smem_u32(const void* p) {
    uint32_t a;
    asm("{ .reg .u64 t; cvta.to.shared.u64 t, %1; cvt.u32.u64 %0, t; }"
        : "=r"(a) : "l"(p));
    return a;
}
__device__ __forceinline__ void ldsm4(uint32_t* r, uint32_t addr) {
    asm volatile("ldmatrix.sync.aligned.m8n8.x4.shared.b16 {%0,%1,%2,%3}, [%4];"
                 : "=r"(r[0]), "=r"(r[1]), "=r"(r[2]), "=r"(r[3]) : "r"(addr));
}
__device__ __forceinline__ void cp16(uint32_t dst, const void* src) {
    asm volatile("cp.async.cg.shared.global [%0], [%1], 16;"
                 :: "r"(dst), "l"(src) : "memory");
}
#define CP_COMMIT() asm volatile("cp.async.commit_group;" ::: "memory")
#define CP_WAIT(n)  asm volatile("cp.async.wait_group %0;" :: "n"(n) : "memory")

// ---------------- fp16 mma GEMM (proven): C = A(rows,K)@W(O,K)^T -------------
// BM=128, BN=128, BK=32. 256 threads = 8 warps (4M x 2N), warp tile 32x64.
template<int O, int K, bool AF16, bool OUTH>
__global__ __launch_bounds__(256)
void hgemm(const __half* __restrict__ Wh, const float* __restrict__ bias,
           const void* __restrict__ Ag, void* __restrict__ Cg)
{
    constexpr int CCH = K / 32;
    __shared__ __align__(16) __half2 As2[128][20];
    __shared__ __align__(16) __half2 Bs2[128][20];
    const int row0 = blockIdx.y * 128;
    const int o0   = blockIdx.x * 128;
    const int tid  = threadIdx.x;
    const int lane = tid & 31;
    const int wid  = tid >> 5;
    const int wm = wid & 3;
    const int wn = wid >> 2;
    const int lr = lane & 3;
    const int rsel = lane & 15;
    const int wofs = (lane >> 4) << 2;

    float acc[2][8][4];
#pragma unroll
    for (int mt = 0; mt < 2; mt++)
#pragma unroll
        for (int nt = 0; nt < 8; nt++)
#pragma unroll
            for (int q = 0; q < 4; q++) acc[mt][nt][q] = 0.f;

    uint4  ra[2], rbv[2];
    float4 fa[2][2];

    auto fetch = [&](int c) {
        if (AF16) {
            const __half* s = (const __half*)Ag +
                (size_t)(row0 + (tid >> 1)) * K + c * 32 + (tid & 1) * 16;
            ra[0] = *(const uint4*)s;
            ra[1] = *(const uint4*)(s + 8);
        } else {
#pragma unroll
            for (int i = 0; i < 2; i++) {
                int lin = tid + i * 256;
                int r = lin >> 2, cq = (lin & 3) * 4;
                const float* s = (const float*)Ag +
                    (size_t)(row0 + r) * K + c * 32 + cq * 2;
                fa[i][0] = *(const float4*)s;
                fa[i][1] = *(const float4*)(s + 4);
            }
        }
        const __half* w = Wh + (size_t)(o0 + (tid >> 1)) * K + c * 32 + (tid & 1) * 16;
        rbv[0] = *(const uint4*)w;
        rbv[1] = *(const uint4*)(w + 8);
    };
    auto store = [&]() {
        int r = tid >> 1, c0 = (tid & 1) * 8;
        if (AF16) {
            *(uint4*)&As2[r][c0]     = ra[0];
            *(uint4*)&As2[r][c0 + 4] = ra[1];
        } else {
#pragma unroll
            for (int i = 0; i < 2; i++) {
                int lin = tid + i * 256;
                int rr = lin >> 2, cq = (lin & 3) * 4;
                uint4 u;
                u.x = packh2(fa[i][0].x, fa[i][0].y);
                u.y = packh2(fa[i][0].z, fa[i][0].w);
                u.z = packh2(fa[i][1].x, fa[i][1].y);
                u.w = packh2(fa[i][1].z, fa[i][1].w);
                *(uint4*)&As2[rr][cq] = u;
            }
        }
        *(uint4*)&Bs2[r][c0]     = rbv[0];
        *(uint4*)&Bs2[r][c0 + 4] = rbv[1];
    };

    fetch(0);
#pragma unroll 1
    for (int c = 0; c < CCH; c++) {
        store();
        __syncthreads();
        if (c + 1 < CCH) fetch(c + 1);
#pragma unroll
        for (int ks = 0; ks < 2; ks++) {
            const int wsel = ks * 8 + wofs;
            uint32_t bf[8][2];
#pragma unroll
            for (int np = 0; np < 4; np++) {
                uint32_t q[4];
                ldsm4(q, smem_u32(&Bs2[wn * 64 + np * 16 + rsel][wsel]));
                bf[np*2][0]   = q[0];
                bf[np*2+1][0] = q[1];
                bf[np*2][1]   = q[2];
                bf[np*2+1][1] = q[3];
            }
#pragma unroll
            for (int mt = 0; mt < 2; mt++) {
                uint32_t a[4];
                ldsm4(a, smem_u32(&As2[wm * 32 + mt * 16 + rsel][wsel]));
#pragma unroll
                for (int nt = 0; nt < 8; nt++)
                    mma16816(acc[mt][nt], a, bf[nt][0], bf[nt][1]);
            }
        }
        __syncthreads();
    }

    const int lq = lane >> 2;
#pragma unroll
    for (int mt = 0; mt < 2; mt++) {
#pragma unroll
        for (int h = 0; h < 2; h++) {
            int r = row0 + wm * 32 + mt * 16 + h * 8 + lq;
#pragma unroll
            for (int nt = 0; nt < 8; nt++) {
                int o = o0 + wn * 64 + nt * 8 + lr * 2;
                float v0 = acc[mt][nt][h * 2 + 0];
                float v1 = acc[mt][nt][h * 2 + 1];
                if (bias) { v0 += bias[o]; v1 += bias[o + 1]; }
                if (OUTH) {
                    __half2 hv = __floats2half2_rn(v0, v1);
                    *(__half2*)((__half*)Cg + (size_t)r * O + o) = hv;
                } else {
                    *(float2*)((float*)Cg + (size_t)r * O + o) = make_float2(v0, v1);
                }
            }
        }
    }
}

// ---------------- mega: pe + hid-chunks + logits + softmax + gather + agg ----
// grid (RR/64) = 4096 CTAs, 256 thr, 2 CTAs/SM. BM=64 rows, BN=256 (full out).
// Layout (bytes): Wst [0,40960) Pst [40960,50176) Hs [50176,59392)
//                 Hc [59392,64512) sPE [64512,98304). Dynamic smem 98304.
__global__ __launch_bounds__(256, 2)
void mega_attn(const __half* __restrict__ w2h,    // (256,512)
               const __half* __restrict__ pw2h,   // (256,64)
               const __half* __restrict__ pre1h,  // (512,64)
               const __half* __restrict__ hrelu,  // (R,64)
               const __half* __restrict__ W1q,    // (B*N,512)
               const __half* __restrict__ W1k,    // (B*M,512)
               const int*   __restrict__ idxg,
               const float* __restrict__ aA, const float* __restrict__ cA,
               const float* __restrict__ pb2,
               const float* __restrict__ valft,   // (B*M,256)
               float* __restrict__ aggv)          // (B*N,256)
{
    extern __shared__ char dsm[];
    __half2 (*Wst)[256][20] = (__half2(*)[256][20])(dsm);          // 2*20480
    __half2 (*Pst)[32][36]  = (__half2(*)[32][36])(dsm + 40960);   // 2*4608
    __half2 (*Hs)[36]       = (__half2(*)[36])(dsm + 50176);       // 9216
    __half2 (*Hc)[20]       = (__half2(*)[20])(dsm + 59392);       // 5120
    __half2 (*sPE)[132]     = (__half2(*)[132])(dsm + 64512);      // 33792
    __half2 (*Pw)[36]       = (__half2(*)[36])(dsm);               // alias (pe phase)
    __shared__ int sidx[64];
    const uint32_t sW = smem_u32(dsm);
    const uint32_t sP = sW + 40960;
    const int row0 = blockIdx.x * 64;
    const int tid  = threadIdx.x;
    const int lane = tid & 31;
    const int wid  = tid >> 5;
    const int lq = lane >> 2;
    const int lr = lane & 3;
    const int rsel = lane & 15;
    const int wofs = (lane >> 4) << 2;
    const int wm2 = wid & 3;       // hid sub-GEMM M group
    const int wn2 = wid >> 2;      // hid sub-GEMM N group
    const int bb = row0 >> 16;

    if (tid < 64) sidx[tid] = idxg[row0 + tid];
    // load hrelu tile (64x64 halves) and pw2h (256x64) into alias area
    {
        int r = tid >> 2, q = tid & 3;
        const __half* s = hrelu + (size_t)(row0 + r) * PHD + q * 16;
        *(uint4*)&Hs[r][q * 8]     = *(const uint4*)s;
        *(uint4*)&Hs[r][q * 8 + 4] = *(const uint4*)(s + 8);
#pragma unroll
        for (int i = 0; i < 8; i++) {
            int lin = tid + i * 256;
            int rr = lin >> 3, qq = lin & 7;
            *(uint4*)&Pw[rr][qq * 4] = *(const uint4*)(pw2h + (size_t)rr * PHD + qq * 8);
        }
    }
    __syncthreads();

    // ---- pe phase: pe = Hs @ pw2h^T (warp cols wid*32..+32) -> sPE ----
    {
        float acc2[4][4][4];
#pragma unroll
        for (int mt = 0; mt < 4; mt++)
#pragma unroll
            for (int nt = 0; nt < 4; nt++)
#pragma unroll
                for (int q = 0; q < 4; q++) acc2[mt][nt][q] = 0.f;
#pragma unroll
        for (int kk = 0; kk < 4; kk++) {
            const int wsel = kk * 8 + wofs;
            uint32_t bf[4][2];
#pragma unroll
            for (int np = 0; np < 2; np++) {
                uint32_t q4[4];
                ldsm4(q4, smem_u32(&Pw[wid * 32 + np * 16 + rsel][wsel]));
                bf[np*2][0]   = q4[0];
                bf[np*2+1][0] = q4[1];
                bf[np*2][1]   = q4[2];
                bf[np*2+1][1] = q4[3];
            }
#pragma unroll
            for (int mt = 0; mt < 4; mt++) {
                uint32_t a[4];
                ldsm4(a, smem_u32(&Hs[mt * 16 + rsel][wsel]));
#pragma unroll
                for (int nt = 0; nt < 4; nt++)
                    mma16816(acc2[mt][nt], a, bf[nt][0], bf[nt][1]);
            }
        }
#pragma unroll
        for (int mt = 0; mt < 4; mt++)
#pragma unroll
            for (int nt = 0; nt < 4; nt++) {
                int c = wid * 32 + nt * 8 + lr * 2;
                float2 pbv = *(const float2*)(pb2 + c);
                sPE[mt*16 + lq][wid*16 + nt*4 + lr] =
                    __floats2half2_rn(acc2[mt][nt][0] + pbv.x, acc2[mt][nt][1] + pbv.y);
                sPE[mt*16 + 8 + lq][wid*16 + nt*4 + lr] =
                    __floats2half2_rn(acc2[mt][nt][2] + pbv.x, acc2[mt][nt][3] + pbv.y);
            }
    }
    __syncthreads();   // release alias area before w2h staging

    // ---- main loop: per 32-wide AH chunk: hid chunk -> logits mma ----
    auto fetchW = [&](int c, int buf) {
#pragma unroll
        for (int i = 0; i < 4; i++) {
            int lin = tid + i * 256;
            int r = lin >> 2, q = lin & 3;
            cp16(sW + (uint32_t)buf * 20480 + (uint32_t)r * 80 + q * 16,
                 w2h + (size_t)r * AHD + c * 32 + q * 8);
        }
    };
    auto fetchP = [&](int c, int buf) {
        int r = tid >> 3, q = tid & 7;    // 32 rows x 8 x 16B = full 128B rows
        cp16(sP + (uint32_t)buf * 4608 + (uint32_t)r * 144 + q * 16,
             pre1h + (size_t)(c * 32 + r) * PHD + q * 8);
    };

    float acc1[4][4][4];
#pragma unroll
    for (int mt = 0; mt < 4; mt++)
#pragma unroll
        for (int nt = 0; nt < 4; nt++)
#pragma unroll
            for (int q = 0; q < 4; q++) acc1[mt][nt][q] = 0.f;

    fetchW(0, 0);
    fetchP(0, 0);
    CP_COMMIT();
#pragma unroll 1
    for (int c = 0; c < AHD / 32; c++) {
        CP_WAIT(0);
        __syncthreads();
        if (c + 1 < AHD / 32) {
            fetchW(c + 1, (c + 1) & 1);
            fetchP(c + 1, (c + 1) & 1);
        }
        CP_COMMIT();
        // hid sub-GEMM: rows wm2*16..+16, ah cols wn2*16..+16, K=64 (from Hs)
        float ha[2][4];
#pragma unroll
        for (int n2 = 0; n2 < 2; n2++)
#pragma unroll
            for (int q = 0; q < 4; q++) ha[n2][q] = 0.f;
#pragma unroll
        for (int kk = 0; kk < 4; kk++) {
            const int wsel = kk * 8 + wofs;
            uint32_t a[4], q4[4];
            ldsm4(a, smem_u32(&Hs[wm2 * 16 + rsel][wsel]));
            ldsm4(q4, smem_u32(&Pst[c & 1][wn2 * 16 + rsel][wsel]));
            mma16816(ha[0], a, q4[0], q4[2]);
            mma16816(ha[1], a, q4[1], q4[3]);
        }
        // epilogue: gather W1q/W1k + BN + relu -> Hc
#pragma unroll
        for (int h = 0; h < 2; h++) {
            int r = wm2 * 16 + h * 8 + lq;
            int gp = (row0 + r) >> 4;
            int j = sidx[r];
            const __half* qp = W1q + (size_t)gp * AHD;
            const __half* kp = W1k + ((size_t)bb * MM + j) * AHD;
#pragma unroll
            for (int n2 = 0; n2 < 2; n2++) {
                int ah = c * 32 + wn2 * 16 + n2 * 8 + lr * 2;
                float2 qv = __half22float2(*(const __half2*)(qp + ah));
                float2 kv = __half22float2(*(const __half2*)(kp + ah));
                float2 av = *(const float2*)(aA + ah);
                float2 cv = *(const float2*)(cA + ah);
                float v0 = fmaxf((ha[n2][h*2+0] + qv.x - kv.x) * av.x + cv.x, 0.f);
                float v1 = fmaxf((ha[n2][h*2+1] + qv.y - kv.y) * av.y + cv.y, 0.f);
                Hc[r][wn2 * 8 + n2 * 4 + lr] = __floats2half2_rn(v0, v1);
            }
        }
        __syncthreads();
        // logits mma: warp cols wid*32..+32; A = Hc, B = Wst[c&1]
#pragma unroll
        for (int ks = 0; ks < 2; ks++) {
            const int wsel = ks * 8 + wofs;
            uint32_t bf[4][2];
#pragma unroll
            for (int np = 0; np < 2; np++) {
                uint32_t q4[4];
                ldsm4(q4, smem_u32(&Wst[c & 1][wid * 32 + np * 16 + rsel][wsel]));
                bf[np*2][0]   = q4[0];
                bf[np*2+1][0] = q4[1];
                bf[np*2][1]   = q4[2];
                bf[np*2+1][1] = q4[3];
            }
#pragma unroll
            for (int mt = 0; mt < 4; mt++) {
                uint32_t a[4];
                ldsm4(a, smem_u32(&Hc[mt * 16 + rsel][wsel]));
#pragma unroll
                for (int nt = 0; nt < 4; nt++)
                    mma16816(acc1[mt][nt], a, bf[nt][0], bf[nt][1]);
            }
        }
    }

    // ---- softmax over k (16 rows per point, within warp) + gather + agg ----
#pragma unroll
    for (int mt = 0; mt < 4; mt++) {
        const int pt = (row0 + mt * 16) >> 4;
        const int j0 = sidx[mt * 16 + lq];
        const int j1 = sidx[mt * 16 + 8 + lq];
        const float* v0b = valft + ((size_t)bb * MM + j0) * DD;
        const float* v1b = valft + ((size_t)bb * MM + j1) * DD;
#pragma unroll
        for (int nt = 0; nt < 4; nt++) {
            const int c = wid * 32 + nt * 8 + lr * 2;
            float2 vv0 = *(const float2*)(v0b + c);
            float2 vv1 = *(const float2*)(v1b + c);
            float2 p0 = __half22float2(sPE[mt*16 + lq][wid*16 + nt*4 + lr]);
            float2 p1 = __half22float2(sPE[mt*16 + 8 + lq][wid*16 + nt*4 + lr]);
            float outc[2];
#pragma unroll
            for (int j = 0; j < 2; j++) {
                float l0 = acc1[mt][nt][j];
                float l1 = acc1[mt][nt][2 + j];
                float m = fmaxf(l0, l1);
                m = fmaxf(m, __shfl_xor_sync(0xffffffffu, m, 4));
                m = fmaxf(m, __shfl_xor_sync(0xffffffffu, m, 8));
                m = fmaxf(m, __shfl_xor_sync(0xffffffffu, m, 16));
                float e0 = __expf(l0 - m), e1 = __expf(l1 - m);
                float S = e0 + e1;
                S += __shfl_xor_sync(0xffffffffu, S, 4);
                S += __shfl_xor_sync(0xffffffffu, S, 8);
                S += __shfl_xor_sync(0xffffffffu, S, 16);
                float pe0 = j ? p0.y : p0.x;
                float pe1 = j ? p1.y : p1.x;
                float va0 = j ? vv0.y : vv0.x;
                float va1 = j ? vv1.y : vv1.x;
                float T = e0 * (va0 + pe0) + e1 * (va1 + pe1);
                T += __shfl_xor_sync(0xffffffffu, T, 4);
                T += __shfl_xor_sync(0xffffffffu, T, 8);
                T += __shfl_xor_sync(0xffffffffu, T, 16);
                outc[j] = T / S;
            }
            if (lq == 0)
                *(float2*)(aggv + (size_t)pt * DD + c) = make_float2(outc[0], outc[1]);
        }
    }
}

// ---------------- precompute + weight conversions ----------------------------
__global__ void precomp_kernel(const float* __restrict__ w1,
                               const float* __restrict__ pw2,
                               const float* __restrict__ pb2,
                               const float* __restrict__ ag, const float* __restrict__ abeta,
                               const float* __restrict__ amu, const float* __restrict__ avar,
                               const float* __restrict__ ab1,
                               const float* __restrict__ pg, const float* __restrict__ pbeta,
                               const float* __restrict__ pmu, const float* __restrict__ pvar,
                               const float* __restrict__ pb1,
                               float* __restrict__ pre1, __half* __restrict__ pre1h,
                               float* __restrict__ aA,
                               float* __restrict__ cA, float* __restrict__ aP,
                               float* __restrict__ cP)
{
    int o = blockIdx.x;
    if (o < AHD) {
        int p = threadIdx.x;
        float s = 0.f;
        for (int c = 0; c < DD; c++) s += w1[o*DD + c] * pw2[c*PHD + p];
        pre1[o*PHD + p] = s;
        pre1h[o*PHD + p] = __float2half_rn(s);
        if (p == 0) {
            float vb = 0.f;
            for (int c = 0; c < DD; c++) vb += w1[o*DD + c] * pb2[c];
            float inv = ag[o] / sqrtf(avar[o] + 1e-5f);
            aA[o] = inv;
            cA[o] = (ab1[o] - amu[o]) * inv + abeta[o] + vb * inv;
        }
    } else {
        int p = threadIdx.x;
        float inv = pg[p] / sqrtf(pvar[p] + 1e-5f);
        aP[p] = inv;
        cP[p] = (pb1[p] - pmu[p]) * inv + pbeta[p];
    }
}

#define CV1 (AHD*DD)
#define CV2 (CV1 + DD*AHD)
#define CV3 (CV2 + DD*PHD)
#define CV4 (CV3 + DD*DD)
#define CV5 (CV4 + DD*DD)
__global__ void cvt_all_kernel(const float* __restrict__ w1, const float* __restrict__ w2,
                               const float* __restrict__ pw2, const float* __restrict__ wk,
                               const float* __restrict__ wv,
                               __half* __restrict__ w1h, __half* __restrict__ w2h,
                               __half* __restrict__ pw2h, __half* __restrict__ wkh,
                               __half* __restrict__ wvh)
{
    int i = blockIdx.x * 256 + threadIdx.x;
    if (i < CV1)      w1h [i]       = __float2half_rn(w1 [i]);
    else if (i < CV2) w2h [i - CV1] = __float2half_rn(w2 [i - CV1]);
    else if (i < CV3) pw2h[i - CV2] = __float2half_rn(pw2[i - CV2]);
    else if (i < CV4) wkh [i - CV3] = __float2half_rn(wk [i - CV3]);
    else if (i < CV5) wvh [i - CV4] = __float2half_rn(wv [i - CV4]);
}

// ---------------- SIMT fp32 GEMM (small front/end GEMMs) ---------------------
constexpr int TBO = 128, TBX = 128, TBK = 16;

template<bool A_RM, bool OUT_XO>
__global__ __launch_bounds__(256)
void gemm_k(const float* __restrict__ W, const float* __restrict__ bias,
            const float* __restrict__ A, const float* __restrict__ resid,
            float* __restrict__ C, int O, int K, int X, size_t sA, size_t sC)
{
    __shared__ float As[TBK][TBX];
    __shared__ float Ws[TBK][TBO];
    const int bx = blockIdx.x * TBX;
    const int bo = blockIdx.y * TBO;
    const int b  = blockIdx.z;
    const float* Ab = A + (size_t)b * sA;
    float* Cb = C + (size_t)b * sC;
    const int tid = threadIdx.x;
    const int tco = (tid & 15) * 4;
    const int tcx = (tid >> 4) * 4;

    float acc[8][8];
#pragma unroll
    for (int i = 0; i < 8; i++)
#pragma unroll
        for (int j = 0; j < 8; j++) acc[i][j] = 0.f;

    for (int k0 = 0; k0 < K; k0 += TBK) {
        if (A_RM) {
            int row = tid >> 1, c0 = (tid & 1) * 8;
            const float* p = Ab + (size_t)(bx + row) * K + k0 + c0;
            float4 v0 = *(const float4*)p;
            float4 v1 = *(const float4*)(p + 4);
            As[c0+0][row] = v0.x; As[c0+1][row] = v0.y;
            As[c0+2][row] = v0.z; As[c0+3][row] = v0.w;
            As[c0+4][row] = v1.x; As[c0+5][row] = v1.y;
            As[c0+6][row] = v1.z; As[c0+7][row] = v1.w;
        } else {
            int kk = tid >> 4, x8 = (tid & 15) * 8;
            const float* p = Ab + (size_t)(k0 + kk) * X + bx + x8;
            float4 v0 = *(const float4*)p;
            float4 v1 = *(const float4*)(p + 4);
            *(float4*)&As[kk][x8]     = v0;
            *(float4*)&As[kk][x8 + 4] = v1;
        }
        {
            int row = tid >> 1, c0 = (tid & 1) * 8;
            const float* p = W + (size_t)(bo + row) * K + k0 + c0;
            float4 v0 = *(const float4*)p;
            float4 v1 = *(const float4*)(p + 4);
            Ws[c0+0][row] = v0.x; Ws[c0+1][row] = v0.y;
            Ws[c0+2][row] = v0.z; Ws[c0+3][row] = v0.w;
            Ws[c0+4][row] = v1.x; Ws[c0+5][row] = v1.y;
            Ws[c0+6][row] = v1.z; Ws[c0+7][row] = v1.w;
        }
        __syncthreads();
#pragma unroll
        for (int kk = 0; kk < TBK; kk++) {
            float4 a0 = *(const float4*)&As[kk][tcx];
            float4 a1 = *(const float4*)&As[kk][tcx + 64];
            float4 w0 = *(const float4*)&Ws[kk][tco];
            float4 w1 = *(const float4*)&Ws[kk][tco + 64];
            float a[8] = {a0.x, a0.y, a0.z, a0.w, a1.x, a1.y, a1.z, a1.w};
            float w[8] = {w0.x, w0.y, w0.z, w0.w, w1.x, w1.y, w1.z, w1.w};
#pragma unroll
            for (int i = 0; i < 8; i++)
#pragma unroll
                for (int j = 0; j < 8; j++)
                    acc[i][j] = fmaf(a[i], w[j], acc[i][j]);
        }
        __syncthreads();
    }
#pragma unroll
    for (int i = 0; i < 8; i++) {
        int xx = bx + (i < 4 ? tcx + i : 64 + tcx + (i - 4));
#pragma unroll
        for (int jh = 0; jh < 2; jh++) {
            int oo = bo + tco + jh * 64;
            float vr[4];
#pragma unroll
            for (int j = 0; j < 4; j++) vr[j] = acc[i][jh * 4 + j];
            if (bias) {
#pragma unroll
                for (int j = 0; j < 4; j++) vr[j] += bias[oo + j];
            }
            if (OUT_XO) {
                size_t ix = (size_t)xx * O + oo;
                if (resid) {
                    float4 rv = *(const float4*)(resid + (size_t)b * sC + ix);
                    vr[0] += rv.x; vr[1] += rv.y; vr[2] += rv.z; vr[3] += rv.w;
                }
                float4 ov = {vr[0], vr[1], vr[2], vr[3]};
                *(float4*)(Cb + ix) = ov;
            } else {
#pragma unroll
                for (int j = 0; j < 4; j++) {
                    size_t ix = (size_t)(oo + j) * X + xx;
                    float v = vr[j];
                    if (resid) v += resid[(size_t)b * sC + ix];
                    Cb[ix] = v;
                }
            }
        }
    }
}

// ---------------- KNN --------------------------------------------------------
__global__ __launch_bounds__(128)
void knn_kernel(const float* __restrict__ pf,
                const float* __restrict__ seed,
                int* __restrict__ idx_out)
{
    __shared__ float sx[MM], sy[MM], sz[MM], ss[MM];
    __shared__ float sd[4][MM];
    int b = blockIdx.y;
    const float* sb = seed + (size_t)b * MM * 3;
    for (int j = threadIdx.x; j < MM; j += 128) {
        float x = sb[j*3], y = sb[j*3+1], z = sb[j*3+2];
        sx[j] = x; sy[j] = y; sz[j] = z; ss[j] = x*x + y*y + z*z;
    }
    __syncthreads();
    int w = threadIdx.x >> 5, lane = threadIdx.x & 31;
    int n = blockIdx.x * 4 + w;
    const float* q = pf + ((size_t)b * NN + n) * 3;
    float qx = q[0], qy = q[1], qz = q[2];
    float qn = qx*qx + qy*qy + qz*qz;
    float* d = sd[w];
    for (int j = lane; j < MM; j += 32)
        d[j] = qn + ss[j] - 2.f * (qx*sx[j] + qy*sy[j] + qz*sz[j]);
    __syncwarp();
    int* out = idx_out + ((size_t)b * NN + n) * KNB;
    for (int t = 0; t < KNB; t++) {
        float best = 1e30f; int bi = 0;
        for (int j = lane; j < MM; j += 32) {
            float v = d[j];
            if (v < best || (v == best && j < bi)) { best = v; bi = j; }
        }
#pragma unroll
        for (int off = 16; off; off >>= 1) {
            float ov = __shfl_xor_sync(0xffffffffu, best, off);
            int   oi = __shfl_xor_sync(0xffffffffu, bi, off);
            if (ov < best || (ov == best && oi < bi)) { best = ov; bi = oi; }
        }
        if (lane == 0) out[t] = bi;
        if (lane == (bi & 31)) d[bi] = 1e30f;
        __syncwarp();
    }
}

// ---------------- geometry -> hrelu (R,64) fp16 ------------------------------
__global__ __launch_bounds__(256)
void geom_kernel(const float* __restrict__ pos,
                 const float* __restrict__ seed,
                 const int*   __restrict__ idxg,
                 const float* __restrict__ pw1,
                 const float* __restrict__ aP, const float* __restrict__ cP,
                 __half* __restrict__ hrelu)
{
    int r = blockIdx.x * 256 + threadIdx.x;
    int b = r >> 16;
    int n = (r >> 4) & (NN - 1);
    int j = idxg[r];
    float px = pos[((size_t)b * 3 + 0) * NN + n];
    float py = pos[((size_t)b * 3 + 1) * NN + n];
    float pz = pos[((size_t)b * 3 + 2) * NN + n];
    const float* sj = seed + ((size_t)b * MM + j) * 3;
    float rx = px - sj[0], ry = py - sj[1], rz = pz - sj[2];
    float ds = sqrtf(rx*rx + ry*ry + rz*rz);
    __half2* out = (__half2*)(hrelu + (size_t)r * PHD);
#pragma unroll
    for (int p0 = 0; p0 < PHD; p0 += 2) {
        float t[2];
#pragma unroll
        for (int u = 0; u < 2; u++) {
            int p = p0 + u;
            float raw = __ldg(&pw1[p*4]) * ds + __ldg(&pw1[p*4+1]) * rx
                      + __ldg(&pw1[p*4+2]) * ry + __ldg(&pw1[p*4+3]) * rz;
            t[u] = fmaxf(raw * __ldg(&aP[p]) + __ldg(&cP[p]), 0.f);
        }
        out[p0 >> 1] = __floats2half2_rn(t[0], t[1]);
    }
}

// ---------------- launch -----------------------------------------------------
extern "C" void kernel_launch(void* const* d_in, const int* in_sizes, int n_in,
                              void* d_out, int out_size)
{
    const float* pos      = (const float*)d_in[0];
    const float* pf       = (const float*)d_in[1];
    const float* fea      = (const float*)d_in[2];
    const float* seed     = (const float*)d_in[3];
    const float* seed_fea = (const float*)d_in[4];
    const float* w_start  = (const float*)d_in[5];
    const float* b_start  = (const float*)d_in[6];
    const float* w_key    = (const float*)d_in[7];
    const float* b_key    = (const float*)d_in[8];
    const float* w_value  = (const float*)d_in[9];
    const float* b_value  = (const float*)d_in[10];
    const float* w_query  = (const float*)d_in[11];
    const float* b_query  = (const float*)d_in[12];
    const float* pos_w1   = (const float*)d_in[13];
    const float* pos_b1   = (const float*)d_in[14];
    const float* pos_g1   = (const float*)d_in[15];
    const float* pos_beta1= (const float*)d_in[16];
    const float* pos_mu1  = (const float*)d_in[17];
    const float* pos_var1 = (const float*)d_in[18];
    const float* pos_w2   = (const float*)d_in[19];
    const float* pos_b2   = (const float*)d_in[20];
    const float* attn_w1  = (const float*)d_in[21];
    const float* attn_b1  = (const float*)d_in[22];
    const float* attn_g1  = (const float*)d_in[23];
    const float* attn_beta1=(const float*)d_in[24];
    const float* attn_mu1 = (const float*)d_in[25];
    const float* attn_var1= (const float*)d_in[26];
    const float* attn_w2  = (const float*)d_in[27];
    // d_in[28] = attn_b2: cancels in softmax over K
    const float* w_end    = (const float*)d_in[29];
    const float* b_end    = (const float*)d_in[30];

    float *valueT, *keyfT, *valftT, *queryT, *aggv, *pre1;
    float *aA, *cA, *aP, *cP;
    __half *W1qt, *W1kt, *hrelu, *pre1h, *w1h, *w2h, *pw2h, *wkh, *wvh;
    int* idx;
    cudaGetSymbolAddress((void**)&valueT, g_valueT);
    cudaGetSymbolAddress((void**)&keyfT,  g_keyfT);
    cudaGetSymbolAddress((void**)&valftT, g_valftT);
    cudaGetSymbolAddress((void**)&queryT, g_queryT);
    cudaGetSymbolAddress((void**)&W1qt,   g_W1qt);
    cudaGetSymbolAddress((void**)&W1kt,   g_W1kt);
    cudaGetSymbolAddress((void**)&idx,    g_idx);
    cudaGetSymbolAddress((void**)&hrelu,  g_hrelu);
    cudaGetSymbolAddress((void**)&aggv,   g_agg);
    cudaGetSymbolAddress((void**)&pre1,   g_pre1);
    cudaGetSymbolAddress((void**)&pre1h,  g_pre1h);
    cudaGetSymbolAddress((void**)&w1h,    g_w1h);
    cudaGetSymbolAddress((void**)&w2h,    g_w2h);
    cudaGetSymbolAddress((void**)&pw2h,   g_pw2h);
    cudaGetSymbolAddress((void**)&wkh,    g_wkh);
    cudaGetSymbolAddress((void**)&wvh,    g_wvh);
    cudaGetSymbolAddress((void**)&aA,     g_aA);
    cudaGetSymbolAddress((void**)&cA,     g_cA);
    cudaGetSymbolAddress((void**)&aP,     g_aP);
    cudaGetSymbolAddress((void**)&cP,     g_cP);

    cudaFuncSetAttribute(mega_attn, cudaFuncAttributeMaxDynamicSharedMemorySize, 98304);

    precomp_kernel<<<AHD + 1, PHD>>>(attn_w1, pos_w2, pos_b2,
                                     attn_g1, attn_beta1, attn_mu1, attn_var1, attn_b1,
                                     pos_g1, pos_beta1, pos_mu1, pos_var1, pos_b1,
                                     pre1, pre1h, aA, cA, aP, cP);
    cvt_all_kernel<<<(CV5 + 255)/256, 256>>>(attn_w1, attn_w2, pos_w2, w_key, w_value,
                                             w1h, w2h, pw2h, wkh, wvh);

    // value = w_start @ seed_fea  (SIMT, channel-major A), row-major out
    gemm_k<false,true><<<dim3(MM/128, DD/128, BB), 256>>>(
        w_start, b_start, seed_fea, nullptr, valueT, DD, CC, MM,
        (size_t)CC*MM, (size_t)MM*DD);
    // key/val via fp16 mma (A = valueT fp32 row-major)
    hgemm<256,256,false,false><<<dim3(2, BB*MM/128), 256>>>(
        wkh, b_key, valueT, keyfT);
    hgemm<256,256,false,false><<<dim3(2, BB*MM/128), 256>>>(
        wvh, b_value, valueT, valftT);
    // query (SIMT, channel-major A)
    gemm_k<false,true><<<dim3(NN/128, DD/128, BB), 256>>>(
        w_query, b_query, fea, nullptr, queryT, DD, CC, NN,
        (size_t)CC*NN, (size_t)NN*DD);

    // W1q / W1k via fp16 mma -> fp16 outputs
    hgemm<512,256,false,true><<<dim3(4, BB*NN/128), 256>>>(
        w1h, nullptr, queryT, W1qt);
    hgemm<512,256,false,true><<<dim3(4, BB*MM/128), 256>>>(
        w1h, nullptr, keyfT, W1kt);

    // knn + geometry
    knn_kernel<<<dim3(NN/4, BB), 128>>>(pf, seed, idx);
    geom_kernel<<<RR/256, 256>>>(pos, seed, idx, pos_w1, aP, cP, hrelu);

    // mega: pe + hid chunks + logits + softmax + gather + aggregate -> aggv
    mega_attn<<<RR/64, 256, 98304>>>(
        w2h, pw2h, pre1h, hrelu, W1qt, W1kt, idx, aA, cA, pos_b2, valftT, aggv);

    // out = w_end @ aggv + b_end + fea
    gemm_k<true,false><<<dim3(NN/128, CC/128, BB), 256>>>(
        w_end, b_end, aggv, fea, (float*)d_out, CC, DD, NN,
        (size_t)NN*DD, (size_t)CC*NN);
}

// round 17
// speedup vs baseline: 1.4656x; 1.0073x over previous
#include <cuda_runtime.h>
#include <cuda_fp16.h>
#include <cstdint>
#include <cstddef>

#define BB 4
#define NN 4096
#define MM 1024
#define CC 128
#define DD 256
#define PHD 64
#define AHD 512
#define KNB 16
#define RR (BB*NN*KNB)   // 262144 rows (b,n,k)

// ---------------- static scratch --------------------------------------------
__device__ float  g_valueT[BB*MM*DD];     // (B*M, D)
__device__ float  g_valftT[BB*MM*DD];
__device__ float  g_queryT[BB*NN*DD];     // (B*N, D)
__device__ __half g_W1qt  [BB*NN*AHD];    // (B*N, AH) fp16
__device__ __half g_W1kt  [BB*MM*AHD];    // (B*M, AH) fp16
__device__ int    g_idx   [RR];
__device__ __half g_hrelu [16777216];     // (R, 64) fp16
__device__ float  g_agg   [BB*NN*DD];     // (B*N, 256) aggv
__device__ float  g_pre1  [AHD*PHD];
__device__ __half g_pre1h [AHD*PHD];
__device__ __half g_w1h   [AHD*DD];       // attn_w1 fp16
__device__ __half g_w2h   [DD*AHD];       // attn_w2 fp16
__device__ __half g_pw2h  [DD*PHD];       // pos_w2 fp16
__device__ __half g_wvh   [DD*DD];        // w_value fp16
__device__ __half g_W1Kh  [AHD*DD];       // attn_w1 @ w_key, fp16 (512,256)
__device__ float  g_vbk   [AHD];          // attn_w1 @ b_key
__device__ float  g_aA[AHD], g_cA[AHD], g_aP[PHD], g_cP[PHD];

// ---------------- helpers ----------------------------------------------------
__device__ __forceinline__ void mma16816(float* d, const uint32_t* a,
                                         uint32_t b0, uint32_t b1) {
    asm volatile(
        "mma.sync.aligned.m16n8k16.row.col.f32.f16.f16.f32 "
        "{%0,%1,%2,%3},{%4,%5,%6,%7},{%8,%9},{%0,%1,%2,%3};"
        : "+f"(d[0]), "+f"(d[1]), "+f"(d[2]), "+f"(d[3])
        : "r"(a[0]), "r"(a[1]), "r"(a[2]), "r"(a[3]), "r"(b0), "r"(b1));
}
__device__ __forceinline__ uint32_t packh2(float x, float y) {
    __half2 h = __floats2half2_rn(x, y);
    return *(uint32_t*)&h;
}
__device__ __forceinline__ uint32_t smem_u32(const void* p) {
    uint32_t a;
    asm("{ .reg .u64 t; cvta.to.shared.u64 t, %1; cvt.u32.u64 %0, t; }"
        : "=r"(a) : "l"(p));
    return a;
}
__device__ __forceinline__ void ldsm4(uint32_t* r, uint32_t addr) {
    asm volatile("ldmatrix.sync.aligned.m8n8.x4.shared.b16 {%0,%1,%2,%3}, [%4];"
                 : "=r"(r[0]), "=r"(r[1]), "=r"(r[2]), "=r"(r[3]) : "r"(addr));
}
__device__ __forceinline__ void cp16(uint32_t dst, const void* src) {
    asm volatile("cp.async.cg.shared.global [%0], [%1], 16;"
                 :: "r"(dst), "l"(src) : "memory");
}
#define CP_COMMIT() asm volatile("cp.async.commit_group;" ::: "memory")
#define CP_WAIT(n)  asm volatile("cp.async.wait_group %0;" :: "n"(n) : "memory")

// ---------------- fp16 mma GEMM (proven): C = A(rows,K)@W(O,K)^T -------------
// BM=128, BN=128, BK=32. 256 threads = 8 warps (4M x 2N), warp tile 32x64.
template<int O, int K, bool AF16, bool OUTH>
__global__ __launch_bounds__(256)
void hgemm(const __half* __restrict__ Wh, const float* __restrict__ bias,
           const void* __restrict__ Ag, void* __restrict__ Cg)
{
    constexpr int CCH = K / 32;
    __shared__ __align__(16) __half2 As2[128][20];
    __shared__ __align__(16) __half2 Bs2[128][20];
    const int row0 = blockIdx.y * 128;
    const int o0   = blockIdx.x * 128;
    const int tid  = threadIdx.x;
    const int lane = tid & 31;
    const int wid  = tid >> 5;
    const int wm = wid & 3;
    const int wn = wid >> 2;
    const int lr = lane & 3;
    const int rsel = lane & 15;
    const int wofs = (lane >> 4) << 2;

    float acc[2][8][4];
#pragma unroll
    for (int mt = 0; mt < 2; mt++)
#pragma unroll
        for (int nt = 0; nt < 8; nt++)
#pragma unroll
            for (int q = 0; q < 4; q++) acc[mt][nt][q] = 0.f;

    uint4  ra[2], rbv[2];
    float4 fa[2][2];

    auto fetch = [&](int c) {
        if (AF16) {
            const __half* s = (const __half*)Ag +
                (size_t)(row0 + (tid >> 1)) * K + c * 32 + (tid & 1) * 16;
            ra[0] = *(const uint4*)s;
            ra[1] = *(const uint4*)(s + 8);
        } else {
#pragma unroll
            for (int i = 0; i < 2; i++) {
                int lin = tid + i * 256;
                int r = lin >> 2, cq = (lin & 3) * 4;
                const float* s = (const float*)Ag +
                    (size_t)(row0 + r) * K + c * 32 + cq * 2;
                fa[i][0] = *(const float4*)s;
                fa[i][1] = *(const float4*)(s + 4);
            }
        }
        const __half* w = Wh + (size_t)(o0 + (tid >> 1)) * K + c * 32 + (tid & 1) * 16;
        rbv[0] = *(const uint4*)w;
        rbv[1] = *(const uint4*)(w + 8);
    };
    auto store = [&]() {
        int r = tid >> 1, c0 = (tid & 1) * 8;
        if (AF16) {
            *(uint4*)&As2[r][c0]     = ra[0];
            *(uint4*)&As2[r][c0 + 4] = ra[1];
        } else {
#pragma unroll
            for (int i = 0; i < 2; i++) {
                int lin = tid + i * 256;
                int rr = lin >> 2, cq = (lin & 3) * 4;
                uint4 u;
                u.x = packh2(fa[i][0].x, fa[i][0].y);
                u.y = packh2(fa[i][0].z, fa[i][0].w);
                u.z = packh2(fa[i][1].x, fa[i][1].y);
                u.w = packh2(fa[i][1].z, fa[i][1].w);
                *(uint4*)&As2[rr][cq] = u;
            }
        }
        *(uint4*)&Bs2[r][c0]     = rbv[0];
        *(uint4*)&Bs2[r][c0 + 4] = rbv[1];
    };

    fetch(0);
#pragma unroll 1
    for (int c = 0; c < CCH; c++) {
        store();
        __syncthreads();
        if (c + 1 < CCH) fetch(c + 1);
#pragma unroll
        for (int ks = 0; ks < 2; ks++) {
            const int wsel = ks * 8 + wofs;
            uint32_t bf[8][2];
#pragma unroll
            for (int np = 0; np < 4; np++) {
                uint32_t q[4];
                ldsm4(q, smem_u32(&Bs2[wn * 64 + np * 16 + rsel][wsel]));
                bf[np*2][0]   = q[0];
                bf[np*2+1][0] = q[1];
                bf[np*2][1]   = q[2];
                bf[np*2+1][1] = q[3];
            }
#pragma unroll
            for (int mt = 0; mt < 2; mt++) {
                uint32_t a[4];
                ldsm4(a, smem_u32(&As2[wm * 32 + mt * 16 + rsel][wsel]));
#pragma unroll
                for (int nt = 0; nt < 8; nt++)
                    mma16816(acc[mt][nt], a, bf[nt][0], bf[nt][1]);
            }
        }
        __syncthreads();
    }

    const int lq = lane >> 2;
#pragma unroll
    for (int mt = 0; mt < 2; mt++) {
#pragma unroll
        for (int h = 0; h < 2; h++) {
            int r = row0 + wm * 32 + mt * 16 + h * 8 + lq;
#pragma unroll
            for (int nt = 0; nt < 8; nt++) {
                int o = o0 + wn * 64 + nt * 8 + lr * 2;
                float v0 = acc[mt][nt][h * 2 + 0];
                float v1 = acc[mt][nt][h * 2 + 1];
                if (bias) { v0 += bias[o]; v1 += bias[o + 1]; }
                if (OUTH) {
                    __half2 hv = __floats2half2_rn(v0, v1);
                    *(__half2*)((__half*)Cg + (size_t)r * O + o) = hv;
                } else {
                    *(float2*)((float*)Cg + (size_t)r * O + o) = make_float2(v0, v1);
                }
            }
        }
    }
}

// ---------------- mega: pe + hid-chunks + logits + softmax + gather + agg ----
// grid (RR/64) = 4096 CTAs, 256 thr, 2 CTAs/SM. BM=64 rows, BN=256 (full out).
// Layout (bytes): Wst [0,40960) Pst [40960,50176) Hs [50176,59392)
//   Hc [59392,64512) sPE [64512,98304) sAAf [98304,100352)
//   sCCf [100352,102400) sW1q [102400,106496). Dynamic smem 106496.
__global__ __launch_bounds__(256, 2)
void mega_attn(const __half* __restrict__ w2h,    // (256,512)
               const __half* __restrict__ pw2h,   // (256,64)
               const __half* __restrict__ pre1h,  // (512,64)
               const __half* __restrict__ hrelu,  // (R,64)
               const __half* __restrict__ W1q,    // (B*N,512)
               const __half* __restrict__ W1k,    // (B*M,512)
               const int*   __restrict__ idxg,
               const float* __restrict__ aA, const float* __restrict__ cA,
               const float* __restrict__ pb2,
               const float* __restrict__ valft,   // (B*M,256)
               float* __restrict__ aggv)          // (B*N,256)
{
    extern __shared__ char dsm[];
    __half2 (*Wst)[256][20] = (__half2(*)[256][20])(dsm);          // 2*20480
    __half2 (*Pst)[32][36]  = (__half2(*)[32][36])(dsm + 40960);   // 2*4608
    __half2 (*Hs)[36]       = (__half2(*)[36])(dsm + 50176);       // 9216
    __half2 (*Hc)[20]       = (__half2(*)[20])(dsm + 59392);       // 5120
    __half2 (*sPE)[132]     = (__half2(*)[132])(dsm + 64512);      // 33792
    float*  sAAf            = (float*)(dsm + 98304);               // 2048
    float*  sCCf            = (float*)(dsm + 100352);              // 2048
    __half* sW1qh           = (__half*)(dsm + 102400);             // 4096
    __half2 (*Pw)[36]       = (__half2(*)[36])(dsm);               // alias (pe phase)
    __shared__ int sidx[64];
    const uint32_t sW = smem_u32(dsm);
    const uint32_t sP = sW + 40960;
    const int row0 = blockIdx.x * 64;
    const int tid  = threadIdx.x;
    const int lane = tid & 31;
    const int wid  = tid >> 5;
    const int lq = lane >> 2;
    const int lr = lane & 3;
    const int rsel = lane & 15;
    const int wofs = (lane >> 4) << 2;
    const int wm2 = wid & 3;       // hid sub-GEMM M group
    const int wn2 = wid >> 2;      // hid sub-GEMM N group
    const int bb = row0 >> 16;

    if (tid < 64) sidx[tid] = idxg[row0 + tid];
    // load hrelu tile, pw2h (alias), aA/cA, and the tile's 4 W1q rows
    {
        int r = tid >> 2, q = tid & 3;
        const __half* s = hrelu + (size_t)(row0 + r) * PHD + q * 16;
        *(uint4*)&Hs[r][q * 8]     = *(const uint4*)s;
        *(uint4*)&Hs[r][q * 8 + 4] = *(const uint4*)(s + 8);
#pragma unroll
        for (int i = 0; i < 8; i++) {
            int lin = tid + i * 256;
            int rr = lin >> 3, qq = lin & 7;
            *(uint4*)&Pw[rr][qq * 4] = *(const uint4*)(pw2h + (size_t)rr * PHD + qq * 8);
        }
        sAAf[tid]       = aA[tid];
        sAAf[tid + 256] = aA[tid + 256];
        sCCf[tid]       = cA[tid];
        sCCf[tid + 256] = cA[tid + 256];
#pragma unroll
        for (int i = 0; i < 4; i++) {
            int idx2 = tid + i * 256;           // 0..1023 half2
            int p = idx2 >> 8, col = idx2 & 255;
            ((__half2*)sW1qh)[idx2] =
                ((const __half2*)(W1q + (size_t)((row0 >> 4) + p) * AHD))[col];
        }
    }
    __syncthreads();

    // ---- pe phase: pe = Hs @ pw2h^T (warp cols wid*32..+32) -> sPE ----
    {
        float acc2[4][4][4];
#pragma unroll
        for (int mt = 0; mt < 4; mt++)
#pragma unroll
            for (int nt = 0; nt < 4; nt++)
#pragma unroll
                for (int q = 0; q < 4; q++) acc2[mt][nt][q] = 0.f;
#pragma unroll
        for (int kk = 0; kk < 4; kk++) {
            const int wsel = kk * 8 + wofs;
            uint32_t bf[4][2];
#pragma unroll
            for (int np = 0; np < 2; np++) {
                uint32_t q4[4];
                ldsm4(q4, smem_u32(&Pw[wid * 32 + np * 16 + rsel][wsel]));
                bf[np*2][0]   = q4[0];
                bf[np*2+1][0] = q4[1];
                bf[np*2][1]   = q4[2];
                bf[np*2+1][1] = q4[3];
            }
#pragma unroll
            for (int mt = 0; mt < 4; mt++) {
                uint32_t a[4];
                ldsm4(a, smem_u32(&Hs[mt * 16 + rsel][wsel]));
#pragma unroll
                for (int nt = 0; nt < 4; nt++)
                    mma16816(acc2[mt][nt], a, bf[nt][0], bf[nt][1]);
            }
        }
#pragma unroll
        for (int mt = 0; mt < 4; mt++)
#pragma unroll
            for (int nt = 0; nt < 4; nt++) {
                int c = wid * 32 + nt * 8 + lr * 2;
                float2 pbv = *(const float2*)(pb2 + c);
                sPE[mt*16 + lq][wid*16 + nt*4 + lr] =
                    __floats2half2_rn(acc2[mt][nt][0] + pbv.x, acc2[mt][nt][1] + pbv.y);
                sPE[mt*16 + 8 + lq][wid*16 + nt*4 + lr] =
                    __floats2half2_rn(acc2[mt][nt][2] + pbv.x, acc2[mt][nt][3] + pbv.y);
            }
    }
    __syncthreads();   // release alias area before w2h staging

    // ---- main loop: per 32-wide AH chunk: hid chunk -> logits mma ----
    auto fetchW = [&](int c, int buf) {
#pragma unroll
        for (int i = 0; i < 4; i++) {
            int lin = tid + i * 256;
            int r = lin >> 2, q = lin & 3;
            cp16(sW + (uint32_t)buf * 20480 + (uint32_t)r * 80 + q * 16,
                 w2h + (size_t)r * AHD + c * 32 + q * 8);
        }
    };
    auto fetchP = [&](int c, int buf) {
        int r = tid >> 3, q = tid & 7;
        cp16(sP + (uint32_t)buf * 4608 + (uint32_t)r * 144 + q * 16,
             pre1h + (size_t)(c * 32 + r) * PHD + q * 8);
    };

    float acc1[4][4][4];
#pragma unroll
    for (int mt = 0; mt < 4; mt++)
#pragma unroll
        for (int nt = 0; nt < 4; nt++)
#pragma unroll
            for (int q = 0; q < 4; q++) acc1[mt][nt][q] = 0.f;

    fetchW(0, 0);
    fetchP(0, 0);
    CP_COMMIT();
#pragma unroll 1
    for (int c = 0; c < AHD / 32; c++) {
        CP_WAIT(0);
        __syncthreads();
        if (c + 1 < AHD / 32) {
            fetchW(c + 1, (c + 1) & 1);
            fetchP(c + 1, (c + 1) & 1);
        }
        CP_COMMIT();
        // hid sub-GEMM: rows wm2*16..+16, ah cols wn2*16..+16, K=64 (from Hs)
        float ha[2][4];
#pragma unroll
        for (int n2 = 0; n2 < 2; n2++)
#pragma unroll
            for (int q = 0; q < 4; q++) ha[n2][q] = 0.f;
#pragma unroll
        for (int kk = 0; kk < 4; kk++) {
            const int wsel = kk * 8 + wofs;
            uint32_t a[4], q4[4];
            ldsm4(a, smem_u32(&Hs[wm2 * 16 + rsel][wsel]));
            ldsm4(q4, smem_u32(&Pst[c & 1][wn2 * 16 + rsel][wsel]));
            mma16816(ha[0], a, q4[0], q4[2]);
            mma16816(ha[1], a, q4[1], q4[3]);
        }
        // epilogue: gather W1q(smem)/W1k(global) + BN + relu -> Hc
#pragma unroll
        for (int h = 0; h < 2; h++) {
            int r = wm2 * 16 + h * 8 + lq;
            int j = sidx[r];
            const __half* qp = sW1qh + wm2 * AHD;     // point within tile = wm2
            const __half* kp = W1k + ((size_t)bb * MM + j) * AHD;
#pragma unroll
            for (int n2 = 0; n2 < 2; n2++) {
                int ah = c * 32 + wn2 * 16 + n2 * 8 + lr * 2;
                float2 qv = __half22float2(*(const __half2*)(qp + ah));
                float2 kv = __half22float2(*(const __half2*)(kp + ah));
                float2 av = *(const float2*)(sAAf + ah);
                float2 cv = *(const float2*)(sCCf + ah);
                float v0 = fmaxf((ha[n2][h*2+0] + qv.x - kv.x) * av.x + cv.x, 0.f);
                float v1 = fmaxf((ha[n2][h*2+1] + qv.y - kv.y) * av.y + cv.y, 0.f);
                Hc[r][wn2 * 8 + n2 * 4 + lr] = __floats2half2_rn(v0, v1);
            }
        }
        __syncthreads();
        // logits mma: warp cols wid*32..+32; A = Hc, B = Wst[c&1]
#pragma unroll
        for (int ks = 0; ks < 2; ks++) {
            const int wsel = ks * 8 + wofs;
            uint32_t bf[4][2];
#pragma unroll
            for (int np = 0; np < 2; np++) {
                uint32_t q4[4];
                ldsm4(q4, smem_u32(&Wst[c & 1][wid * 32 + np * 16 + rsel][wsel]));
                bf[np*2][0]   = q4[0];
                bf[np*2+1][0] = q4[1];
                bf[np*2][1]   = q4[2];
                bf[np*2+1][1] = q4[3];
            }
#pragma unroll
            for (int mt = 0; mt < 4; mt++) {
                uint32_t a[4];
                ldsm4(a, smem_u32(&Hc[mt * 16 + rsel][wsel]));
#pragma unroll
                for (int nt = 0; nt < 4; nt++)
                    mma16816(acc1[mt][nt], a, bf[nt][0], bf[nt][1]);
            }
        }
    }

    // ---- softmax over k (16 rows per point, within warp) + gather + agg ----
#pragma unroll
    for (int mt = 0; mt < 4; mt++) {
        const int pt = (row0 + mt * 16) >> 4;
        const int j0 = sidx[mt * 16 + lq];
        const int j1 = sidx[mt * 16 + 8 + lq];
        const float* v0b = valft + ((size_t)bb * MM + j0) * DD;
        const float* v1b = valft + ((size_t)bb * MM + j1) * DD;
#pragma unroll
        for (int nt = 0; nt < 4; nt++) {
            const int c = wid * 32 + nt * 8 + lr * 2;
            float2 vv0 = *(const float2*)(v0b + c);
            float2 vv1 = *(const float2*)(v1b + c);
            float2 p0 = __half22float2(sPE[mt*16 + lq][wid*16 + nt*4 + lr]);
            float2 p1 = __half22float2(sPE[mt*16 + 8 + lq][wid*16 + nt*4 + lr]);
            float outc[2];
#pragma unroll
            for (int j = 0; j < 2; j++) {
                float l0 = acc1[mt][nt][j];
                float l1 = acc1[mt][nt][2 + j];
                float m = fmaxf(l0, l1);
                m = fmaxf(m, __shfl_xor_sync(0xffffffffu, m, 4));
                m = fmaxf(m, __shfl_xor_sync(0xffffffffu, m, 8));
                m = fmaxf(m, __shfl_xor_sync(0xffffffffu, m, 16));
                float e0 = __expf(l0 - m), e1 = __expf(l1 - m);
                float S = e0 + e1;
                S += __shfl_xor_sync(0xffffffffu, S, 4);
                S += __shfl_xor_sync(0xffffffffu, S, 8);
                S += __shfl_xor_sync(0xffffffffu, S, 16);
                float pe0 = j ? p0.y : p0.x;
                float pe1 = j ? p1.y : p1.x;
                float va0 = j ? vv0.y : vv0.x;
                float va1 = j ? vv1.y : vv1.x;
                float T = e0 * (va0 + pe0) + e1 * (va1 + pe1);
                T += __shfl_xor_sync(0xffffffffu, T, 4);
                T += __shfl_xor_sync(0xffffffffu, T, 8);
                T += __shfl_xor_sync(0xffffffffu, T, 16);
                outc[j] = T / S;
            }
            if (lq == 0)
                *(float2*)(aggv + (size_t)pt * DD + c) = make_float2(outc[0], outc[1]);
        }
    }
}

// ---------------- precompute + weight conversions ----------------------------
__global__ void precomp_kernel(const float* __restrict__ w1,
                               const float* __restrict__ pw2,
                               const float* __restrict__ pb2,
                               const float* __restrict__ ag, const float* __restrict__ abeta,
                               const float* __restrict__ amu, const float* __restrict__ avar,
                               const float* __restrict__ ab1,
                               const float* __restrict__ pg, const float* __restrict__ pbeta,
                               const float* __restrict__ pmu, const float* __restrict__ pvar,
                               const float* __restrict__ pb1,
                               float* __restrict__ pre1, __half* __restrict__ pre1h,
                               float* __restrict__ aA,
                               float* __restrict__ cA, float* __restrict__ aP,
                               float* __restrict__ cP)
{
    int o = blockIdx.x;
    if (o < AHD) {
        int p = threadIdx.x;
        float s = 0.f;
        for (int c = 0; c < DD; c++) s += w1[o*DD + c] * pw2[c*PHD + p];
        pre1[o*PHD + p] = s;
        pre1h[o*PHD + p] = __float2half_rn(s);
        if (p == 0) {
            float vb = 0.f;
            for (int c = 0; c < DD; c++) vb += w1[o*DD + c] * pb2[c];
            float inv = ag[o] / sqrtf(avar[o] + 1e-5f);
            aA[o] = inv;
            cA[o] = (ab1[o] - amu[o]) * inv + abeta[o] + vb * inv;
        }
    } else {
        int p = threadIdx.x;
        float inv = pg[p] / sqrtf(pvar[p] + 1e-5f);
        aP[p] = inv;
        cP[p] = (pb1[p] - pmu[p]) * inv + pbeta[p];
    }
}

// W1K = attn_w1 @ w_key (512,256) fp16, vbk = attn_w1 @ b_key
__global__ void precomp2_kernel(const float* __restrict__ w1,
                                const float* __restrict__ wk,
                                const float* __restrict__ bk,
                                __half* __restrict__ W1Kh,
                                float* __restrict__ vbk)
{
    int o = blockIdx.x;
    int e = threadIdx.x;
    float s = 0.f;
    for (int d = 0; d < DD; d++) s += w1[o*DD + d] * wk[d*DD + e];
    W1Kh[o*DD + e] = __float2half_rn(s);
    if (e == 0) {
        float t = 0.f;
        for (int d = 0; d < DD; d++) t += w1[o*DD + d] * bk[d];
        vbk[o] = t;
    }
}

#define CV1 (AHD*DD)
#define CV2 (CV1 + DD*AHD)
#define CV3 (CV2 + DD*PHD)
#define CV4 (CV3 + DD*DD)
__global__ void cvt_all_kernel(const float* __restrict__ w1, const float* __restrict__ w2,
                               const float* __restrict__ pw2, const float* __restrict__ wv,
                               __half* __restrict__ w1h, __half* __restrict__ w2h,
                               __half* __restrict__ pw2h, __half* __restrict__ wvh)
{
    int i = blockIdx.x * 256 + threadIdx.x;
    if (i < CV1)      w1h [i]       = __float2half_rn(w1 [i]);
    else if (i < CV2) w2h [i - CV1] = __float2half_rn(w2 [i - CV1]);
    else if (i < CV3) pw2h[i - CV2] = __float2half_rn(pw2[i - CV2]);
    else if (i < CV4) wvh [i - CV3] = __float2half_rn(wv [i - CV3]);
}

// ---------------- SIMT fp32 GEMM (small front/end GEMMs) ---------------------
constexpr int TBO = 128, TBX = 128, TBK = 16;

template<bool A_RM, bool OUT_XO>
__global__ __launch_bounds__(256)
void gemm_k(const float* __restrict__ W, const float* __restrict__ bias,
            const float* __restrict__ A, const float* __restrict__ resid,
            float* __restrict__ C, int O, int K, int X, size_t sA, size_t sC)
{
    __shared__ float As[TBK][TBX];
    __shared__ float Ws[TBK][TBO];
    const int bx = blockIdx.x * TBX;
    const int bo = blockIdx.y * TBO;
    const int b  = blockIdx.z;
    const float* Ab = A + (size_t)b * sA;
    float* Cb = C + (size_t)b * sC;
    const int tid = threadIdx.x;
    const int tco = (tid & 15) * 4;
    const int tcx = (tid >> 4) * 4;

    float acc[8][8];
#pragma unroll
    for (int i = 0; i < 8; i++)
#pragma unroll
        for (int j = 0; j < 8; j++) acc[i][j] = 0.f;

    for (int k0 = 0; k0 < K; k0 += TBK) {
        if (A_RM) {
            int row = tid >> 1, c0 = (tid & 1) * 8;
            const float* p = Ab + (size_t)(bx + row) * K + k0 + c0;
            float4 v0 = *(const float4*)p;
            float4 v1 = *(const float4*)(p + 4);
            As[c0+0][row] = v0.x; As[c0+1][row] = v0.y;
            As[c0+2][row] = v0.z; As[c0+3][row] = v0.w;
            As[c0+4][row] = v1.x; As[c0+5][row] = v1.y;
            As[c0+6][row] = v1.z; As[c0+7][row] = v1.w;
        } else {
            int kk = tid >> 4, x8 = (tid & 15) * 8;
            const float* p = Ab + (size_t)(k0 + kk) * X + bx + x8;
            float4 v0 = *(const float4*)p;
            float4 v1 = *(const float4*)(p + 4);
            *(float4*)&As[kk][x8]     = v0;
            *(float4*)&As[kk][x8 + 4] = v1;
        }
        {
            int row = tid >> 1, c0 = (tid & 1) * 8;
            const float* p = W + (size_t)(bo + row) * K + k0 + c0;
            float4 v0 = *(const float4*)p;
            float4 v1 = *(const float4*)(p + 4);
            Ws[c0+0][row] = v0.x; Ws[c0+1][row] = v0.y;
            Ws[c0+2][row] = v0.z; Ws[c0+3][row] = v0.w;
            Ws[c0+4][row] = v1.x; Ws[c0+5][row] = v1.y;
            Ws[c0+6][row] = v1.z; Ws[c0+7][row] = v1.w;
        }
        __syncthreads();
#pragma unroll
        for (int kk = 0; kk < TBK; kk++) {
            float4 a0 = *(const float4*)&As[kk][tcx];
            float4 a1 = *(const float4*)&As[kk][tcx + 64];
            float4 w0 = *(const float4*)&Ws[kk][tco];
            float4 w1 = *(const float4*)&Ws[kk][tco + 64];
            float a[8] = {a0.x, a0.y, a0.z, a0.w, a1.x, a1.y, a1.z, a1.w};
            float w[8] = {w0.x, w0.y, w0.z, w0.w, w1.x, w1.y, w1.z, w1.w};
#pragma unroll
            for (int i = 0; i < 8; i++)
#pragma unroll
                for (int j = 0; j < 8; j++)
                    acc[i][j] = fmaf(a[i], w[j], acc[i][j]);
        }
        __syncthreads();
    }
#pragma unroll
    for (int i = 0; i < 8; i++) {
        int xx = bx + (i < 4 ? tcx + i : 64 + tcx + (i - 4));
#pragma unroll
        for (int jh = 0; jh < 2; jh++) {
            int oo = bo + tco + jh * 64;
            float vr[4];
#pragma unroll
            for (int j = 0; j < 4; j++) vr[j] = acc[i][jh * 4 + j];
            if (bias) {
#pragma unroll
                for (int j = 0; j < 4; j++) vr[j] += bias[oo + j];
            }
            if (OUT_XO) {
                size_t ix = (size_t)xx * O + oo;
                if (resid) {
                    float4 rv = *(const float4*)(resid + (size_t)b * sC + ix);
                    vr[0] += rv.x; vr[1] += rv.y; vr[2] += rv.z; vr[3] += rv.w;
                }
                float4 ov = {vr[0], vr[1], vr[2], vr[3]};
                *(float4*)(Cb + ix) = ov;
            } else {
#pragma unroll
                for (int j = 0; j < 4; j++) {
                    size_t ix = (size_t)(oo + j) * X + xx;
                    float v = vr[j];
                    if (resid) v += resid[(size_t)b * sC + ix];
                    Cb[ix] = v;
                }
            }
        }
    }
}

// ---------------- KNN --------------------------------------------------------
__global__ __launch_bounds__(128)
void knn_kernel(const float* __restrict__ pf,
                const float* __restrict__ seed,
                int* __restrict__ idx_out)
{
    __shared__ float sx[MM], sy[MM], sz[MM], ss[MM];
    __shared__ float sd[4][MM];
    int b = blockIdx.y;
    const float* sb = seed + (size_t)b * MM * 3;
    for (int j = threadIdx.x; j < MM; j += 128) {
        float x = sb[j*3], y = sb[j*3+1], z = sb[j*3+2];
        sx[j] = x; sy[j] = y; sz[j] = z; ss[j] = x*x + y*y + z*z;
    }
    __syncthreads();
    int w = threadIdx.x >> 5, lane = threadIdx.x & 31;
    int n = blockIdx.x * 4 + w;
    const float* q = pf + ((size_t)b * NN + n) * 3;
    float qx = q[0], qy = q[1], qz = q[2];
    float qn = qx*qx + qy*qy + qz*qz;
    float* d = sd[w];
    for (int j = lane; j < MM; j += 32)
        d[j] = qn + ss[j] - 2.f * (qx*sx[j] + qy*sy[j] + qz*sz[j]);
    __syncwarp();
    int* out = idx_out + ((size_t)b * NN + n) * KNB;
    for (int t = 0; t < KNB; t++) {
        float best = 1e30f; int bi = 0;
        for (int j = lane; j < MM; j += 32) {
            float v = d[j];
            if (v < best || (v == best && j < bi)) { best = v; bi = j; }
        }
#pragma unroll
        for (int off = 16; off; off >>= 1) {
            float ov = __shfl_xor_sync(0xffffffffu, best, off);
            int   oi = __shfl_xor_sync(0xffffffffu, bi, off);
            if (ov < best || (ov == best && oi < bi)) { best = ov; bi = oi; }
        }
        if (lane == 0) out[t] = bi;
        if (lane == (bi & 31)) d[bi] = 1e30f;
        __syncwarp();
    }
}

// ---------------- geometry -> hrelu (R,64) fp16 ------------------------------
__global__ __launch_bounds__(256)
void geom_kernel(const float* __restrict__ pos,
                 const float* __restrict__ seed,
                 const int*   __restrict__ idxg,
                 const float* __restrict__ pw1,
                 const float* __restrict__ aP, const float* __restrict__ cP,
                 __half* __restrict__ hrelu)
{
    int r = blockIdx.x * 256 + threadIdx.x;
    int b = r >> 16;
    int n = (r >> 4) & (NN - 1);
    int j = idxg[r];
    float px = pos[((size_t)b * 3 + 0) * NN + n];
    float py = pos[((size_t)b * 3 + 1) * NN + n];
    float pz = pos[((size_t)b * 3 + 2) * NN + n];
    const float* sj = seed + ((size_t)b * MM + j) * 3;
    float rx = px - sj[0], ry = py - sj[1], rz = pz - sj[2];
    float ds = sqrtf(rx*rx + ry*ry + rz*rz);
    __half2* out = (__half2*)(hrelu + (size_t)r * PHD);
#pragma unroll
    for (int p0 = 0; p0 < PHD; p0 += 2) {
        float t[2];
#pragma unroll
        for (int u = 0; u < 2; u++) {
            int p = p0 + u;
            float raw = __ldg(&pw1[p*4]) * ds + __ldg(&pw1[p*4+1]) * rx
                      + __ldg(&pw1[p*4+2]) * ry + __ldg(&pw1[p*4+3]) * rz;
            t[u] = fmaxf(raw * __ldg(&aP[p]) + __ldg(&cP[p]), 0.f);
        }
        out[p0 >> 1] = __floats2half2_rn(t[0], t[1]);
    }
}

// ---------------- launch -----------------------------------------------------
extern "C" void kernel_launch(void* const* d_in, const int* in_sizes, int n_in,
                              void* d_out, int out_size)
{
    const float* pos      = (const float*)d_in[0];
    const float* pf       = (const float*)d_in[1];
    const float* fea      = (const float*)d_in[2];
    const float* seed     = (const float*)d_in[3];
    const float* seed_fea = (const float*)d_in[4];
    const float* w_start  = (const float*)d_in[5];
    const float* b_start  = (const float*)d_in[6];
    const float* w_key    = (const float*)d_in[7];
    const float* b_key    = (const float*)d_in[8];
    const float* w_value  = (const float*)d_in[9];
    const float* b_value  = (const float*)d_in[10];
    const float* w_query  = (const float*)d_in[11];
    const float* b_query  = (const float*)d_in[12];
    const float* pos_w1   = (const float*)d_in[13];
    const float* pos_b1   = (const float*)d_in[14];
    const float* pos_g1   = (const float*)d_in[15];
    const float* pos_beta1= (const float*)d_in[16];
    const float* pos_mu1  = (const float*)d_in[17];
    const float* pos_var1 = (const float*)d_in[18];
    const float* pos_w2   = (const float*)d_in[19];
    const float* pos_b2   = (const float*)d_in[20];
    const float* attn_w1  = (const float*)d_in[21];
    const float* attn_b1  = (const float*)d_in[22];
    const float* attn_g1  = (const float*)d_in[23];
    const float* attn_beta1=(const float*)d_in[24];
    const float* attn_mu1 = (const float*)d_in[25];
    const float* attn_var1= (const float*)d_in[26];
    const float* attn_w2  = (const float*)d_in[27];
    // d_in[28] = attn_b2: cancels in softmax over K
    const float* w_end    = (const float*)d_in[29];
    const float* b_end    = (const float*)d_in[30];

    float *valueT, *valftT, *queryT, *aggv, *pre1, *vbk;
    float *aA, *cA, *aP, *cP;
    __half *W1qt, *W1kt, *hrelu, *pre1h, *w1h, *w2h, *pw2h, *wvh, *W1Kh;
    int* idx;
    cudaGetSymbolAddress((void**)&valueT, g_valueT);
    cudaGetSymbolAddress((void**)&valftT, g_valftT);
    cudaGetSymbolAddress((void**)&queryT, g_queryT);
    cudaGetSymbolAddress((void**)&W1qt,   g_W1qt);
    cudaGetSymbolAddress((void**)&W1kt,   g_W1kt);
    cudaGetSymbolAddress((void**)&idx,    g_idx);
    cudaGetSymbolAddress((void**)&hrelu,  g_hrelu);
    cudaGetSymbolAddress((void**)&aggv,   g_agg);
    cudaGetSymbolAddress((void**)&pre1,   g_pre1);
    cudaGetSymbolAddress((void**)&pre1h,  g_pre1h);
    cudaGetSymbolAddress((void**)&w1h,    g_w1h);
    cudaGetSymbolAddress((void**)&w2h,    g_w2h);
    cudaGetSymbolAddress((void**)&pw2h,   g_pw2h);
    cudaGetSymbolAddress((void**)&wvh,    g_wvh);
    cudaGetSymbolAddress((void**)&W1Kh,   g_W1Kh);
    cudaGetSymbolAddress((void**)&vbk,    g_vbk);
    cudaGetSymbolAddress((void**)&aA,     g_aA);
    cudaGetSymbolAddress((void**)&cA,     g_cA);
    cudaGetSymbolAddress((void**)&aP,     g_aP);
    cudaGetSymbolAddress((void**)&cP,     g_cP);

    cudaFuncSetAttribute(mega_attn, cudaFuncAttributeMaxDynamicSharedMemorySize, 106496);

    precomp_kernel<<<AHD + 1, PHD>>>(attn_w1, pos_w2, pos_b2,
                                     attn_g1, attn_beta1, attn_mu1, attn_var1, attn_b1,
                                     pos_g1, pos_beta1, pos_mu1, pos_var1, pos_b1,
                                     pre1, pre1h, aA, cA, aP, cP);
    precomp2_kernel<<<AHD, DD>>>(attn_w1, w_key, b_key, W1Kh, vbk);
    cvt_all_kernel<<<(CV4 + 255)/256, 256>>>(attn_w1, attn_w2, pos_w2, w_value,
                                             w1h, w2h, pw2h, wvh);

    // value = w_start @ seed_fea  (SIMT, channel-major A), row-major out
    gemm_k<false,true><<<dim3(MM/128, DD/128, BB), 256>>>(
        w_start, b_start, seed_fea, nullptr, valueT, DD, CC, MM,
        (size_t)CC*MM, (size_t)MM*DD);
    // valft via fp16 mma (A = valueT fp32 row-major)
    hgemm<256,256,false,false><<<dim3(2, BB*MM/128), 256>>>(
        wvh, b_value, valueT, valftT);
    // W1k = (attn_w1@w_key) @ value + attn_w1@b_key  (fp16 out)
    hgemm<512,256,false,true><<<dim3(4, BB*MM/128), 256>>>(
        W1Kh, vbk, valueT, W1kt);
    // query (SIMT, channel-major A)
    gemm_k<false,true><<<dim3(NN/128, DD/128, BB), 256>>>(
        w_query, b_query, fea, nullptr, queryT, DD, CC, NN,
        (size_t)CC*NN, (size_t)NN*DD);
    // W1q via fp16 mma -> fp16 output
    hgemm<512,256,false,true><<<dim3(4, BB*NN/128), 256>>>(
        w1h, nullptr, queryT, W1qt);

    // knn + geometry
    knn_kernel<<<dim3(NN/4, BB), 128>>>(pf, seed, idx);
    geom_kernel<<<RR/256, 256>>>(pos, seed, idx, pos_w1, aP, cP, hrelu);

    // mega: pe + hid chunks + logits + softmax + gather + aggregate -> aggv
    mega_attn<<<RR/64, 256, 106496>>>(
        w2h, pw2h, pre1h, hrelu, W1qt, W1kt, idx, aA, cA, pos_b2, valftT, aggv);

    // out = w_end @ aggv + b_end + fea
    gemm_k<true,false><<<dim3(NN/128, CC/128, BB), 256>>>(
        w_end, b_end, aggv, fea, (float*)d_out, CC, DD, NN,
        (size_t)NN*DD, (size_t)CC*NN);
}